// round 8
// baseline (speedup 1.0000x reference)
#include <cuda_runtime.h>
#include <cuda_fp16.h>
#include <math.h>

#define BB 2
#define CC 256
#define TT 400
#define FF 256
#define KK 32
#define EPSV 1e-6f

typedef unsigned long long ull;

// ---------------- scratch ------------------------------------------------------
__device__ float g_emb0   [(size_t)BB*CC*TT*FF];   // used as fp16 (half the space)
__device__ float g_qseed  [(size_t)BB*CC*TT*KK];
__device__ float g_q2     [(size_t)BB*CC*TT*KK];
__device__ float g_pooled [(size_t)BB*CC*TT*KK];
__device__ float g_hidden [(size_t)BB*CC*TT*KK];
__device__ float g_hffn   [(size_t)BB*2*CC*TT*KK];
__device__ float g_P      [CC*CC];
__device__ float g_OV     [CC*CC];
__device__ float g_Wp     [CC*CC];
__device__ float g_Wf     [2*CC*CC];
__device__ float g_u      [CC];
__device__ float g_w2     [CC];
__device__ float g_bias2  [CC];
__device__ float g_colt   [BB*TT*KK];
__device__ float g_misc   [4];

// ---------------- helpers ------------------------------------------------------
__device__ __forceinline__ unsigned sptr(const void* p) {
    return (unsigned)__cvta_generic_to_shared(p);
}
__device__ __forceinline__ void ldmx4(unsigned* a, unsigned addr) {
    asm volatile("ldmatrix.sync.aligned.m8n8.x4.shared.b16 {%0,%1,%2,%3}, [%4];"
        : "=r"(a[0]), "=r"(a[1]), "=r"(a[2]), "=r"(a[3]) : "r"(addr));
}
__device__ __forceinline__ void ldmx2t(unsigned& b0, unsigned& b1, unsigned addr) {
    asm volatile("ldmatrix.sync.aligned.m8n8.x2.trans.shared.b16 {%0,%1}, [%2];"
        : "=r"(b0), "=r"(b1) : "r"(addr));
}
__device__ __forceinline__ void mma_h(float* c, const unsigned* a, unsigned b0, unsigned b1) {
    asm volatile("mma.sync.aligned.m16n8k16.row.col.f32.f16.f16.f32 "
        "{%0,%1,%2,%3}, {%4,%5,%6,%7}, {%8,%9}, {%0,%1,%2,%3};"
        : "+f"(c[0]), "+f"(c[1]), "+f"(c[2]), "+f"(c[3])
        : "r"(a[0]), "r"(a[1]), "r"(a[2]), "r"(a[3]), "r"(b0), "r"(b1));
}
// split v into hi (fp16) + lo (fp16 of residual)
__device__ __forceinline__ void split2(float x, float y, __half2& hi, __half2& lo) {
    hi = __floats2half2_rn(x, y);
    float2 hf = __half22float2(hi);
    lo = __floats2half2_rn(x - hf.x, y - hf.y);
}

// ---------------- unified fp16 tensor-core GEMM (single precision level) --------
// Y[b,o,n] = epi( sum_c W[o,c] * Xeff[b,c,n] ); Xeff = X or X*silu(Xg)
// epi: optional *invrms[n] (in-kernel sumsq of Xeff), +bias, +addsrc; fp32 or fp16 out
__global__ void __launch_bounds__(512, 1)
gemm_h(const float* __restrict__ W, const float* __restrict__ bias,
       const float* __restrict__ X, const float* __restrict__ Xg,
       float* __restrict__ Y, __half* __restrict__ Yh,
       const float* __restrict__ addsrc,
       int invMode, int Cout, int Ntot, long xbstride)
{
    __shared__ __half Wh[2][256][24];
    __shared__ __half Xh[2][16][136];
    __shared__ float invs[128];
    __shared__ float4 part[16][32];

    int b  = blockIdx.z;
    int n0 = blockIdx.x * 128;
    int o0 = blockIdx.y * 256;
    const float* Xb  = X + (size_t)b * xbstride;
    const float* Xgb = Xg ? Xg + (size_t)b * xbstride : nullptr;
    float* Yb  = Y  ? Y  + (size_t)b * (size_t)Cout * Ntot : nullptr;
    __half* Yhb = Yh ? Yh + (size_t)b * (size_t)Cout * Ntot : nullptr;
    const float* Ab = addsrc ? addsrc + (size_t)b * (size_t)Cout * Ntot : nullptr;

    int tid = threadIdx.x;
    int lane = tid & 31, warp = tid >> 5;
    int wm = warp & 7, wn = warp >> 3;
    int group = lane >> 2, tid4 = lane & 3;

    int wm_ld = tid >> 2;
    int wkw   = tid & 3;
    int xk    = tid >> 5;
    int xn4   = (tid & 31) * 4;

    float acc[2][8][4];
    #pragma unroll
    for (int mt = 0; mt < 2; mt++)
        #pragma unroll
        for (int nt = 0; nt < 8; nt++)
            #pragma unroll
            for (int r = 0; r < 4; r++) acc[mt][nt][r] = 0.f;

    float4 ssq = make_float4(0.f, 0.f, 0.f, 0.f);
    float4 wreg0, wreg1, xreg;

    {
        const float* wp = W + (size_t)(o0 + wm_ld) * 256 + wkw * 4;
        wreg0 = *(const float4*)wp;
        wreg1 = *(const float4*)(wp + (size_t)128 * 256);
        xreg = *(const float4*)(Xb + (size_t)xk * Ntot + n0 + xn4);
        if (Xgb) {
            float4 g = *(const float4*)(Xgb + (size_t)xk * Ntot + n0 + xn4);
            xreg.x *= g.x / (1.f + __expf(-g.x));
            xreg.y *= g.y / (1.f + __expf(-g.y));
            xreg.z *= g.z / (1.f + __expf(-g.z));
            xreg.w *= g.w / (1.f + __expf(-g.w));
        }
        if (invMode) {
            ssq.x += xreg.x * xreg.x; ssq.y += xreg.y * xreg.y;
            ssq.z += xreg.z * xreg.z; ssq.w += xreg.w * xreg.w;
        }
    }

    #pragma unroll 1
    for (int kt = 0; kt < 16; kt++) {
        int buf = kt & 1;
        {
            __half2* wr0 = (__half2*)&Wh[buf][wm_ld][0];
            wr0[2 * wkw]     = __floats2half2_rn(wreg0.x, wreg0.y);
            wr0[2 * wkw + 1] = __floats2half2_rn(wreg0.z, wreg0.w);
            __half2* wr1 = (__half2*)&Wh[buf][128 + wm_ld][0];
            wr1[2 * wkw]     = __floats2half2_rn(wreg1.x, wreg1.y);
            wr1[2 * wkw + 1] = __floats2half2_rn(wreg1.z, wreg1.w);
            __half2* xr = (__half2*)&Xh[buf][xk][xn4];
            xr[0] = __floats2half2_rn(xreg.x, xreg.y);
            xr[1] = __floats2half2_rn(xreg.z, xreg.w);
        }
        __syncthreads();
        if (kt < 15) {
            int k0 = (kt + 1) * 16;
            const float* wp = W + (size_t)(o0 + wm_ld) * 256 + k0 + wkw * 4;
            wreg0 = *(const float4*)wp;
            wreg1 = *(const float4*)(wp + (size_t)128 * 256);
            xreg = *(const float4*)(Xb + (size_t)(k0 + xk) * Ntot + n0 + xn4);
            if (Xgb) {
                float4 g = *(const float4*)(Xgb + (size_t)(k0 + xk) * Ntot + n0 + xn4);
                xreg.x *= g.x / (1.f + __expf(-g.x));
                xreg.y *= g.y / (1.f + __expf(-g.y));
                xreg.z *= g.z / (1.f + __expf(-g.z));
                xreg.w *= g.w / (1.f + __expf(-g.w));
            }
            if (invMode) {
                ssq.x += xreg.x * xreg.x; ssq.y += xreg.y * xreg.y;
                ssq.z += xreg.z * xreg.z; ssq.w += xreg.w * xreg.w;
            }
        }
        unsigned a[2][4];
        #pragma unroll
        for (int mt = 0; mt < 2; mt++) {
            int row = wm * 32 + mt * 16 + (lane & 15);
            ldmx4(a[mt], sptr(&Wh[buf][row][(lane >> 4) * 8]));
        }
        #pragma unroll
        for (int nt = 0; nt < 8; nt++) {
            unsigned b0, b1;
            ldmx2t(b0, b1, sptr(&Xh[buf][lane & 15][wn * 64 + nt * 8]));
            mma_h(acc[0][nt], a[0], b0, b1);
            mma_h(acc[1][nt], a[1], b0, b1);
        }
    }

    if (invMode) {
        part[xk][tid & 31] = ssq;
        __syncthreads();
        if (tid < 32) {
            float4 s = part[0][tid];
            #pragma unroll
            for (int r = 1; r < 16; r++) {
                float4 p = part[r][tid];
                s.x += p.x; s.y += p.y; s.z += p.z; s.w += p.w;
            }
            invs[tid * 4 + 0] = rsqrtf(s.x * (1.f / CC) + EPSV);
            invs[tid * 4 + 1] = rsqrtf(s.y * (1.f / CC) + EPSV);
            invs[tid * 4 + 2] = rsqrtf(s.z * (1.f / CC) + EPSV);
            invs[tid * 4 + 3] = rsqrtf(s.w * (1.f / CC) + EPSV);
        }
        __syncthreads();
    }

    #pragma unroll
    for (int mt = 0; mt < 2; mt++) {
        int row = o0 + wm * 32 + mt * 16 + group;
        float bv0 = bias ? bias[row]     : 0.f;
        float bv8 = bias ? bias[row + 8] : 0.f;
        #pragma unroll
        for (int nt = 0; nt < 8; nt++) {
            int cl = wn * 64 + nt * 8 + tid4 * 2;
            int col = n0 + cl;
            size_t i0 = (size_t)row * Ntot + col;
            size_t i8 = (size_t)(row + 8) * Ntot + col;
            float a0 = acc[mt][nt][0], a1 = acc[mt][nt][1];
            float a2 = acc[mt][nt][2], a3 = acc[mt][nt][3];
            if (invMode) {
                float s0 = invs[cl], s1 = invs[cl + 1];
                a0 *= s0; a1 *= s1; a2 *= s0; a3 *= s1;
            }
            float2 v0 = make_float2(a0 + bv0, a1 + bv0);
            float2 v8 = make_float2(a2 + bv8, a3 + bv8);
            if (Ab) {
                float2 r0 = *(const float2*)(Ab + i0);
                float2 r8 = *(const float2*)(Ab + i8);
                v0.x += r0.x; v0.y += r0.y;
                v8.x += r8.x; v8.y += r8.y;
            }
            if (Yhb) {
                *(__half2*)(Yhb + i0) = __floats2half2_rn(v0.x, v0.y);
                *(__half2*)(Yhb + i8) = __floats2half2_rn(v8.x, v8.y);
            } else {
                *(float2*)(Yb + i0) = v0;
                *(float2*)(Yb + i8) = v8;
            }
        }
    }
}

// ---------------- split-fp16 (near-fp32) tensor-core GEMM -----------------------
// Same semantics as gemm_h (fp32 out only) but W and X split into hi+lo fp16,
// 3 MMAs per tile: ahi*bhi + ahi*blo + alo*bhi. Single-buffered smem.
__global__ void __launch_bounds__(512, 1)
gemm_hs(const float* __restrict__ W, const float* __restrict__ bias,
        const float* __restrict__ X, const float* __restrict__ Xg,
        float* __restrict__ Y, const float* __restrict__ addsrc,
        int invMode, int Cout, int Ntot, long xbstride)
{
    __shared__ __half Whh[256][24], Whl[256][24];
    __shared__ __half Xhh[16][136], Xhl[16][136];
    __shared__ float invs[128];
    __shared__ float4 part[16][32];

    int b  = blockIdx.z;
    int n0 = blockIdx.x * 128;
    int o0 = blockIdx.y * 256;
    const float* Xb  = X + (size_t)b * xbstride;
    const float* Xgb = Xg ? Xg + (size_t)b * xbstride : nullptr;
    float* Yb = Y + (size_t)b * (size_t)Cout * Ntot;
    const float* Ab = addsrc ? addsrc + (size_t)b * (size_t)Cout * Ntot : nullptr;

    int tid = threadIdx.x;
    int lane = tid & 31, warp = tid >> 5;
    int wm = warp & 7, wn = warp >> 3;
    int group = lane >> 2, tid4 = lane & 3;

    int wm_ld = tid >> 2;
    int wkw   = tid & 3;
    int xk    = tid >> 5;
    int xn4   = (tid & 31) * 4;

    float acc[2][8][4];
    #pragma unroll
    for (int mt = 0; mt < 2; mt++)
        #pragma unroll
        for (int nt = 0; nt < 8; nt++)
            #pragma unroll
            for (int r = 0; r < 4; r++) acc[mt][nt][r] = 0.f;

    float4 ssq = make_float4(0.f, 0.f, 0.f, 0.f);
    float4 wreg0, wreg1, xreg;

    {
        const float* wp = W + (size_t)(o0 + wm_ld) * 256 + wkw * 4;
        wreg0 = *(const float4*)wp;
        wreg1 = *(const float4*)(wp + (size_t)128 * 256);
        xreg = *(const float4*)(Xb + (size_t)xk * Ntot + n0 + xn4);
        if (Xgb) {
            float4 g = *(const float4*)(Xgb + (size_t)xk * Ntot + n0 + xn4);
            xreg.x *= g.x / (1.f + __expf(-g.x));
            xreg.y *= g.y / (1.f + __expf(-g.y));
            xreg.z *= g.z / (1.f + __expf(-g.z));
            xreg.w *= g.w / (1.f + __expf(-g.w));
        }
        if (invMode) {
            ssq.x += xreg.x * xreg.x; ssq.y += xreg.y * xreg.y;
            ssq.z += xreg.z * xreg.z; ssq.w += xreg.w * xreg.w;
        }
    }

    #pragma unroll 1
    for (int kt = 0; kt < 16; kt++) {
        if (kt) __syncthreads();   // previous MMAs must finish before overwrite
        {
            __half2 hi, lo;
            __half2* wh0 = (__half2*)&Whh[wm_ld][0];
            __half2* wl0 = (__half2*)&Whl[wm_ld][0];
            split2(wreg0.x, wreg0.y, hi, lo); wh0[2*wkw]   = hi; wl0[2*wkw]   = lo;
            split2(wreg0.z, wreg0.w, hi, lo); wh0[2*wkw+1] = hi; wl0[2*wkw+1] = lo;
            __half2* wh1 = (__half2*)&Whh[128 + wm_ld][0];
            __half2* wl1 = (__half2*)&Whl[128 + wm_ld][0];
            split2(wreg1.x, wreg1.y, hi, lo); wh1[2*wkw]   = hi; wl1[2*wkw]   = lo;
            split2(wreg1.z, wreg1.w, hi, lo); wh1[2*wkw+1] = hi; wl1[2*wkw+1] = lo;
            __half2* xh = (__half2*)&Xhh[xk][xn4];
            __half2* xl = (__half2*)&Xhl[xk][xn4];
            split2(xreg.x, xreg.y, hi, lo); xh[0] = hi; xl[0] = lo;
            split2(xreg.z, xreg.w, hi, lo); xh[1] = hi; xl[1] = lo;
        }
        __syncthreads();
        if (kt < 15) {
            int k0 = (kt + 1) * 16;
            const float* wp = W + (size_t)(o0 + wm_ld) * 256 + k0 + wkw * 4;
            wreg0 = *(const float4*)wp;
            wreg1 = *(const float4*)(wp + (size_t)128 * 256);
            xreg = *(const float4*)(Xb + (size_t)(k0 + xk) * Ntot + n0 + xn4);
            if (Xgb) {
                float4 g = *(const float4*)(Xgb + (size_t)(k0 + xk) * Ntot + n0 + xn4);
                xreg.x *= g.x / (1.f + __expf(-g.x));
                xreg.y *= g.y / (1.f + __expf(-g.y));
                xreg.z *= g.z / (1.f + __expf(-g.z));
                xreg.w *= g.w / (1.f + __expf(-g.w));
            }
            if (invMode) {
                ssq.x += xreg.x * xreg.x; ssq.y += xreg.y * xreg.y;
                ssq.z += xreg.z * xreg.z; ssq.w += xreg.w * xreg.w;
            }
        }
        unsigned ah[2][4], al[2][4];
        #pragma unroll
        for (int mt = 0; mt < 2; mt++) {
            int row = wm * 32 + mt * 16 + (lane & 15);
            ldmx4(ah[mt], sptr(&Whh[row][(lane >> 4) * 8]));
            ldmx4(al[mt], sptr(&Whl[row][(lane >> 4) * 8]));
        }
        #pragma unroll
        for (int nt = 0; nt < 8; nt++) {
            unsigned bh0, bh1, bl0, bl1;
            ldmx2t(bh0, bh1, sptr(&Xhh[lane & 15][wn * 64 + nt * 8]));
            ldmx2t(bl0, bl1, sptr(&Xhl[lane & 15][wn * 64 + nt * 8]));
            mma_h(acc[0][nt], ah[0], bh0, bh1);
            mma_h(acc[0][nt], ah[0], bl0, bl1);
            mma_h(acc[0][nt], al[0], bh0, bh1);
            mma_h(acc[1][nt], ah[1], bh0, bh1);
            mma_h(acc[1][nt], ah[1], bl0, bl1);
            mma_h(acc[1][nt], al[1], bh0, bh1);
        }
    }

    if (invMode) {
        part[xk][tid & 31] = ssq;
        __syncthreads();
        if (tid < 32) {
            float4 s = part[0][tid];
            #pragma unroll
            for (int r = 1; r < 16; r++) {
                float4 p = part[r][tid];
                s.x += p.x; s.y += p.y; s.z += p.z; s.w += p.w;
            }
            invs[tid * 4 + 0] = rsqrtf(s.x * (1.f / CC) + EPSV);
            invs[tid * 4 + 1] = rsqrtf(s.y * (1.f / CC) + EPSV);
            invs[tid * 4 + 2] = rsqrtf(s.z * (1.f / CC) + EPSV);
            invs[tid * 4 + 3] = rsqrtf(s.w * (1.f / CC) + EPSV);
        }
        __syncthreads();
    }

    #pragma unroll
    for (int mt = 0; mt < 2; mt++) {
        int row = o0 + wm * 32 + mt * 16 + group;
        float bv0 = bias ? bias[row]     : 0.f;
        float bv8 = bias ? bias[row + 8] : 0.f;
        #pragma unroll
        for (int nt = 0; nt < 8; nt++) {
            int cl = wn * 64 + nt * 8 + tid4 * 2;
            int col = n0 + cl;
            size_t i0 = (size_t)row * Ntot + col;
            size_t i8 = (size_t)(row + 8) * Ntot + col;
            float a0 = acc[mt][nt][0], a1 = acc[mt][nt][1];
            float a2 = acc[mt][nt][2], a3 = acc[mt][nt][3];
            if (invMode) {
                float s0 = invs[cl], s1 = invs[cl + 1];
                a0 *= s0; a1 *= s1; a2 *= s0; a3 *= s1;
            }
            float2 v0 = make_float2(a0 + bv0, a1 + bv0);
            float2 v8 = make_float2(a2 + bv8, a3 + bv8);
            if (Ab) {
                float2 r0 = *(const float2*)(Ab + i0);
                float2 r8 = *(const float2*)(Ab + i8);
                v0.x += r0.x; v0.y += r0.y;
                v8.x += r8.x; v8.y += r8.y;
            }
            *(float2*)(Yb + i0) = v0;
            *(float2*)(Yb + i8) = v8;
        }
    }
}

// ---------------- W row-scale precompute ----------------------------------------
__global__ void wscale_kernel(const float* __restrict__ W, const float* __restrict__ rs,
                              float* __restrict__ Wo, int n) {
    int i = blockIdx.x * 256 + threadIdx.x;
    if (i < n) Wo[i] = W[i] * rs[i & 255];
}

// ---------------- merged precompute GEMMs: P (tn) and OV (nn) -------------------
__global__ void pre_gemms(const float* __restrict__ kw, const float* __restrict__ qw,
                          const float* __restrict__ ow, const float* __restrict__ vw,
                          float* __restrict__ P, float* __restrict__ OV) {
    __shared__ float As[32][33], Bs[32][33];
    int mode = blockIdx.z;
    int m0 = blockIdx.y * 32, n0 = blockIdx.x * 32;
    int tx = threadIdx.x, ty = threadIdx.y;
    int tid = ty * 16 + tx;
    const float* A = mode ? ow : kw;
    const float* B = mode ? vw : qw;
    float acc[2][2] = {{0.f,0.f},{0.f,0.f}};
    for (int r0 = 0; r0 < CC; r0 += 32) {
        #pragma unroll
        for (int i = 0; i < 4; i++) {
            int e = i * 256 + tid;
            int a = e >> 5, c = e & 31;
            Bs[a][c] = B[(size_t)(r0 + a) * CC + n0 + c];
            As[a][c] = mode ? A[(size_t)(m0 + a) * CC + r0 + c]
                            : A[(size_t)(r0 + a) * CC + m0 + c];
        }
        __syncthreads();
        if (mode) {
            #pragma unroll
            for (int r = 0; r < 32; r++) {
                float a0 = As[ty*2][r], a1 = As[ty*2+1][r];
                float b0 = Bs[r][tx*2], b1 = Bs[r][tx*2+1];
                acc[0][0] += a0*b0; acc[0][1] += a0*b1;
                acc[1][0] += a1*b0; acc[1][1] += a1*b1;
            }
        } else {
            #pragma unroll
            for (int r = 0; r < 32; r++) {
                float a0 = As[r][ty*2], a1 = As[r][ty*2+1];
                float b0 = Bs[r][tx*2], b1 = Bs[r][tx*2+1];
                acc[0][0] += a0*b0; acc[0][1] += a0*b1;
                acc[1][0] += a1*b0; acc[1][1] += a1*b1;
            }
        }
        __syncthreads();
    }
    float* C = mode ? OV : P;
    #pragma unroll
    for (int i = 0; i < 2; i++)
        #pragma unroll
        for (int j = 0; j < 2; j++)
            C[(size_t)(m0 + ty*2 + i) * CC + n0 + tx*2 + j] = acc[i][j];
}

// ---------------- parallel vector precompute (256 blocks) -----------------------
__global__ void vec_pre_kernel(const float* __restrict__ qw, const float* __restrict__ qb,
                               const float* __restrict__ kw, const float* __restrict__ kb,
                               const float* __restrict__ ow, const float* __restrict__ ob,
                               const float* __restrict__ vb) {
    __shared__ float red[4][8];
    int j = blockIdx.x;
    int o = threadIdx.x;
    float su = qb[o] * kw[(size_t)o * CC + j];
    float sw = qw[(size_t)o * CC + j] * kb[o];
    float sb = ow[(size_t)j * CC + o] * vb[o];
    float s0 = (j == 0) ? qb[o] * kb[o] : 0.f;
    #pragma unroll
    for (int d = 16; d; d >>= 1) {
        su += __shfl_xor_sync(0xffffffffu, su, d);
        sw += __shfl_xor_sync(0xffffffffu, sw, d);
        sb += __shfl_xor_sync(0xffffffffu, sb, d);
        s0 += __shfl_xor_sync(0xffffffffu, s0, d);
    }
    if ((o & 31) == 0) {
        int w = o >> 5;
        red[0][w] = su; red[1][w] = sw; red[2][w] = sb; red[3][w] = s0;
    }
    __syncthreads();
    if (o == 0) {
        float a = 0.f, b2 = 0.f, c = 0.f, d2 = 0.f;
        #pragma unroll
        for (int i = 0; i < 8; i++) {
            a += red[0][i]; b2 += red[1][i]; c += red[2][i]; d2 += red[3][i];
        }
        g_u[j] = a;
        g_w2[j] = b2;
        g_bias2[j] = c + ob[j];
        if (j == 0) g_misc[0] = d2;
    }
}

// ---------------- depthwise 3x3 causal conv + SiLU (fp16 input) -----------------
#define TB 8
__global__ void dwconv8_kernel(const __half* __restrict__ src,
                               const float* __restrict__ dww, const float* __restrict__ dwb,
                               float* __restrict__ emb) {
    int nblk = TT / TB;
    long idx = blockIdx.x;
    int tb = (int)(idx % nblk);
    long bc = idx / nblk;
    int c = (int)(bc % CC);
    int t0 = tb * TB;
    int f = threadIdx.x;
    __shared__ float rows[TB + 2][FF + 2];
    size_t chbase = (size_t)bc * TT * FF;
    #pragma unroll
    for (int r = 0; r < TB + 2; r++) {
        int tt = t0 - 2 + r;
        rows[r][f + 1] = (tt >= 0) ? __half2float(src[chbase + (size_t)tt * FF + f]) : 0.f;
        if (f == 0) { rows[r][0] = 0.f; rows[r][FF + 1] = 0.f; }
    }
    __syncthreads();
    float w[9];
    #pragma unroll
    for (int i = 0; i < 9; i++) w[i] = dww[c * 9 + i];
    float bv = dwb[c];
    #pragma unroll
    for (int r = 0; r < TB; r++) {
        float s = bv;
        #pragma unroll
        for (int dt = 0; dt < 3; dt++)
            #pragma unroll
            for (int df = 0; df < 3; df++)
                s += w[dt * 3 + df] * rows[r + dt][f + df];
        s = s / (1.f + __expf(-s));
        emb[chbase + (size_t)(t0 + r) * FF + f] = s;
    }
}

// ---------------- qseed: batched skinny GEMM on tensor cores --------------------
// Y[row, k] = sum_f emb_flat[row, f] * basis[k, f];  rows = B*C*T
__global__ void __launch_bounds__(256, 2)
qseed_mma_kernel(const float* __restrict__ emb, const float* __restrict__ basis,
                 float* __restrict__ Y)
{
    __shared__ __half Ah[2][128][40];
    __shared__ __half Bh[256 * 40];      // [f][k], flat
    long row0 = (long)blockIdx.x * 128;
    int tid = threadIdx.x;
    int lane = tid & 31, warp = tid >> 5;
    int group = lane >> 2, tid4 = lane & 3;

    // basis -> Bh[f*40 + k] fp16 (transposed)
    #pragma unroll
    for (int i = 0; i < 8; i++) {
        int e = i * 256 + tid;
        int k = e >> 6, f4 = e & 63;
        float4 v = *(const float4*)(basis + (size_t)k * 256 + f4 * 4);
        Bh[(f4 * 4 + 0) * 40 + k] = __float2half(v.x);
        Bh[(f4 * 4 + 1) * 40 + k] = __float2half(v.y);
        Bh[(f4 * 4 + 2) * 40 + k] = __float2half(v.z);
        Bh[(f4 * 4 + 3) * 40 + k] = __float2half(v.w);
    }

    float acc[4][4];
    #pragma unroll
    for (int nt = 0; nt < 4; nt++)
        #pragma unroll
        for (int r = 0; r < 4; r++) acc[nt][r] = 0.f;

    float4 areg[4];
    #pragma unroll
    for (int i = 0; i < 4; i++) {
        int e = i * 256 + tid;
        int m = e >> 3, j = e & 7;
        areg[i] = *(const float4*)(emb + (row0 + m) * 256 + j * 4);
    }

    #pragma unroll 1
    for (int kt = 0; kt < 8; kt++) {
        int buf = kt & 1;
        #pragma unroll
        for (int i = 0; i < 4; i++) {
            int e = i * 256 + tid;
            int m = e >> 3, j = e & 7;
            __half2* d = (__half2*)&Ah[buf][m][j * 4];
            d[0] = __floats2half2_rn(areg[i].x, areg[i].y);
            d[1] = __floats2half2_rn(areg[i].z, areg[i].w);
        }
        __syncthreads();
        if (kt < 7) {
            int ksn = (kt + 1) * 32;
            #pragma unroll
            for (int i = 0; i < 4; i++) {
                int e = i * 256 + tid;
                int m = e >> 3, j = e & 7;
                areg[i] = *(const float4*)(emb + (row0 + m) * 256 + ksn + j * 4);
            }
        }
        #pragma unroll
        for (int kk = 0; kk < 2; kk++) {
            unsigned a[4];
            ldmx4(a, sptr(&Ah[buf][warp * 16 + (lane & 15)][kk * 16 + (lane >> 4) * 8]));
            #pragma unroll
            for (int nt = 0; nt < 4; nt++) {
                unsigned b0, b1;
                ldmx2t(b0, b1, sptr(&Bh[(kt * 32 + kk * 16 + (lane & 15)) * 40 + nt * 8]));
                mma_h(acc[nt], a, b0, b1);
            }
        }
    }

    long r1 = row0 + warp * 16 + group;
    #pragma unroll
    for (int nt = 0; nt < 4; nt++) {
        int col = nt * 8 + tid4 * 2;
        *(float2*)(Y + r1 * 32 + col)       = make_float2(acc[nt][0], acc[nt][1]);
        *(float2*)(Y + (r1 + 8) * 32 + col) = make_float2(acc[nt][2], acc[nt][3]);
    }
}

// ---------------- colt: colt[bt][k] = sum_c w2[c]*qseed[b,c,t,k] + s0 ----------
__global__ void colt_kernel(const float* __restrict__ qs) {
    __shared__ float part[8][32];
    int bt = blockIdx.x;
    int b = bt / TT, t = bt % TT;
    size_t base = ((size_t)b * CC * TT + t) * KK;
    int k = threadIdx.x & 31, cg = threadIdx.x >> 5;
    float s = 0.f;
    for (int c = cg; c < CC; c += 8)
        s += g_w2[c] * qs[base + (size_t)c * TT * KK + k];
    part[cg][k] = s;
    __syncthreads();
    if (threadIdx.x < 32) {
        float tot = g_misc[0];
        #pragma unroll
        for (int i = 0; i < 8; i++) tot += part[i][k];
        g_colt[bt * KK + k] = tot;
    }
}

// ---------------- fused attention: scores(MMA) + softmax + pooled(MMA) ----------
// smem: Eh[256][264] fp16 | union{ q2T[48][264] fp16, scoresF[33][264] f32,
//       poolSm[256][34] f32 } | Wt[256][40] fp16
#define ATTN_SMEM (256*264*2 + 34848 + 256*40*2)
__global__ void __launch_bounds__(256, 1)
attn_mma_kernel(const float* __restrict__ Q2, const float* __restrict__ emb,
                const float* __restrict__ rb,
                const float* __restrict__ ssp, const float* __restrict__ psp,
                float* __restrict__ pooled)
{
    extern __shared__ __align__(16) char sm_[];
    __half* Eh = (__half*)sm_;
    char* regU = sm_ + 256 * 264 * 2;
    __half* q2T = (__half*)regU;
    float* scoresF = (float*)regU;
    float* poolSm = (float*)regU;
    __half* Wt = (__half*)(regU + 34848);
    __shared__ float colts[32];

    int bt = blockIdx.x;
    int b = bt / TT, t = bt % TT;
    size_t qframe = ((size_t)b * CC * TT + t) * KK;
    size_t eframe = ((size_t)b * CC * TT + t) * FF;
    int tid = threadIdx.x;
    int lane = tid & 31, warp = tid >> 5;
    int group = lane >> 2, tid4 = lane & 3;

    // ---- load emb frame -> Eh fp16
    #pragma unroll 8
    for (int i = 0; i < 64; i++) {
        int e = i * 256 + tid;
        int c = e >> 6, f4 = e & 63;
        float4 v = *(const float4*)(emb + eframe + (size_t)c * TT * FF + f4 * 4);
        __half2* dst = (__half2*)&Eh[c * 264 + f4 * 4];
        dst[0] = __floats2half2_rn(v.x, v.y);
        dst[1] = __floats2half2_rn(v.z, v.w);
    }
    // ---- zero q2T rows 32..47, then u row (32)
    for (int e = tid; e < 16 * 264; e += 256)
        q2T[32 * 264 + e] = __float2half(0.f);
    q2T[32 * 264 + tid] = __float2half(g_u[tid]);
    // ---- load q2 frame [c][k] -> q2T[k][c] fp16
    #pragma unroll
    for (int i = 0; i < 8; i++) {
        int e = i * 256 + tid;
        int c = e >> 3, j = e & 7;
        float4 v = *(const float4*)(Q2 + qframe + (size_t)c * TT * KK + j * 4);
        q2T[(4*j + 0) * 264 + c] = __float2half(v.x);
        q2T[(4*j + 1) * 264 + c] = __float2half(v.y);
        q2T[(4*j + 2) * 264 + c] = __float2half(v.z);
        q2T[(4*j + 3) * 264 + c] = __float2half(v.w);
    }
    if (tid < 32) colts[tid] = g_colt[bt * KK + tid];
    __syncthreads();

    // ---- pass 1: scores[k(48), f] MMA; warp owns 32 f-columns
    float acc1[3][4][4];
    #pragma unroll
    for (int mt = 0; mt < 3; mt++)
        #pragma unroll
        for (int nt = 0; nt < 4; nt++)
            #pragma unroll
            for (int r = 0; r < 4; r++) acc1[mt][nt][r] = 0.f;

    #pragma unroll 1
    for (int ks = 0; ks < 256; ks += 16) {
        unsigned a[3][4];
        #pragma unroll
        for (int mt = 0; mt < 3; mt++)
            ldmx4(a[mt], sptr(&q2T[(mt * 16 + (lane & 15)) * 264 + ks + (lane >> 4) * 8]));
        #pragma unroll
        for (int nt = 0; nt < 4; nt++) {
            unsigned b0, b1;
            ldmx2t(b0, b1, sptr(&Eh[(ks + (lane & 15)) * 264 + warp * 32 + nt * 8]));
            mma_h(acc1[0][nt], a[0], b0, b1);
            mma_h(acc1[1][nt], a[1], b0, b1);
            mma_h(acc1[2][nt], a[2], b0, b1);
        }
    }
    __syncthreads();   // q2T reads complete; region becomes scoresF

    #pragma unroll
    for (int mt = 0; mt < 2; mt++)
        #pragma unroll
        for (int nt = 0; nt < 4; nt++) {
            int row = mt * 16 + group;
            int col = warp * 32 + nt * 8 + tid4 * 2;
            *(float2*)&scoresF[row * 264 + col]       = make_float2(acc1[mt][nt][0], acc1[mt][nt][1]);
            *(float2*)&scoresF[(row + 8) * 264 + col] = make_float2(acc1[mt][nt][2], acc1[mt][nt][3]);
        }
    if (group == 0) {
        #pragma unroll
        for (int nt = 0; nt < 4; nt++) {
            int col = warp * 32 + nt * 8 + tid4 * 2;
            *(float2*)&scoresF[32 * 264 + col] = make_float2(acc1[2][nt][0], acc1[2][nt][1]);
        }
    }
    __syncthreads();

    // ---- softmax per k; weights -> Wt[f][k] fp16
    float ss = *ssp, ps = *psp;
    #pragma unroll
    for (int rr = 0; rr < 4; rr++) {
        int k = warp * 4 + rr;
        float cv = colts[k];
        float v[8];
        float m = -1e30f;
        #pragma unroll
        for (int i = 0; i < 8; i++) {
            int f = lane + 32 * i;
            float raw = scoresF[k * 264 + f];
            float uu  = scoresF[32 * 264 + f];
            v[i] = ss * (raw + uu + cv) + rb[k * FF + f] * ps;
            m = fmaxf(m, v[i]);
        }
        #pragma unroll
        for (int o = 16; o; o >>= 1) m = fmaxf(m, __shfl_xor_sync(0xffffffffu, m, o));
        float s = 0.f;
        #pragma unroll
        for (int i = 0; i < 8; i++) { v[i] = __expf(v[i] - m); s += v[i]; }
        #pragma unroll
        for (int o = 16; o; o >>= 1) s += __shfl_xor_sync(0xffffffffu, s, o);
        float inv = 1.f / s;
        #pragma unroll
        for (int i = 0; i < 8; i++) {
            int f = lane + 32 * i;
            Wt[f * 40 + k] = __float2half(v[i] * inv);
        }
    }
    __syncthreads();

    // ---- pass 2: pooled[c, k] = sum_f Eh[c,f] * Wt[f,k]; warp owns 32 c-rows
    float acc2[2][4][4];
    #pragma unroll
    for (int mt = 0; mt < 2; mt++)
        #pragma unroll
        for (int nt = 0; nt < 4; nt++)
            #pragma unroll
            for (int r = 0; r < 4; r++) acc2[mt][nt][r] = 0.f;

    #pragma unroll 1
    for (int fs = 0; fs < 256; fs += 16) {
        unsigned a[2][4];
        #pragma unroll
        for (int mt = 0; mt < 2; mt++)
            ldmx4(a[mt], sptr(&Eh[(warp * 32 + mt * 16 + (lane & 15)) * 264 + fs + (lane >> 4) * 8]));
        #pragma unroll
        for (int nt = 0; nt < 4; nt++) {
            unsigned b0, b1;
            ldmx2t(b0, b1, sptr(&Wt[(fs + (lane & 15)) * 40 + nt * 8]));
            mma_h(acc2[0][nt], a[0], b0, b1);
            mma_h(acc2[1][nt], a[1], b0, b1);
        }
    }
    __syncthreads();   // scoresF readers done; region becomes poolSm

    #pragma unroll
    for (int mt = 0; mt < 2; mt++)
        #pragma unroll
        for (int nt = 0; nt < 4; nt++) {
            int row = warp * 32 + mt * 16 + group;
            int col = nt * 8 + tid4 * 2;
            *(float2*)&poolSm[row * 34 + col]       = make_float2(acc2[mt][nt][0], acc2[mt][nt][1]);
            *(float2*)&poolSm[(row + 8) * 34 + col] = make_float2(acc2[mt][nt][2], acc2[mt][nt][3]);
        }
    __syncthreads();
    #pragma unroll
    for (int i = 0; i < 32; i++) {
        int e = i * 256 + tid;
        int c = e >> 5, k = e & 31;
        pooled[qframe + (size_t)c * TT * KK + k] = poolSm[c * 34 + k];
    }
}

// ---------------- host launcher --------------------------------------------------
extern "C" void kernel_launch(void* const* d_in, const int* in_sizes, int n_in,
                              void* d_out, int out_size) {
    const float* x          = (const float*)d_in[0];
    const float* pre_norm_w = (const float*)d_in[1];
    const float* pre_pw_w   = (const float*)d_in[2];
    const float* pre_pw_b   = (const float*)d_in[3];
    const float* pre_dw_w   = (const float*)d_in[4];
    const float* pre_dw_b   = (const float*)d_in[5];
    const float* q_w        = (const float*)d_in[6];
    const float* q_b        = (const float*)d_in[7];
    const float* k_w        = (const float*)d_in[8];
    const float* k_b        = (const float*)d_in[9];
    const float* v_w        = (const float*)d_in[10];
    const float* v_b        = (const float*)d_in[11];
    const float* out_w      = (const float*)d_in[12];
    const float* out_b      = (const float*)d_in[13];
    const float* ffn_norm_w = (const float*)d_in[14];
    const float* ffn_in_w   = (const float*)d_in[15];
    const float* ffn_in_b   = (const float*)d_in[16];
    const float* ffn_out_w  = (const float*)d_in[17];
    const float* ffn_out_b  = (const float*)d_in[18];
    const float* score_scale= (const float*)d_in[19];
    const float* prior_scale= (const float*)d_in[20];
    const float* query_basis= (const float*)d_in[21];
    const float* routing_bias=(const float*)d_in[22];

    float* out        = (float*)d_out;
    float* out_hidden = out;
    float* out_emb    = out + (size_t)BB * CC * TT * KK;

    float *emb0, *qseed, *q2, *pooled, *hidden, *hffn;
    float *P, *OV, *Wp, *Wf, *bias2;
    cudaGetSymbolAddress((void**)&emb0,   g_emb0);
    cudaGetSymbolAddress((void**)&qseed,  g_qseed);
    cudaGetSymbolAddress((void**)&q2,     g_q2);
    cudaGetSymbolAddress((void**)&pooled, g_pooled);
    cudaGetSymbolAddress((void**)&hidden, g_hidden);
    cudaGetSymbolAddress((void**)&hffn,   g_hffn);
    cudaGetSymbolAddress((void**)&P,      g_P);
    cudaGetSymbolAddress((void**)&OV,     g_OV);
    cudaGetSymbolAddress((void**)&Wp,     g_Wp);
    cudaGetSymbolAddress((void**)&Wf,     g_Wf);
    cudaGetSymbolAddress((void**)&bias2,  g_bias2);

    cudaFuncSetAttribute(attn_mma_kernel,
                         cudaFuncAttributeMaxDynamicSharedMemorySize, ATTN_SMEM);

    const int NBT = BB * TT;       // 800
    const int NF  = TT * FF;       // 102400
    const int NK  = TT * KK;       // 12800

    // precompute
    wscale_kernel<<<256, 256>>>(pre_pw_w, pre_norm_w, Wp, CC*CC);
    wscale_kernel<<<512, 256>>>(ffn_in_w, ffn_norm_w, Wf, 2*CC*CC);
    pre_gemms<<<dim3(8, 8, 2), dim3(16, 16)>>>(k_w, q_w, out_w, v_w, P, OV);
    vec_pre_kernel<<<256, 256>>>(q_w, q_b, k_w, k_b, out_w, out_b, v_b);

    // 1. pre pw with fused RMSNorm -> emb0 (fp16 storage)
    gemm_h<<<dim3(NF/128, 1, BB), 512>>>(Wp, pre_pw_b, x, nullptr,
                                         nullptr, (__half*)emb0, nullptr,
                                         1, CC, NF, (long)CC * NF);
    // 2. depthwise conv + SiLU -> emb (into d_out)
    dwconv8_kernel<<<(long)BB*CC*(TT/TB), FF>>>((const __half*)emb0, pre_dw_w, pre_dw_b, out_emb);
    // 3. qseed = emb @ basis^T
    qseed_mma_kernel<<<(BB*CC*TT)/128, 256>>>(out_emb, query_basis, qseed);
    // 4. colt
    colt_kernel<<<NBT, 256>>>(qseed);
    // 5. q2 = P @ qseed
    gemm_h<<<dim3(NK/128, 1, BB), 512>>>(P, nullptr, qseed, nullptr, q2, nullptr, nullptr,
                                         0, CC, NK, (long)CC * NK);
    // 6. fused attention (scores MMA + softmax + pooled MMA)
    attn_mma_kernel<<<NBT, 256, ATTN_SMEM>>>(q2, out_emb, routing_bias,
                                             score_scale, prior_scale, pooled);
    // 7. hidden = OV @ pooled + bias2   [split-fp16, near-fp32]
    gemm_hs<<<dim3(NK/128, 1, BB), 512>>>(OV, bias2, pooled, nullptr, hidden, nullptr,
                                          0, CC, NK, (long)CC * NK);
    // 8. ffn_in with fused RMSNorm       [split-fp16]
    gemm_hs<<<dim3(NK/128, 2, BB), 512>>>(Wf, ffn_in_b, hidden, nullptr, hffn, nullptr,
                                          1, 2*CC, NK, (long)CC * NK);
    // 9. ffn_out with fused GLU load + residual -> d_out   [split-fp16]
    gemm_hs<<<dim3(NK/128, 1, BB), 512>>>(ffn_out_w, ffn_out_b, hffn, hffn + (size_t)CC * NK,
                                          out_hidden, hidden,
                                          0, CC, NK, (long)2 * CC * NK);
}

// round 9
// speedup vs baseline: 1.0551x; 1.0551x over previous
#include <cuda_runtime.h>
#include <cuda_fp16.h>
#include <math.h>

#define BB 2
#define CC 256
#define TT 400
#define FF 256
#define KK 32
#define EPSV 1e-6f

typedef unsigned long long ull;

// ---------------- scratch ------------------------------------------------------
__device__ float  g_emb0   [(size_t)BB*CC*TT*FF];   // used as fp16 (half the space)
__device__ __half g_embh   [(size_t)BB*CC*TT*FF];   // fp16 copy of emb
__device__ float  g_qseed  [(size_t)BB*CC*TT*KK];
__device__ float  g_q2     [(size_t)BB*CC*TT*KK];
__device__ float  g_pooled [(size_t)BB*CC*TT*KK];
__device__ float  g_hidden [(size_t)BB*CC*TT*KK];
__device__ float  g_hffn   [(size_t)BB*2*CC*TT*KK];
__device__ float  g_P      [CC*CC];
__device__ float  g_OV     [CC*CC];
__device__ float  g_Wp     [CC*CC];
__device__ float  g_Wf     [2*CC*CC];
__device__ float  g_u      [CC];
__device__ float  g_w2     [CC];
__device__ float  g_bias2  [CC];
__device__ float  g_colt   [BB*TT*KK];
__device__ float  g_misc   [4];

// ---------------- helpers ------------------------------------------------------
__device__ __forceinline__ unsigned sptr(const void* p) {
    return (unsigned)__cvta_generic_to_shared(p);
}
__device__ __forceinline__ void ldmx4(unsigned* a, unsigned addr) {
    asm volatile("ldmatrix.sync.aligned.m8n8.x4.shared.b16 {%0,%1,%2,%3}, [%4];"
        : "=r"(a[0]), "=r"(a[1]), "=r"(a[2]), "=r"(a[3]) : "r"(addr));
}
__device__ __forceinline__ void ldmx2t(unsigned& b0, unsigned& b1, unsigned addr) {
    asm volatile("ldmatrix.sync.aligned.m8n8.x2.trans.shared.b16 {%0,%1}, [%2];"
        : "=r"(b0), "=r"(b1) : "r"(addr));
}
__device__ __forceinline__ void mma_h(float* c, const unsigned* a, unsigned b0, unsigned b1) {
    asm volatile("mma.sync.aligned.m16n8k16.row.col.f32.f16.f16.f32 "
        "{%0,%1,%2,%3}, {%4,%5,%6,%7}, {%8,%9}, {%0,%1,%2,%3};"
        : "+f"(c[0]), "+f"(c[1]), "+f"(c[2]), "+f"(c[3])
        : "r"(a[0]), "r"(a[1]), "r"(a[2]), "r"(a[3]), "r"(b0), "r"(b1));
}
__device__ __forceinline__ void split2(float x, float y, __half2& hi, __half2& lo) {
    hi = __floats2half2_rn(x, y);
    float2 hf = __half22float2(hi);
    lo = __floats2half2_rn(x - hf.x, y - hf.y);
}

// ---------------- unified fp16 tensor-core GEMM --------------------------------
__global__ void __launch_bounds__(512, 1)
gemm_h(const float* __restrict__ W, const float* __restrict__ bias,
       const float* __restrict__ X, const float* __restrict__ Xg,
       float* __restrict__ Y, __half* __restrict__ Yh,
       const float* __restrict__ addsrc,
       int invMode, int Cout, int Ntot, long xbstride)
{
    __shared__ __half Wh[2][256][24];
    __shared__ __half Xh[2][16][136];
    __shared__ float invs[128];
    __shared__ float4 part[16][32];

    int b  = blockIdx.z;
    int n0 = blockIdx.x * 128;
    int o0 = blockIdx.y * 256;
    const float* Xb  = X + (size_t)b * xbstride;
    const float* Xgb = Xg ? Xg + (size_t)b * xbstride : nullptr;
    float* Yb  = Y  ? Y  + (size_t)b * (size_t)Cout * Ntot : nullptr;
    __half* Yhb = Yh ? Yh + (size_t)b * (size_t)Cout * Ntot : nullptr;
    const float* Ab = addsrc ? addsrc + (size_t)b * (size_t)Cout * Ntot : nullptr;

    int tid = threadIdx.x;
    int lane = tid & 31, warp = tid >> 5;
    int wm = warp & 7, wn = warp >> 3;
    int group = lane >> 2, tid4 = lane & 3;

    int wm_ld = tid >> 2;
    int wkw   = tid & 3;
    int xk    = tid >> 5;
    int xn4   = (tid & 31) * 4;

    float acc[2][8][4];
    #pragma unroll
    for (int mt = 0; mt < 2; mt++)
        #pragma unroll
        for (int nt = 0; nt < 8; nt++)
            #pragma unroll
            for (int r = 0; r < 4; r++) acc[mt][nt][r] = 0.f;

    float4 ssq = make_float4(0.f, 0.f, 0.f, 0.f);
    float4 wreg0, wreg1, xreg;

    {
        const float* wp = W + (size_t)(o0 + wm_ld) * 256 + wkw * 4;
        wreg0 = *(const float4*)wp;
        wreg1 = *(const float4*)(wp + (size_t)128 * 256);
        xreg = *(const float4*)(Xb + (size_t)xk * Ntot + n0 + xn4);
        if (Xgb) {
            float4 g = *(const float4*)(Xgb + (size_t)xk * Ntot + n0 + xn4);
            xreg.x *= g.x / (1.f + __expf(-g.x));
            xreg.y *= g.y / (1.f + __expf(-g.y));
            xreg.z *= g.z / (1.f + __expf(-g.z));
            xreg.w *= g.w / (1.f + __expf(-g.w));
        }
        if (invMode) {
            ssq.x += xreg.x * xreg.x; ssq.y += xreg.y * xreg.y;
            ssq.z += xreg.z * xreg.z; ssq.w += xreg.w * xreg.w;
        }
    }

    #pragma unroll 1
    for (int kt = 0; kt < 16; kt++) {
        int buf = kt & 1;
        {
            __half2* wr0 = (__half2*)&Wh[buf][wm_ld][0];
            wr0[2 * wkw]     = __floats2half2_rn(wreg0.x, wreg0.y);
            wr0[2 * wkw + 1] = __floats2half2_rn(wreg0.z, wreg0.w);
            __half2* wr1 = (__half2*)&Wh[buf][128 + wm_ld][0];
            wr1[2 * wkw]     = __floats2half2_rn(wreg1.x, wreg1.y);
            wr1[2 * wkw + 1] = __floats2half2_rn(wreg1.z, wreg1.w);
            __half2* xr = (__half2*)&Xh[buf][xk][xn4];
            xr[0] = __floats2half2_rn(xreg.x, xreg.y);
            xr[1] = __floats2half2_rn(xreg.z, xreg.w);
        }
        __syncthreads();
        if (kt < 15) {
            int k0 = (kt + 1) * 16;
            const float* wp = W + (size_t)(o0 + wm_ld) * 256 + k0 + wkw * 4;
            wreg0 = *(const float4*)wp;
            wreg1 = *(const float4*)(wp + (size_t)128 * 256);
            xreg = *(const float4*)(Xb + (size_t)(k0 + xk) * Ntot + n0 + xn4);
            if (Xgb) {
                float4 g = *(const float4*)(Xgb + (size_t)(k0 + xk) * Ntot + n0 + xn4);
                xreg.x *= g.x / (1.f + __expf(-g.x));
                xreg.y *= g.y / (1.f + __expf(-g.y));
                xreg.z *= g.z / (1.f + __expf(-g.z));
                xreg.w *= g.w / (1.f + __expf(-g.w));
            }
            if (invMode) {
                ssq.x += xreg.x * xreg.x; ssq.y += xreg.y * xreg.y;
                ssq.z += xreg.z * xreg.z; ssq.w += xreg.w * xreg.w;
            }
        }
        unsigned a[2][4];
        #pragma unroll
        for (int mt = 0; mt < 2; mt++) {
            int row = wm * 32 + mt * 16 + (lane & 15);
            ldmx4(a[mt], sptr(&Wh[buf][row][(lane >> 4) * 8]));
        }
        #pragma unroll
        for (int nt = 0; nt < 8; nt++) {
            unsigned b0, b1;
            ldmx2t(b0, b1, sptr(&Xh[buf][lane & 15][wn * 64 + nt * 8]));
            mma_h(acc[0][nt], a[0], b0, b1);
            mma_h(acc[1][nt], a[1], b0, b1);
        }
    }

    if (invMode) {
        part[xk][tid & 31] = ssq;
        __syncthreads();
        if (tid < 32) {
            float4 s = part[0][tid];
            #pragma unroll
            for (int r = 1; r < 16; r++) {
                float4 p = part[r][tid];
                s.x += p.x; s.y += p.y; s.z += p.z; s.w += p.w;
            }
            invs[tid * 4 + 0] = rsqrtf(s.x * (1.f / CC) + EPSV);
            invs[tid * 4 + 1] = rsqrtf(s.y * (1.f / CC) + EPSV);
            invs[tid * 4 + 2] = rsqrtf(s.z * (1.f / CC) + EPSV);
            invs[tid * 4 + 3] = rsqrtf(s.w * (1.f / CC) + EPSV);
        }
        __syncthreads();
    }

    #pragma unroll
    for (int mt = 0; mt < 2; mt++) {
        int row = o0 + wm * 32 + mt * 16 + group;
        float bv0 = bias ? bias[row]     : 0.f;
        float bv8 = bias ? bias[row + 8] : 0.f;
        #pragma unroll
        for (int nt = 0; nt < 8; nt++) {
            int cl = wn * 64 + nt * 8 + tid4 * 2;
            int col = n0 + cl;
            size_t i0 = (size_t)row * Ntot + col;
            size_t i8 = (size_t)(row + 8) * Ntot + col;
            float a0 = acc[mt][nt][0], a1 = acc[mt][nt][1];
            float a2 = acc[mt][nt][2], a3 = acc[mt][nt][3];
            if (invMode) {
                float s0 = invs[cl], s1 = invs[cl + 1];
                a0 *= s0; a1 *= s1; a2 *= s0; a3 *= s1;
            }
            float2 v0 = make_float2(a0 + bv0, a1 + bv0);
            float2 v8 = make_float2(a2 + bv8, a3 + bv8);
            if (Ab) {
                float2 r0 = *(const float2*)(Ab + i0);
                float2 r8 = *(const float2*)(Ab + i8);
                v0.x += r0.x; v0.y += r0.y;
                v8.x += r8.x; v8.y += r8.y;
            }
            if (Yhb) {
                *(__half2*)(Yhb + i0) = __floats2half2_rn(v0.x, v0.y);
                *(__half2*)(Yhb + i8) = __floats2half2_rn(v8.x, v8.y);
            } else {
                *(float2*)(Yb + i0) = v0;
                *(float2*)(Yb + i8) = v8;
            }
        }
    }
}

// ---------------- split-fp16 (near-fp32) GEMM, double-buffered -------------------
// Dynamic smem layout (halves unless noted):
//   Whh[2][256][24] | Whl[2][256][24] | Xhh[2][16][136] | Xhl[2][16][136]
//   | part[16][32] float4 | invs[128] float
#define HS_WHH 0
#define HS_WHL (2*256*24)
#define HS_XHH (2*(2*256*24))
#define HS_XHL (HS_XHH + 2*16*136)
#define HS_HALves (HS_XHL + 2*16*136)
#define HS_PART_B (HS_HALves * 2)
#define HS_INVS_B (HS_PART_B + 16*32*16)
#define HS_SMEM   (HS_INVS_B + 128*4)
__global__ void __launch_bounds__(512, 1)
gemm_hs(const float* __restrict__ W, const float* __restrict__ bias,
        const float* __restrict__ X, const float* __restrict__ Xg,
        float* __restrict__ Y, const float* __restrict__ addsrc,
        int invMode, int Cout, int Ntot, long xbstride)
{
    extern __shared__ __align__(16) char hsm[];
    __half* Whh = (__half*)(hsm) ;                 // [2][256][24]
    __half* Whl = (__half*)(hsm) + HS_WHL;
    __half* Xhh = (__half*)(hsm) + HS_XHH;         // [2][16][136]
    __half* Xhl = (__half*)(hsm) + HS_XHL;
    float4* part = (float4*)(hsm + HS_PART_B);     // [16][32]
    float*  invs = (float*)(hsm + HS_INVS_B);      // [128]

    int b  = blockIdx.z;
    int n0 = blockIdx.x * 128;
    int o0 = blockIdx.y * 256;
    const float* Xb  = X + (size_t)b * xbstride;
    const float* Xgb = Xg ? Xg + (size_t)b * xbstride : nullptr;
    float* Yb = Y + (size_t)b * (size_t)Cout * Ntot;
    const float* Ab = addsrc ? addsrc + (size_t)b * (size_t)Cout * Ntot : nullptr;

    int tid = threadIdx.x;
    int lane = tid & 31, warp = tid >> 5;
    int wm = warp & 7, wn = warp >> 3;
    int group = lane >> 2, tid4 = lane & 3;

    int wm_ld = tid >> 2;
    int wkw   = tid & 3;
    int xk    = tid >> 5;
    int xn4   = (tid & 31) * 4;

    float acc[2][8][4];
    #pragma unroll
    for (int mt = 0; mt < 2; mt++)
        #pragma unroll
        for (int nt = 0; nt < 8; nt++)
            #pragma unroll
            for (int r = 0; r < 4; r++) acc[mt][nt][r] = 0.f;

    float4 ssq = make_float4(0.f, 0.f, 0.f, 0.f);
    float4 wreg0, wreg1, xreg;

    {
        const float* wp = W + (size_t)(o0 + wm_ld) * 256 + wkw * 4;
        wreg0 = *(const float4*)wp;
        wreg1 = *(const float4*)(wp + (size_t)128 * 256);
        xreg = *(const float4*)(Xb + (size_t)xk * Ntot + n0 + xn4);
        if (Xgb) {
            float4 g = *(const float4*)(Xgb + (size_t)xk * Ntot + n0 + xn4);
            xreg.x *= g.x / (1.f + __expf(-g.x));
            xreg.y *= g.y / (1.f + __expf(-g.y));
            xreg.z *= g.z / (1.f + __expf(-g.z));
            xreg.w *= g.w / (1.f + __expf(-g.w));
        }
        if (invMode) {
            ssq.x += xreg.x * xreg.x; ssq.y += xreg.y * xreg.y;
            ssq.z += xreg.z * xreg.z; ssq.w += xreg.w * xreg.w;
        }
    }

    #pragma unroll 1
    for (int kt = 0; kt < 16; kt++) {
        int buf = kt & 1;
        {
            __half2 hi, lo;
            __half2* wh0 = (__half2*)&Whh[(buf * 256 + wm_ld) * 24];
            __half2* wl0 = (__half2*)&Whl[(buf * 256 + wm_ld) * 24];
            split2(wreg0.x, wreg0.y, hi, lo); wh0[2*wkw]   = hi; wl0[2*wkw]   = lo;
            split2(wreg0.z, wreg0.w, hi, lo); wh0[2*wkw+1] = hi; wl0[2*wkw+1] = lo;
            __half2* wh1 = (__half2*)&Whh[(buf * 256 + 128 + wm_ld) * 24];
            __half2* wl1 = (__half2*)&Whl[(buf * 256 + 128 + wm_ld) * 24];
            split2(wreg1.x, wreg1.y, hi, lo); wh1[2*wkw]   = hi; wl1[2*wkw]   = lo;
            split2(wreg1.z, wreg1.w, hi, lo); wh1[2*wkw+1] = hi; wl1[2*wkw+1] = lo;
            __half2* xh = (__half2*)&Xhh[(buf * 16 + xk) * 136 + xn4];
            __half2* xl = (__half2*)&Xhl[(buf * 16 + xk) * 136 + xn4];
            split2(xreg.x, xreg.y, hi, lo); xh[0] = hi; xl[0] = lo;
            split2(xreg.z, xreg.w, hi, lo); xh[1] = hi; xl[1] = lo;
        }
        __syncthreads();
        if (kt < 15) {
            int k0 = (kt + 1) * 16;
            const float* wp = W + (size_t)(o0 + wm_ld) * 256 + k0 + wkw * 4;
            wreg0 = *(const float4*)wp;
            wreg1 = *(const float4*)(wp + (size_t)128 * 256);
            xreg = *(const float4*)(Xb + (size_t)(k0 + xk) * Ntot + n0 + xn4);
            if (Xgb) {
                float4 g = *(const float4*)(Xgb + (size_t)(k0 + xk) * Ntot + n0 + xn4);
                xreg.x *= g.x / (1.f + __expf(-g.x));
                xreg.y *= g.y / (1.f + __expf(-g.y));
                xreg.z *= g.z / (1.f + __expf(-g.z));
                xreg.w *= g.w / (1.f + __expf(-g.w));
            }
            if (invMode) {
                ssq.x += xreg.x * xreg.x; ssq.y += xreg.y * xreg.y;
                ssq.z += xreg.z * xreg.z; ssq.w += xreg.w * xreg.w;
            }
        }
        unsigned ah[2][4], al[2][4];
        #pragma unroll
        for (int mt = 0; mt < 2; mt++) {
            int row = buf * 256 + wm * 32 + mt * 16 + (lane & 15);
            ldmx4(ah[mt], sptr(&Whh[row * 24 + (lane >> 4) * 8]));
            ldmx4(al[mt], sptr(&Whl[row * 24 + (lane >> 4) * 8]));
        }
        #pragma unroll
        for (int nt = 0; nt < 8; nt++) {
            unsigned bh0, bh1, bl0, bl1;
            int xrow = buf * 16 + (lane & 15);
            ldmx2t(bh0, bh1, sptr(&Xhh[xrow * 136 + wn * 64 + nt * 8]));
            ldmx2t(bl0, bl1, sptr(&Xhl[xrow * 136 + wn * 64 + nt * 8]));
            mma_h(acc[0][nt], ah[0], bh0, bh1);
            mma_h(acc[0][nt], ah[0], bl0, bl1);
            mma_h(acc[0][nt], al[0], bh0, bh1);
            mma_h(acc[1][nt], ah[1], bh0, bh1);
            mma_h(acc[1][nt], ah[1], bl0, bl1);
            mma_h(acc[1][nt], al[1], bh0, bh1);
        }
    }

    if (invMode) {
        part[xk * 32 + (tid & 31)] = ssq;
        __syncthreads();
        if (tid < 32) {
            float4 s = part[tid];
            #pragma unroll
            for (int r = 1; r < 16; r++) {
                float4 p = part[r * 32 + tid];
                s.x += p.x; s.y += p.y; s.z += p.z; s.w += p.w;
            }
            invs[tid * 4 + 0] = rsqrtf(s.x * (1.f / CC) + EPSV);
            invs[tid * 4 + 1] = rsqrtf(s.y * (1.f / CC) + EPSV);
            invs[tid * 4 + 2] = rsqrtf(s.z * (1.f / CC) + EPSV);
            invs[tid * 4 + 3] = rsqrtf(s.w * (1.f / CC) + EPSV);
        }
        __syncthreads();
    }

    #pragma unroll
    for (int mt = 0; mt < 2; mt++) {
        int row = o0 + wm * 32 + mt * 16 + group;
        float bv0 = bias ? bias[row]     : 0.f;
        float bv8 = bias ? bias[row + 8] : 0.f;
        #pragma unroll
        for (int nt = 0; nt < 8; nt++) {
            int cl = wn * 64 + nt * 8 + tid4 * 2;
            int col = n0 + cl;
            size_t i0 = (size_t)row * Ntot + col;
            size_t i8 = (size_t)(row + 8) * Ntot + col;
            float a0 = acc[mt][nt][0], a1 = acc[mt][nt][1];
            float a2 = acc[mt][nt][2], a3 = acc[mt][nt][3];
            if (invMode) {
                float s0 = invs[cl], s1 = invs[cl + 1];
                a0 *= s0; a1 *= s1; a2 *= s0; a3 *= s1;
            }
            float2 v0 = make_float2(a0 + bv0, a1 + bv0);
            float2 v8 = make_float2(a2 + bv8, a3 + bv8);
            if (Ab) {
                float2 r0 = *(const float2*)(Ab + i0);
                float2 r8 = *(const float2*)(Ab + i8);
                v0.x += r0.x; v0.y += r0.y;
                v8.x += r8.x; v8.y += r8.y;
            }
            *(float2*)(Yb + i0) = v0;
            *(float2*)(Yb + i8) = v8;
        }
    }
}

// ---------------- W row-scale precompute ----------------------------------------
__global__ void wscale_kernel(const float* __restrict__ W, const float* __restrict__ rs,
                              float* __restrict__ Wo, int n) {
    int i = blockIdx.x * 256 + threadIdx.x;
    if (i < n) Wo[i] = W[i] * rs[i & 255];
}

// ---------------- merged precompute GEMMs: P (tn) and OV (nn) -------------------
__global__ void pre_gemms(const float* __restrict__ kw, const float* __restrict__ qw,
                          const float* __restrict__ ow, const float* __restrict__ vw,
                          float* __restrict__ P, float* __restrict__ OV) {
    __shared__ float As[32][33], Bs[32][33];
    int mode = blockIdx.z;
    int m0 = blockIdx.y * 32, n0 = blockIdx.x * 32;
    int tx = threadIdx.x, ty = threadIdx.y;
    int tid = ty * 16 + tx;
    const float* A = mode ? ow : kw;
    const float* B = mode ? vw : qw;
    float acc[2][2] = {{0.f,0.f},{0.f,0.f}};
    for (int r0 = 0; r0 < CC; r0 += 32) {
        #pragma unroll
        for (int i = 0; i < 4; i++) {
            int e = i * 256 + tid;
            int a = e >> 5, c = e & 31;
            Bs[a][c] = B[(size_t)(r0 + a) * CC + n0 + c];
            As[a][c] = mode ? A[(size_t)(m0 + a) * CC + r0 + c]
                            : A[(size_t)(r0 + a) * CC + m0 + c];
        }
        __syncthreads();
        if (mode) {
            #pragma unroll
            for (int r = 0; r < 32; r++) {
                float a0 = As[ty*2][r], a1 = As[ty*2+1][r];
                float b0 = Bs[r][tx*2], b1 = Bs[r][tx*2+1];
                acc[0][0] += a0*b0; acc[0][1] += a0*b1;
                acc[1][0] += a1*b0; acc[1][1] += a1*b1;
            }
        } else {
            #pragma unroll
            for (int r = 0; r < 32; r++) {
                float a0 = As[r][ty*2], a1 = As[r][ty*2+1];
                float b0 = Bs[r][tx*2], b1 = Bs[r][tx*2+1];
                acc[0][0] += a0*b0; acc[0][1] += a0*b1;
                acc[1][0] += a1*b0; acc[1][1] += a1*b1;
            }
        }
        __syncthreads();
    }
    float* C = mode ? OV : P;
    #pragma unroll
    for (int i = 0; i < 2; i++)
        #pragma unroll
        for (int j = 0; j < 2; j++)
            C[(size_t)(m0 + ty*2 + i) * CC + n0 + tx*2 + j] = acc[i][j];
}

// ---------------- parallel vector precompute -------------------------------------
__global__ void vec_pre_kernel(const float* __restrict__ qw, const float* __restrict__ qb,
                               const float* __restrict__ kw, const float* __restrict__ kb,
                               const float* __restrict__ ow, const float* __restrict__ ob,
                               const float* __restrict__ vb) {
    __shared__ float red[4][8];
    int j = blockIdx.x;
    int o = threadIdx.x;
    float su = qb[o] * kw[(size_t)o * CC + j];
    float sw = qw[(size_t)o * CC + j] * kb[o];
    float sb = ow[(size_t)j * CC + o] * vb[o];
    float s0 = (j == 0) ? qb[o] * kb[o] : 0.f;
    #pragma unroll
    for (int d = 16; d; d >>= 1) {
        su += __shfl_xor_sync(0xffffffffu, su, d);
        sw += __shfl_xor_sync(0xffffffffu, sw, d);
        sb += __shfl_xor_sync(0xffffffffu, sb, d);
        s0 += __shfl_xor_sync(0xffffffffu, s0, d);
    }
    if ((o & 31) == 0) {
        int w = o >> 5;
        red[0][w] = su; red[1][w] = sw; red[2][w] = sb; red[3][w] = s0;
    }
    __syncthreads();
    if (o == 0) {
        float a = 0.f, b2 = 0.f, c = 0.f, d2 = 0.f;
        #pragma unroll
        for (int i = 0; i < 8; i++) {
            a += red[0][i]; b2 += red[1][i]; c += red[2][i]; d2 += red[3][i];
        }
        g_u[j] = a;
        g_w2[j] = b2;
        g_bias2[j] = c + ob[j];
        if (j == 0) g_misc[0] = d2;
    }
}

// ---------------- depthwise 3x3 causal conv + SiLU (fp16 in, fp32+fp16 out) -----
#define TB 8
__global__ void dwconv8_kernel(const __half* __restrict__ src,
                               const float* __restrict__ dww, const float* __restrict__ dwb,
                               float* __restrict__ emb, __half* __restrict__ embh) {
    int nblk = TT / TB;
    long idx = blockIdx.x;
    int tb = (int)(idx % nblk);
    long bc = idx / nblk;
    int c = (int)(bc % CC);
    int t0 = tb * TB;
    int f = threadIdx.x;
    __shared__ float rows[TB + 2][FF + 2];
    size_t chbase = (size_t)bc * TT * FF;
    #pragma unroll
    for (int r = 0; r < TB + 2; r++) {
        int tt = t0 - 2 + r;
        rows[r][f + 1] = (tt >= 0) ? __half2float(src[chbase + (size_t)tt * FF + f]) : 0.f;
        if (f == 0) { rows[r][0] = 0.f; rows[r][FF + 1] = 0.f; }
    }
    __syncthreads();
    float w[9];
    #pragma unroll
    for (int i = 0; i < 9; i++) w[i] = dww[c * 9 + i];
    float bv = dwb[c];
    #pragma unroll
    for (int r = 0; r < TB; r++) {
        float s = bv;
        #pragma unroll
        for (int dt = 0; dt < 3; dt++)
            #pragma unroll
            for (int df = 0; df < 3; df++)
                s += w[dt * 3 + df] * rows[r + dt][f + df];
        s = s / (1.f + __expf(-s));
        emb [chbase + (size_t)(t0 + r) * FF + f] = s;
        embh[chbase + (size_t)(t0 + r) * FF + f] = __float2half(s);
    }
}

// ---------------- qseed: batched skinny GEMM on tensor cores (fp16 input) -------
__global__ void __launch_bounds__(256, 2)
qseed_mma_kernel(const __half* __restrict__ embh, const float* __restrict__ basis,
                 float* __restrict__ Y)
{
    __shared__ __half Ah[2][128][40];
    __shared__ __half Bh[256 * 40];      // [f][k], flat
    long row0 = (long)blockIdx.x * 128;
    int tid = threadIdx.x;
    int lane = tid & 31, warp = tid >> 5;
    int group = lane >> 2, tid4 = lane & 3;

    #pragma unroll
    for (int i = 0; i < 8; i++) {
        int e = i * 256 + tid;
        int k = e >> 6, f4 = e & 63;
        float4 v = *(const float4*)(basis + (size_t)k * 256 + f4 * 4);
        Bh[(f4 * 4 + 0) * 40 + k] = __float2half(v.x);
        Bh[(f4 * 4 + 1) * 40 + k] = __float2half(v.y);
        Bh[(f4 * 4 + 2) * 40 + k] = __float2half(v.z);
        Bh[(f4 * 4 + 3) * 40 + k] = __float2half(v.w);
    }

    float acc[4][4];
    #pragma unroll
    for (int nt = 0; nt < 4; nt++)
        #pragma unroll
        for (int r = 0; r < 4; r++) acc[nt][r] = 0.f;

    // 128 rows x 32 halves per tile; per thread 2 x uint4 (8 halves each)
    uint4 areg[2];
    int am = tid >> 1;                 // row 0..127
    int aj = (tid & 1) * 16;           // half offset within 32
    areg[0] = *(const uint4*)(embh + (row0 + am) * 256 + aj);
    areg[1] = *(const uint4*)(embh + (row0 + am) * 256 + aj + 8);

    #pragma unroll 1
    for (int kt = 0; kt < 8; kt++) {
        int buf = kt & 1;
        *(uint4*)&Ah[buf][am][aj]     = areg[0];
        *(uint4*)&Ah[buf][am][aj + 8] = areg[1];
        __syncthreads();
        if (kt < 7) {
            int ksn = (kt + 1) * 32;
            areg[0] = *(const uint4*)(embh + (row0 + am) * 256 + ksn + aj);
            areg[1] = *(const uint4*)(embh + (row0 + am) * 256 + ksn + aj + 8);
        }
        #pragma unroll
        for (int kk = 0; kk < 2; kk++) {
            unsigned a[4];
            ldmx4(a, sptr(&Ah[buf][warp * 16 + (lane & 15)][kk * 16 + (lane >> 4) * 8]));
            #pragma unroll
            for (int nt = 0; nt < 4; nt++) {
                unsigned b0, b1;
                ldmx2t(b0, b1, sptr(&Bh[(kt * 32 + kk * 16 + (lane & 15)) * 40 + nt * 8]));
                mma_h(acc[nt], a, b0, b1);
            }
        }
    }

    long r1 = row0 + warp * 16 + group;
    #pragma unroll
    for (int nt = 0; nt < 4; nt++) {
        int col = nt * 8 + tid4 * 2;
        *(float2*)(Y + r1 * 32 + col)       = make_float2(acc[nt][0], acc[nt][1]);
        *(float2*)(Y + (r1 + 8) * 32 + col) = make_float2(acc[nt][2], acc[nt][3]);
    }
}

// ---------------- colt ------------------------------------------------------------
__global__ void colt_kernel(const float* __restrict__ qs) {
    __shared__ float part[8][32];
    int bt = blockIdx.x;
    int b = bt / TT, t = bt % TT;
    size_t base = ((size_t)b * CC * TT + t) * KK;
    int k = threadIdx.x & 31, cg = threadIdx.x >> 5;
    float s = 0.f;
    for (int c = cg; c < CC; c += 8)
        s += g_w2[c] * qs[base + (size_t)c * TT * KK + k];
    part[cg][k] = s;
    __syncthreads();
    if (threadIdx.x < 32) {
        float tot = g_misc[0];
        #pragma unroll
        for (int i = 0; i < 8; i++) tot += part[i][k];
        g_colt[bt * KK + k] = tot;
    }
}

// ---------------- fused attention: scores(MMA) + softmax + pooled(MMA) ----------
#define ATTN_SMEM (256*264*2 + 34848 + 256*40*2)
__global__ void __launch_bounds__(256, 1)
attn_mma_kernel(const float* __restrict__ Q2, const __half* __restrict__ embh,
                const float* __restrict__ rb,
                const float* __restrict__ ssp, const float* __restrict__ psp,
                float* __restrict__ pooled)
{
    extern __shared__ __align__(16) char sm_[];
    __half* Eh = (__half*)sm_;
    char* regU = sm_ + 256 * 264 * 2;
    __half* q2T = (__half*)regU;
    float* scoresF = (float*)regU;
    float* poolSm = (float*)regU;
    __half* Wt = (__half*)(regU + 34848);
    __shared__ float colts[32];

    int bt = blockIdx.x;
    int b = bt / TT, t = bt % TT;
    size_t qframe = ((size_t)b * CC * TT + t) * KK;
    size_t eframe = ((size_t)b * CC * TT + t) * FF;
    int tid = threadIdx.x;
    int lane = tid & 31, warp = tid >> 5;
    int group = lane >> 2, tid4 = lane & 3;

    // ---- load emb frame -> Eh fp16 (direct copy)
    #pragma unroll 8
    for (int i = 0; i < 32; i++) {
        int e = i * 256 + tid;
        int c = e >> 5, f8 = e & 31;
        *(uint4*)&Eh[c * 264 + f8 * 8] =
            *(const uint4*)(embh + eframe + (size_t)c * TT * FF + f8 * 8);
    }
    // ---- zero q2T rows 32..47, then u row (32)
    for (int e = tid; e < 16 * 264; e += 256)
        q2T[32 * 264 + e] = __float2half(0.f);
    q2T[32 * 264 + tid] = __float2half(g_u[tid]);
    // ---- load q2 frame [c][k] -> q2T[k][c] fp16
    #pragma unroll
    for (int i = 0; i < 8; i++) {
        int e = i * 256 + tid;
        int c = e >> 3, j = e & 7;
        float4 v = *(const float4*)(Q2 + qframe + (size_t)c * TT * KK + j * 4);
        q2T[(4*j + 0) * 264 + c] = __float2half(v.x);
        q2T[(4*j + 1) * 264 + c] = __float2half(v.y);
        q2T[(4*j + 2) * 264 + c] = __float2half(v.z);
        q2T[(4*j + 3) * 264 + c] = __float2half(v.w);
    }
    if (tid < 32) colts[tid] = g_colt[bt * KK + tid];
    __syncthreads();

    // ---- pass 1: scores[k(48), f] MMA; warp owns 32 f-columns
    float acc1[3][4][4];
    #pragma unroll
    for (int mt = 0; mt < 3; mt++)
        #pragma unroll
        for (int nt = 0; nt < 4; nt++)
            #pragma unroll
            for (int r = 0; r < 4; r++) acc1[mt][nt][r] = 0.f;

    #pragma unroll 1
    for (int ks = 0; ks < 256; ks += 16) {
        unsigned a[3][4];
        #pragma unroll
        for (int mt = 0; mt < 3; mt++)
            ldmx4(a[mt], sptr(&q2T[(mt * 16 + (lane & 15)) * 264 + ks + (lane >> 4) * 8]));
        #pragma unroll
        for (int nt = 0; nt < 4; nt++) {
            unsigned b0, b1;
            ldmx2t(b0, b1, sptr(&Eh[(ks + (lane & 15)) * 264 + warp * 32 + nt * 8]));
            mma_h(acc1[0][nt], a[0], b0, b1);
            mma_h(acc1[1][nt], a[1], b0, b1);
            mma_h(acc1[2][nt], a[2], b0, b1);
        }
    }
    __syncthreads();

    #pragma unroll
    for (int mt = 0; mt < 2; mt++)
        #pragma unroll
        for (int nt = 0; nt < 4; nt++) {
            int row = mt * 16 + group;
            int col = warp * 32 + nt * 8 + tid4 * 2;
            *(float2*)&scoresF[row * 264 + col]       = make_float2(acc1[mt][nt][0], acc1[mt][nt][1]);
            *(float2*)&scoresF[(row + 8) * 264 + col] = make_float2(acc1[mt][nt][2], acc1[mt][nt][3]);
        }
    if (group == 0) {
        #pragma unroll
        for (int nt = 0; nt < 4; nt++) {
            int col = warp * 32 + nt * 8 + tid4 * 2;
            *(float2*)&scoresF[32 * 264 + col] = make_float2(acc1[2][nt][0], acc1[2][nt][1]);
        }
    }
    __syncthreads();

    // ---- softmax per k; weights -> Wt[f][k] fp16
    float ss = *ssp, ps = *psp;
    #pragma unroll
    for (int rr = 0; rr < 4; rr++) {
        int k = warp * 4 + rr;
        float cv = colts[k];
        float v[8];
        float m = -1e30f;
        #pragma unroll
        for (int i = 0; i < 8; i++) {
            int f = lane + 32 * i;
            float raw = scoresF[k * 264 + f];
            float uu  = scoresF[32 * 264 + f];
            v[i] = ss * (raw + uu + cv) + rb[k * FF + f] * ps;
            m = fmaxf(m, v[i]);
        }
        #pragma unroll
        for (int o = 16; o; o >>= 1) m = fmaxf(m, __shfl_xor_sync(0xffffffffu, m, o));
        float s = 0.f;
        #pragma unroll
        for (int i = 0; i < 8; i++) { v[i] = __expf(v[i] - m); s += v[i]; }
        #pragma unroll
        for (int o = 16; o; o >>= 1) s += __shfl_xor_sync(0xffffffffu, s, o);
        float inv = 1.f / s;
        #pragma unroll
        for (int i = 0; i < 8; i++) {
            int f = lane + 32 * i;
            Wt[f * 40 + k] = __float2half(v[i] * inv);
        }
    }
    __syncthreads();

    // ---- pass 2: pooled[c, k] = sum_f Eh[c,f] * Wt[f,k]
    float acc2[2][4][4];
    #pragma unroll
    for (int mt = 0; mt < 2; mt++)
        #pragma unroll
        for (int nt = 0; nt < 4; nt++)
            #pragma unroll
            for (int r = 0; r < 4; r++) acc2[mt][nt][r] = 0.f;

    #pragma unroll 1
    for (int fs = 0; fs < 256; fs += 16) {
        unsigned a[2][4];
        #pragma unroll
        for (int mt = 0; mt < 2; mt++)
            ldmx4(a[mt], sptr(&Eh[(warp * 32 + mt * 16 + (lane & 15)) * 264 + fs + (lane >> 4) * 8]));
        #pragma unroll
        for (int nt = 0; nt < 4; nt++) {
            unsigned b0, b1;
            ldmx2t(b0, b1, sptr(&Wt[(fs + (lane & 15)) * 40 + nt * 8]));
            mma_h(acc2[0][nt], a[0], b0, b1);
            mma_h(acc2[1][nt], a[1], b0, b1);
        }
    }
    __syncthreads();

    #pragma unroll
    for (int mt = 0; mt < 2; mt++)
        #pragma unroll
        for (int nt = 0; nt < 4; nt++) {
            int row = warp * 32 + mt * 16 + group;
            int col = nt * 8 + tid4 * 2;
            *(float2*)&poolSm[row * 34 + col]       = make_float2(acc2[mt][nt][0], acc2[mt][nt][1]);
            *(float2*)&poolSm[(row + 8) * 34 + col] = make_float2(acc2[mt][nt][2], acc2[mt][nt][3]);
        }
    __syncthreads();
    #pragma unroll
    for (int i = 0; i < 32; i++) {
        int e = i * 256 + tid;
        int c = e >> 5, k = e & 31;
        pooled[qframe + (size_t)c * TT * KK + k] = poolSm[c * 34 + k];
    }
}

// ---------------- host launcher --------------------------------------------------
extern "C" void kernel_launch(void* const* d_in, const int* in_sizes, int n_in,
                              void* d_out, int out_size) {
    const float* x          = (const float*)d_in[0];
    const float* pre_norm_w = (const float*)d_in[1];
    const float* pre_pw_w   = (const float*)d_in[2];
    const float* pre_pw_b   = (const float*)d_in[3];
    const float* pre_dw_w   = (const float*)d_in[4];
    const float* pre_dw_b   = (const float*)d_in[5];
    const float* q_w        = (const float*)d_in[6];
    const float* q_b        = (const float*)d_in[7];
    const float* k_w        = (const float*)d_in[8];
    const float* k_b        = (const float*)d_in[9];
    const float* v_w        = (const float*)d_in[10];
    const float* v_b        = (const float*)d_in[11];
    const float* out_w      = (const float*)d_in[12];
    const float* out_b      = (const float*)d_in[13];
    const float* ffn_norm_w = (const float*)d_in[14];
    const float* ffn_in_w   = (const float*)d_in[15];
    const float* ffn_in_b   = (const float*)d_in[16];
    const float* ffn_out_w  = (const float*)d_in[17];
    const float* ffn_out_b  = (const float*)d_in[18];
    const float* score_scale= (const float*)d_in[19];
    const float* prior_scale= (const float*)d_in[20];
    const float* query_basis= (const float*)d_in[21];
    const float* routing_bias=(const float*)d_in[22];

    float* out        = (float*)d_out;
    float* out_hidden = out;
    float* out_emb    = out + (size_t)BB * CC * TT * KK;

    float *emb0, *qseed, *q2, *pooled, *hidden, *hffn;
    float *P, *OV, *Wp, *Wf, *bias2;
    __half* embh;
    cudaGetSymbolAddress((void**)&emb0,   g_emb0);
    cudaGetSymbolAddress((void**)&embh,   g_embh);
    cudaGetSymbolAddress((void**)&qseed,  g_qseed);
    cudaGetSymbolAddress((void**)&q2,     g_q2);
    cudaGetSymbolAddress((void**)&pooled, g_pooled);
    cudaGetSymbolAddress((void**)&hidden, g_hidden);
    cudaGetSymbolAddress((void**)&hffn,   g_hffn);
    cudaGetSymbolAddress((void**)&P,      g_P);
    cudaGetSymbolAddress((void**)&OV,     g_OV);
    cudaGetSymbolAddress((void**)&Wp,     g_Wp);
    cudaGetSymbolAddress((void**)&Wf,     g_Wf);
    cudaGetSymbolAddress((void**)&bias2,  g_bias2);

    cudaFuncSetAttribute(attn_mma_kernel,
                         cudaFuncAttributeMaxDynamicSharedMemorySize, ATTN_SMEM);
    cudaFuncSetAttribute(gemm_hs,
                         cudaFuncAttributeMaxDynamicSharedMemorySize, HS_SMEM);

    const int NBT = BB * TT;       // 800
    const int NF  = TT * FF;       // 102400
    const int NK  = TT * KK;       // 12800

    // precompute
    wscale_kernel<<<256, 256>>>(pre_pw_w, pre_norm_w, Wp, CC*CC);
    wscale_kernel<<<512, 256>>>(ffn_in_w, ffn_norm_w, Wf, 2*CC*CC);
    pre_gemms<<<dim3(8, 8, 2), dim3(16, 16)>>>(k_w, q_w, out_w, v_w, P, OV);
    vec_pre_kernel<<<256, 256>>>(q_w, q_b, k_w, k_b, out_w, out_b, v_b);

    // 1. pre pw with fused RMSNorm -> emb0 (fp16 storage)
    gemm_h<<<dim3(NF/128, 1, BB), 512>>>(Wp, pre_pw_b, x, nullptr,
                                         nullptr, (__half*)emb0, nullptr,
                                         1, CC, NF, (long)CC * NF);
    // 2. depthwise conv + SiLU -> emb (fp32 into d_out) + embh (fp16)
    dwconv8_kernel<<<(long)BB*CC*(TT/TB), FF>>>((const __half*)emb0, pre_dw_w, pre_dw_b,
                                                out_emb, embh);
    // 3. qseed = emb @ basis^T (fp16 input)
    qseed_mma_kernel<<<(BB*CC*TT)/128, 256>>>(embh, query_basis, qseed);
    // 4. colt
    colt_kernel<<<NBT, 256>>>(qseed);
    // 5. q2 = P @ qseed
    gemm_h<<<dim3(NK/128, 1, BB), 512>>>(P, nullptr, qseed, nullptr, q2, nullptr, nullptr,
                                         0, CC, NK, (long)CC * NK);
    // 6. fused attention (scores MMA + softmax + pooled MMA), fp16 emb input
    attn_mma_kernel<<<NBT, 256, ATTN_SMEM>>>(q2, embh, routing_bias,
                                             score_scale, prior_scale, pooled);
    // 7. hidden = OV @ pooled + bias2   [split-fp16, double-buffered]
    gemm_hs<<<dim3(NK/128, 1, BB), 512, HS_SMEM>>>(OV, bias2, pooled, nullptr, hidden, nullptr,
                                                   0, CC, NK, (long)CC * NK);
    // 8. ffn_in with fused RMSNorm       [split-fp16]
    gemm_hs<<<dim3(NK/128, 2, BB), 512, HS_SMEM>>>(Wf, ffn_in_b, hidden, nullptr, hffn, nullptr,
                                                   1, 2*CC, NK, (long)CC * NK);
    // 9. ffn_out with fused GLU load + residual -> d_out   [split-fp16]
    gemm_hs<<<dim3(NK/128, 1, BB), 512, HS_SMEM>>>(ffn_out_w, ffn_out_b, hffn,
                                                   hffn + (size_t)CC * NK,
                                                   out_hidden, hidden,
                                                   0, CC, NK, (long)2 * CC * NK);
}

// round 10
// speedup vs baseline: 1.1125x; 1.0544x over previous
#include <cuda_runtime.h>
#include <cuda_fp16.h>
#include <math.h>

#define BB 2
#define CC 256
#define TT 400
#define FF 256
#define KK 32
#define EPSV 1e-6f

typedef unsigned long long ull;

// ---------------- scratch ------------------------------------------------------
__device__ float  g_emb0   [(size_t)BB*CC*TT*FF];   // used as fp16 (half the space)
__device__ __half g_embh   [(size_t)BB*CC*TT*FF];   // fp16 copy of emb
__device__ float  g_qseed  [(size_t)BB*CC*TT*KK];
__device__ float  g_q2     [(size_t)BB*CC*TT*KK];
__device__ float  g_pooled [(size_t)BB*CC*TT*KK];
__device__ float  g_hidden [(size_t)BB*CC*TT*KK];
__device__ float  g_hffn   [(size_t)BB*2*CC*TT*KK];
__device__ float  g_P      [CC*CC];
__device__ float  g_OV     [CC*CC];
__device__ float  g_Wp     [CC*CC];
__device__ float  g_Wf     [2*CC*CC];
__device__ float  g_u      [CC];
__device__ float  g_w2     [CC];
__device__ float  g_bias2  [CC];
__device__ float  g_colt   [BB*TT*KK];
__device__ float  g_misc   [4];

// ---------------- helpers ------------------------------------------------------
__device__ __forceinline__ unsigned sptr(const void* p) {
    return (unsigned)__cvta_generic_to_shared(p);
}
__device__ __forceinline__ void ldmx4(unsigned* a, unsigned addr) {
    asm volatile("ldmatrix.sync.aligned.m8n8.x4.shared.b16 {%0,%1,%2,%3}, [%4];"
        : "=r"(a[0]), "=r"(a[1]), "=r"(a[2]), "=r"(a[3]) : "r"(addr));
}
__device__ __forceinline__ void ldmx2t(unsigned& b0, unsigned& b1, unsigned addr) {
    asm volatile("ldmatrix.sync.aligned.m8n8.x2.trans.shared.b16 {%0,%1}, [%2];"
        : "=r"(b0), "=r"(b1) : "r"(addr));
}
__device__ __forceinline__ void mma_h(float* c, const unsigned* a, unsigned b0, unsigned b1) {
    asm volatile("mma.sync.aligned.m16n8k16.row.col.f32.f16.f16.f32 "
        "{%0,%1,%2,%3}, {%4,%5,%6,%7}, {%8,%9}, {%0,%1,%2,%3};"
        : "+f"(c[0]), "+f"(c[1]), "+f"(c[2]), "+f"(c[3])
        : "r"(a[0]), "r"(a[1]), "r"(a[2]), "r"(a[3]), "r"(b0), "r"(b1));
}
__device__ __forceinline__ void split2(float x, float y, __half2& hi, __half2& lo) {
    hi = __floats2half2_rn(x, y);
    float2 hf = __half22float2(hi);
    lo = __floats2half2_rn(x - hf.x, y - hf.y);
}

// ---------------- unified fp16 tensor-core GEMM --------------------------------
__global__ void __launch_bounds__(512, 1)
gemm_h(const float* __restrict__ W, const float* __restrict__ bias,
       const float* __restrict__ X, const float* __restrict__ Xg,
       float* __restrict__ Y, __half* __restrict__ Yh,
       const float* __restrict__ addsrc,
       int invMode, int Cout, int Ntot, long xbstride)
{
    __shared__ __half Wh[2][256][24];
    __shared__ __half Xh[2][16][136];
    __shared__ float invs[128];
    __shared__ float4 part[16][32];

    int b  = blockIdx.z;
    int n0 = blockIdx.x * 128;
    int o0 = blockIdx.y * 256;
    const float* Xb  = X + (size_t)b * xbstride;
    const float* Xgb = Xg ? Xg + (size_t)b * xbstride : nullptr;
    float* Yb  = Y  ? Y  + (size_t)b * (size_t)Cout * Ntot : nullptr;
    __half* Yhb = Yh ? Yh + (size_t)b * (size_t)Cout * Ntot : nullptr;
    const float* Ab = addsrc ? addsrc + (size_t)b * (size_t)Cout * Ntot : nullptr;

    int tid = threadIdx.x;
    int lane = tid & 31, warp = tid >> 5;
    int wm = warp & 7, wn = warp >> 3;
    int group = lane >> 2, tid4 = lane & 3;

    int wm_ld = tid >> 2;
    int wkw   = tid & 3;
    int xk    = tid >> 5;
    int xn4   = (tid & 31) * 4;

    float acc[2][8][4];
    #pragma unroll
    for (int mt = 0; mt < 2; mt++)
        #pragma unroll
        for (int nt = 0; nt < 8; nt++)
            #pragma unroll
            for (int r = 0; r < 4; r++) acc[mt][nt][r] = 0.f;

    float4 ssq = make_float4(0.f, 0.f, 0.f, 0.f);
    float4 wreg0, wreg1, xreg;

    {
        const float* wp = W + (size_t)(o0 + wm_ld) * 256 + wkw * 4;
        wreg0 = *(const float4*)wp;
        wreg1 = *(const float4*)(wp + (size_t)128 * 256);
        xreg = *(const float4*)(Xb + (size_t)xk * Ntot + n0 + xn4);
        if (Xgb) {
            float4 g = *(const float4*)(Xgb + (size_t)xk * Ntot + n0 + xn4);
            xreg.x *= g.x / (1.f + __expf(-g.x));
            xreg.y *= g.y / (1.f + __expf(-g.y));
            xreg.z *= g.z / (1.f + __expf(-g.z));
            xreg.w *= g.w / (1.f + __expf(-g.w));
        }
        if (invMode) {
            ssq.x += xreg.x * xreg.x; ssq.y += xreg.y * xreg.y;
            ssq.z += xreg.z * xreg.z; ssq.w += xreg.w * xreg.w;
        }
    }

    #pragma unroll 1
    for (int kt = 0; kt < 16; kt++) {
        int buf = kt & 1;
        {
            __half2* wr0 = (__half2*)&Wh[buf][wm_ld][0];
            wr0[2 * wkw]     = __floats2half2_rn(wreg0.x, wreg0.y);
            wr0[2 * wkw + 1] = __floats2half2_rn(wreg0.z, wreg0.w);
            __half2* wr1 = (__half2*)&Wh[buf][128 + wm_ld][0];
            wr1[2 * wkw]     = __floats2half2_rn(wreg1.x, wreg1.y);
            wr1[2 * wkw + 1] = __floats2half2_rn(wreg1.z, wreg1.w);
            __half2* xr = (__half2*)&Xh[buf][xk][xn4];
            xr[0] = __floats2half2_rn(xreg.x, xreg.y);
            xr[1] = __floats2half2_rn(xreg.z, xreg.w);
        }
        __syncthreads();
        if (kt < 15) {
            int k0 = (kt + 1) * 16;
            const float* wp = W + (size_t)(o0 + wm_ld) * 256 + k0 + wkw * 4;
            wreg0 = *(const float4*)wp;
            wreg1 = *(const float4*)(wp + (size_t)128 * 256);
            xreg = *(const float4*)(Xb + (size_t)(k0 + xk) * Ntot + n0 + xn4);
            if (Xgb) {
                float4 g = *(const float4*)(Xgb + (size_t)(k0 + xk) * Ntot + n0 + xn4);
                xreg.x *= g.x / (1.f + __expf(-g.x));
                xreg.y *= g.y / (1.f + __expf(-g.y));
                xreg.z *= g.z / (1.f + __expf(-g.z));
                xreg.w *= g.w / (1.f + __expf(-g.w));
            }
            if (invMode) {
                ssq.x += xreg.x * xreg.x; ssq.y += xreg.y * xreg.y;
                ssq.z += xreg.z * xreg.z; ssq.w += xreg.w * xreg.w;
            }
        }
        unsigned a[2][4];
        #pragma unroll
        for (int mt = 0; mt < 2; mt++) {
            int row = wm * 32 + mt * 16 + (lane & 15);
            ldmx4(a[mt], sptr(&Wh[buf][row][(lane >> 4) * 8]));
        }
        #pragma unroll
        for (int nt = 0; nt < 8; nt++) {
            unsigned b0, b1;
            ldmx2t(b0, b1, sptr(&Xh[buf][lane & 15][wn * 64 + nt * 8]));
            mma_h(acc[0][nt], a[0], b0, b1);
            mma_h(acc[1][nt], a[1], b0, b1);
        }
    }

    if (invMode) {
        part[xk][tid & 31] = ssq;
        __syncthreads();
        if (tid < 32) {
            float4 s = part[0][tid];
            #pragma unroll
            for (int r = 1; r < 16; r++) {
                float4 p = part[r][tid];
                s.x += p.x; s.y += p.y; s.z += p.z; s.w += p.w;
            }
            invs[tid * 4 + 0] = rsqrtf(s.x * (1.f / CC) + EPSV);
            invs[tid * 4 + 1] = rsqrtf(s.y * (1.f / CC) + EPSV);
            invs[tid * 4 + 2] = rsqrtf(s.z * (1.f / CC) + EPSV);
            invs[tid * 4 + 3] = rsqrtf(s.w * (1.f / CC) + EPSV);
        }
        __syncthreads();
    }

    #pragma unroll
    for (int mt = 0; mt < 2; mt++) {
        int row = o0 + wm * 32 + mt * 16 + group;
        float bv0 = bias ? bias[row]     : 0.f;
        float bv8 = bias ? bias[row + 8] : 0.f;
        #pragma unroll
        for (int nt = 0; nt < 8; nt++) {
            int cl = wn * 64 + nt * 8 + tid4 * 2;
            int col = n0 + cl;
            size_t i0 = (size_t)row * Ntot + col;
            size_t i8 = (size_t)(row + 8) * Ntot + col;
            float a0 = acc[mt][nt][0], a1 = acc[mt][nt][1];
            float a2 = acc[mt][nt][2], a3 = acc[mt][nt][3];
            if (invMode) {
                float s0 = invs[cl], s1 = invs[cl + 1];
                a0 *= s0; a1 *= s1; a2 *= s0; a3 *= s1;
            }
            float2 v0 = make_float2(a0 + bv0, a1 + bv0);
            float2 v8 = make_float2(a2 + bv8, a3 + bv8);
            if (Ab) {
                float2 r0 = *(const float2*)(Ab + i0);
                float2 r8 = *(const float2*)(Ab + i8);
                v0.x += r0.x; v0.y += r0.y;
                v8.x += r8.x; v8.y += r8.y;
            }
            if (Yhb) {
                *(__half2*)(Yhb + i0) = __floats2half2_rn(v0.x, v0.y);
                *(__half2*)(Yhb + i8) = __floats2half2_rn(v8.x, v8.y);
            } else {
                *(float2*)(Yb + i0) = v0;
                *(float2*)(Yb + i8) = v8;
            }
        }
    }
}

// ---------------- 2-term split GEMM: W split (hi+lo), X plain fp16 --------------
// acc += Wh*x + Wl*x  (2 MMAs / tile) -> A-operand effectively exact.
// Dynamic smem (halves): Whh[2][256][24] | Whl[2][256][24] | Xh[2][16][136]
//                        | part[16][32] float4 | invs[128] float
#define HS_WHL   (2*256*24)
#define HS_XH    (2*(2*256*24))
#define HS_HALV  (HS_XH + 2*16*136)
#define HS_PART_B (HS_HALV * 2)
#define HS_INVS_B (HS_PART_B + 16*32*16)
#define HS_SMEM   (HS_INVS_B + 128*4)
__global__ void __launch_bounds__(512, 1)
gemm_hs(const float* __restrict__ W, const float* __restrict__ bias,
        const float* __restrict__ X, const float* __restrict__ Xg,
        float* __restrict__ Y, const float* __restrict__ addsrc,
        int invMode, int Cout, int Ntot, long xbstride)
{
    extern __shared__ __align__(16) char hsm[];
    __half* Whh = (__half*)(hsm);
    __half* Whl = (__half*)(hsm) + HS_WHL;
    __half* Xh  = (__half*)(hsm) + HS_XH;
    float4* part = (float4*)(hsm + HS_PART_B);
    float*  invs = (float*)(hsm + HS_INVS_B);

    int b  = blockIdx.z;
    int n0 = blockIdx.x * 128;
    int o0 = blockIdx.y * 256;
    const float* Xb  = X + (size_t)b * xbstride;
    const float* Xgb = Xg ? Xg + (size_t)b * xbstride : nullptr;
    float* Yb = Y + (size_t)b * (size_t)Cout * Ntot;
    const float* Ab = addsrc ? addsrc + (size_t)b * (size_t)Cout * Ntot : nullptr;

    int tid = threadIdx.x;
    int lane = tid & 31, warp = tid >> 5;
    int wm = warp & 7, wn = warp >> 3;
    int group = lane >> 2, tid4 = lane & 3;

    int wm_ld = tid >> 2;
    int wkw   = tid & 3;
    int xk    = tid >> 5;
    int xn4   = (tid & 31) * 4;

    float acc[2][8][4];
    #pragma unroll
    for (int mt = 0; mt < 2; mt++)
        #pragma unroll
        for (int nt = 0; nt < 8; nt++)
            #pragma unroll
            for (int r = 0; r < 4; r++) acc[mt][nt][r] = 0.f;

    float4 ssq = make_float4(0.f, 0.f, 0.f, 0.f);
    float4 wreg0, wreg1, xreg;

    {
        const float* wp = W + (size_t)(o0 + wm_ld) * 256 + wkw * 4;
        wreg0 = *(const float4*)wp;
        wreg1 = *(const float4*)(wp + (size_t)128 * 256);
        xreg = *(const float4*)(Xb + (size_t)xk * Ntot + n0 + xn4);
        if (Xgb) {
            float4 g = *(const float4*)(Xgb + (size_t)xk * Ntot + n0 + xn4);
            xreg.x *= g.x / (1.f + __expf(-g.x));
            xreg.y *= g.y / (1.f + __expf(-g.y));
            xreg.z *= g.z / (1.f + __expf(-g.z));
            xreg.w *= g.w / (1.f + __expf(-g.w));
        }
        if (invMode) {
            ssq.x += xreg.x * xreg.x; ssq.y += xreg.y * xreg.y;
            ssq.z += xreg.z * xreg.z; ssq.w += xreg.w * xreg.w;
        }
    }

    #pragma unroll 1
    for (int kt = 0; kt < 16; kt++) {
        int buf = kt & 1;
        {
            __half2 hi, lo;
            __half2* wh0 = (__half2*)&Whh[(buf * 256 + wm_ld) * 24];
            __half2* wl0 = (__half2*)&Whl[(buf * 256 + wm_ld) * 24];
            split2(wreg0.x, wreg0.y, hi, lo); wh0[2*wkw]   = hi; wl0[2*wkw]   = lo;
            split2(wreg0.z, wreg0.w, hi, lo); wh0[2*wkw+1] = hi; wl0[2*wkw+1] = lo;
            __half2* wh1 = (__half2*)&Whh[(buf * 256 + 128 + wm_ld) * 24];
            __half2* wl1 = (__half2*)&Whl[(buf * 256 + 128 + wm_ld) * 24];
            split2(wreg1.x, wreg1.y, hi, lo); wh1[2*wkw]   = hi; wl1[2*wkw]   = lo;
            split2(wreg1.z, wreg1.w, hi, lo); wh1[2*wkw+1] = hi; wl1[2*wkw+1] = lo;
            __half2* xr = (__half2*)&Xh[(buf * 16 + xk) * 136 + xn4];
            xr[0] = __floats2half2_rn(xreg.x, xreg.y);
            xr[1] = __floats2half2_rn(xreg.z, xreg.w);
        }
        __syncthreads();
        if (kt < 15) {
            int k0 = (kt + 1) * 16;
            const float* wp = W + (size_t)(o0 + wm_ld) * 256 + k0 + wkw * 4;
            wreg0 = *(const float4*)wp;
            wreg1 = *(const float4*)(wp + (size_t)128 * 256);
            xreg = *(const float4*)(Xb + (size_t)(k0 + xk) * Ntot + n0 + xn4);
            if (Xgb) {
                float4 g = *(const float4*)(Xgb + (size_t)(k0 + xk) * Ntot + n0 + xn4);
                xreg.x *= g.x / (1.f + __expf(-g.x));
                xreg.y *= g.y / (1.f + __expf(-g.y));
                xreg.z *= g.z / (1.f + __expf(-g.z));
                xreg.w *= g.w / (1.f + __expf(-g.w));
            }
            if (invMode) {
                ssq.x += xreg.x * xreg.x; ssq.y += xreg.y * xreg.y;
                ssq.z += xreg.z * xreg.z; ssq.w += xreg.w * xreg.w;
            }
        }
        unsigned ah[2][4], al[2][4];
        #pragma unroll
        for (int mt = 0; mt < 2; mt++) {
            int row = buf * 256 + wm * 32 + mt * 16 + (lane & 15);
            ldmx4(ah[mt], sptr(&Whh[row * 24 + (lane >> 4) * 8]));
            ldmx4(al[mt], sptr(&Whl[row * 24 + (lane >> 4) * 8]));
        }
        #pragma unroll
        for (int nt = 0; nt < 8; nt++) {
            unsigned b0, b1;
            int xrow = buf * 16 + (lane & 15);
            ldmx2t(b0, b1, sptr(&Xh[xrow * 136 + wn * 64 + nt * 8]));
            mma_h(acc[0][nt], ah[0], b0, b1);
            mma_h(acc[0][nt], al[0], b0, b1);
            mma_h(acc[1][nt], ah[1], b0, b1);
            mma_h(acc[1][nt], al[1], b0, b1);
        }
    }

    if (invMode) {
        part[xk * 32 + (tid & 31)] = ssq;
        __syncthreads();
        if (tid < 32) {
            float4 s = part[tid];
            #pragma unroll
            for (int r = 1; r < 16; r++) {
                float4 p = part[r * 32 + tid];
                s.x += p.x; s.y += p.y; s.z += p.z; s.w += p.w;
            }
            invs[tid * 4 + 0] = rsqrtf(s.x * (1.f / CC) + EPSV);
            invs[tid * 4 + 1] = rsqrtf(s.y * (1.f / CC) + EPSV);
            invs[tid * 4 + 2] = rsqrtf(s.z * (1.f / CC) + EPSV);
            invs[tid * 4 + 3] = rsqrtf(s.w * (1.f / CC) + EPSV);
        }
        __syncthreads();
    }

    #pragma unroll
    for (int mt = 0; mt < 2; mt++) {
        int row = o0 + wm * 32 + mt * 16 + group;
        float bv0 = bias ? bias[row]     : 0.f;
        float bv8 = bias ? bias[row + 8] : 0.f;
        #pragma unroll
        for (int nt = 0; nt < 8; nt++) {
            int cl = wn * 64 + nt * 8 + tid4 * 2;
            int col = n0 + cl;
            size_t i0 = (size_t)row * Ntot + col;
            size_t i8 = (size_t)(row + 8) * Ntot + col;
            float a0 = acc[mt][nt][0], a1 = acc[mt][nt][1];
            float a2 = acc[mt][nt][2], a3 = acc[mt][nt][3];
            if (invMode) {
                float s0 = invs[cl], s1 = invs[cl + 1];
                a0 *= s0; a1 *= s1; a2 *= s0; a3 *= s1;
            }
            float2 v0 = make_float2(a0 + bv0, a1 + bv0);
            float2 v8 = make_float2(a2 + bv8, a3 + bv8);
            if (Ab) {
                float2 r0 = *(const float2*)(Ab + i0);
                float2 r8 = *(const float2*)(Ab + i8);
                v0.x += r0.x; v0.y += r0.y;
                v8.x += r8.x; v8.y += r8.y;
            }
            *(float2*)(Yb + i0) = v0;
            *(float2*)(Yb + i8) = v8;
        }
    }
}

// ---------------- W row-scale precompute ----------------------------------------
__global__ void wscale_kernel(const float* __restrict__ W, const float* __restrict__ rs,
                              float* __restrict__ Wo, int n) {
    int i = blockIdx.x * 256 + threadIdx.x;
    if (i < n) Wo[i] = W[i] * rs[i & 255];
}

// ---------------- merged precompute GEMMs: P (tn) and OV (nn) -------------------
__global__ void pre_gemms(const float* __restrict__ kw, const float* __restrict__ qw,
                          const float* __restrict__ ow, const float* __restrict__ vw,
                          float* __restrict__ P, float* __restrict__ OV) {
    __shared__ float As[32][33], Bs[32][33];
    int mode = blockIdx.z;
    int m0 = blockIdx.y * 32, n0 = blockIdx.x * 32;
    int tx = threadIdx.x, ty = threadIdx.y;
    int tid = ty * 16 + tx;
    const float* A = mode ? ow : kw;
    const float* B = mode ? vw : qw;
    float acc[2][2] = {{0.f,0.f},{0.f,0.f}};
    for (int r0 = 0; r0 < CC; r0 += 32) {
        #pragma unroll
        for (int i = 0; i < 4; i++) {
            int e = i * 256 + tid;
            int a = e >> 5, c = e & 31;
            Bs[a][c] = B[(size_t)(r0 + a) * CC + n0 + c];
            As[a][c] = mode ? A[(size_t)(m0 + a) * CC + r0 + c]
                            : A[(size_t)(r0 + a) * CC + m0 + c];
        }
        __syncthreads();
        if (mode) {
            #pragma unroll
            for (int r = 0; r < 32; r++) {
                float a0 = As[ty*2][r], a1 = As[ty*2+1][r];
                float b0 = Bs[r][tx*2], b1 = Bs[r][tx*2+1];
                acc[0][0] += a0*b0; acc[0][1] += a0*b1;
                acc[1][0] += a1*b0; acc[1][1] += a1*b1;
            }
        } else {
            #pragma unroll
            for (int r = 0; r < 32; r++) {
                float a0 = As[r][ty*2], a1 = As[r][ty*2+1];
                float b0 = Bs[r][tx*2], b1 = Bs[r][tx*2+1];
                acc[0][0] += a0*b0; acc[0][1] += a0*b1;
                acc[1][0] += a1*b0; acc[1][1] += a1*b1;
            }
        }
        __syncthreads();
    }
    float* C = mode ? OV : P;
    #pragma unroll
    for (int i = 0; i < 2; i++)
        #pragma unroll
        for (int j = 0; j < 2; j++)
            C[(size_t)(m0 + ty*2 + i) * CC + n0 + tx*2 + j] = acc[i][j];
}

// ---------------- parallel vector precompute -------------------------------------
__global__ void vec_pre_kernel(const float* __restrict__ qw, const float* __restrict__ qb,
                               const float* __restrict__ kw, const float* __restrict__ kb,
                               const float* __restrict__ ow, const float* __restrict__ ob,
                               const float* __restrict__ vb) {
    __shared__ float red[4][8];
    int j = blockIdx.x;
    int o = threadIdx.x;
    float su = qb[o] * kw[(size_t)o * CC + j];
    float sw = qw[(size_t)o * CC + j] * kb[o];
    float sb = ow[(size_t)j * CC + o] * vb[o];
    float s0 = (j == 0) ? qb[o] * kb[o] : 0.f;
    #pragma unroll
    for (int d = 16; d; d >>= 1) {
        su += __shfl_xor_sync(0xffffffffu, su, d);
        sw += __shfl_xor_sync(0xffffffffu, sw, d);
        sb += __shfl_xor_sync(0xffffffffu, sb, d);
        s0 += __shfl_xor_sync(0xffffffffu, s0, d);
    }
    if ((o & 31) == 0) {
        int w = o >> 5;
        red[0][w] = su; red[1][w] = sw; red[2][w] = sb; red[3][w] = s0;
    }
    __syncthreads();
    if (o == 0) {
        float a = 0.f, b2 = 0.f, c = 0.f, d2 = 0.f;
        #pragma unroll
        for (int i = 0; i < 8; i++) {
            a += red[0][i]; b2 += red[1][i]; c += red[2][i]; d2 += red[3][i];
        }
        g_u[j] = a;
        g_w2[j] = b2;
        g_bias2[j] = c + ob[j];
        if (j == 0) g_misc[0] = d2;
    }
}

// ---------------- depthwise 3x3 causal conv + SiLU (fp16 in, fp32+fp16 out) -----
#define TB 8
__global__ void dwconv8_kernel(const __half* __restrict__ src,
                               const float* __restrict__ dww, const float* __restrict__ dwb,
                               float* __restrict__ emb, __half* __restrict__ embh) {
    int nblk = TT / TB;
    long idx = blockIdx.x;
    int tb = (int)(idx % nblk);
    long bc = idx / nblk;
    int c = (int)(bc % CC);
    int t0 = tb * TB;
    int f = threadIdx.x;
    __shared__ float rows[TB + 2][FF + 2];
    size_t chbase = (size_t)bc * TT * FF;
    #pragma unroll
    for (int r = 0; r < TB + 2; r++) {
        int tt = t0 - 2 + r;
        rows[r][f + 1] = (tt >= 0) ? __half2float(src[chbase + (size_t)tt * FF + f]) : 0.f;
        if (f == 0) { rows[r][0] = 0.f; rows[r][FF + 1] = 0.f; }
    }
    __syncthreads();
    float w[9];
    #pragma unroll
    for (int i = 0; i < 9; i++) w[i] = dww[c * 9 + i];
    float bv = dwb[c];
    #pragma unroll
    for (int r = 0; r < TB; r++) {
        float s = bv;
        #pragma unroll
        for (int dt = 0; dt < 3; dt++)
            #pragma unroll
            for (int df = 0; df < 3; df++)
                s += w[dt * 3 + df] * rows[r + dt][f + df];
        s = s / (1.f + __expf(-s));
        emb [chbase + (size_t)(t0 + r) * FF + f] = s;
        embh[chbase + (size_t)(t0 + r) * FF + f] = __float2half(s);
    }
}

// ---------------- qseed: batched skinny GEMM on tensor cores (fp16 input) -------
__global__ void __launch_bounds__(256, 2)
qseed_mma_kernel(const __half* __restrict__ embh, const float* __restrict__ basis,
                 float* __restrict__ Y)
{
    __shared__ __half Ah[2][128][40];
    __shared__ __half Bh[256 * 40];
    long row0 = (long)blockIdx.x * 128;
    int tid = threadIdx.x;
    int lane = tid & 31, warp = tid >> 5;
    int group = lane >> 2, tid4 = lane & 3;

    #pragma unroll
    for (int i = 0; i < 8; i++) {
        int e = i * 256 + tid;
        int k = e >> 6, f4 = e & 63;
        float4 v = *(const float4*)(basis + (size_t)k * 256 + f4 * 4);
        Bh[(f4 * 4 + 0) * 40 + k] = __float2half(v.x);
        Bh[(f4 * 4 + 1) * 40 + k] = __float2half(v.y);
        Bh[(f4 * 4 + 2) * 40 + k] = __float2half(v.z);
        Bh[(f4 * 4 + 3) * 40 + k] = __float2half(v.w);
    }

    float acc[4][4];
    #pragma unroll
    for (int nt = 0; nt < 4; nt++)
        #pragma unroll
        for (int r = 0; r < 4; r++) acc[nt][r] = 0.f;

    uint4 areg[2];
    int am = tid >> 1;
    int aj = (tid & 1) * 16;
    areg[0] = *(const uint4*)(embh + (row0 + am) * 256 + aj);
    areg[1] = *(const uint4*)(embh + (row0 + am) * 256 + aj + 8);

    #pragma unroll 1
    for (int kt = 0; kt < 8; kt++) {
        int buf = kt & 1;
        *(uint4*)&Ah[buf][am][aj]     = areg[0];
        *(uint4*)&Ah[buf][am][aj + 8] = areg[1];
        __syncthreads();
        if (kt < 7) {
            int ksn = (kt + 1) * 32;
            areg[0] = *(const uint4*)(embh + (row0 + am) * 256 + ksn + aj);
            areg[1] = *(const uint4*)(embh + (row0 + am) * 256 + ksn + aj + 8);
        }
        #pragma unroll
        for (int kk = 0; kk < 2; kk++) {
            unsigned a[4];
            ldmx4(a, sptr(&Ah[buf][warp * 16 + (lane & 15)][kk * 16 + (lane >> 4) * 8]));
            #pragma unroll
            for (int nt = 0; nt < 4; nt++) {
                unsigned b0, b1;
                ldmx2t(b0, b1, sptr(&Bh[(kt * 32 + kk * 16 + (lane & 15)) * 40 + nt * 8]));
                mma_h(acc[nt], a, b0, b1);
            }
        }
    }

    long r1 = row0 + warp * 16 + group;
    #pragma unroll
    for (int nt = 0; nt < 4; nt++) {
        int col = nt * 8 + tid4 * 2;
        *(float2*)(Y + r1 * 32 + col)       = make_float2(acc[nt][0], acc[nt][1]);
        *(float2*)(Y + (r1 + 8) * 32 + col) = make_float2(acc[nt][2], acc[nt][3]);
    }
}

// ---------------- colt ------------------------------------------------------------
__global__ void colt_kernel(const float* __restrict__ qs) {
    __shared__ float part[8][32];
    int bt = blockIdx.x;
    int b = bt / TT, t = bt % TT;
    size_t base = ((size_t)b * CC * TT + t) * KK;
    int k = threadIdx.x & 31, cg = threadIdx.x >> 5;
    float s = 0.f;
    for (int c = cg; c < CC; c += 8)
        s += g_w2[c] * qs[base + (size_t)c * TT * KK + k];
    part[cg][k] = s;
    __syncthreads();
    if (threadIdx.x < 32) {
        float tot = g_misc[0];
        #pragma unroll
        for (int i = 0; i < 8; i++) tot += part[i][k];
        g_colt[bt * KK + k] = tot;
    }
}

// ---------------- fused attention (512 threads): scores + softmax + pooled ------
#define ATTN_SMEM (256*264*2 + 34848 + 256*40*2)
__global__ void __launch_bounds__(512, 1)
attn_mma_kernel(const float* __restrict__ Q2, const __half* __restrict__ embh,
                const float* __restrict__ rb,
                const float* __restrict__ ssp, const float* __restrict__ psp,
                float* __restrict__ pooled)
{
    extern __shared__ __align__(16) char sm_[];
    __half* Eh = (__half*)sm_;
    char* regU = sm_ + 256 * 264 * 2;
    __half* q2T = (__half*)regU;
    float* scoresF = (float*)regU;
    float* poolSm = (float*)regU;
    __half* Wt = (__half*)(regU + 34848);
    __shared__ float colts[32];

    int bt = blockIdx.x;
    int b = bt / TT, t = bt % TT;
    size_t qframe = ((size_t)b * CC * TT + t) * KK;
    size_t eframe = ((size_t)b * CC * TT + t) * FF;
    int tid = threadIdx.x;
    int lane = tid & 31, warp = tid >> 5;      // 16 warps
    int group = lane >> 2, tid4 = lane & 3;

    // ---- load emb frame -> Eh fp16
    #pragma unroll 8
    for (int i = 0; i < 16; i++) {
        int e = i * 512 + tid;
        int c = e >> 5, f8 = e & 31;
        *(uint4*)&Eh[c * 264 + f8 * 8] =
            *(const uint4*)(embh + eframe + (size_t)c * TT * FF + f8 * 8);
    }
    // ---- zero q2T rows 32..47, then u row (32)
    for (int e = tid; e < 16 * 264; e += 512)
        q2T[32 * 264 + e] = __float2half(0.f);
    if (tid < 256) q2T[32 * 264 + tid] = __float2half(g_u[tid]);
    // ---- load q2 frame [c][k] -> q2T[k][c] fp16
    #pragma unroll
    for (int i = 0; i < 4; i++) {
        int e = i * 512 + tid;
        int c = e >> 3, j = e & 7;
        float4 v = *(const float4*)(Q2 + qframe + (size_t)c * TT * KK + j * 4);
        q2T[(4*j + 0) * 264 + c] = __float2half(v.x);
        q2T[(4*j + 1) * 264 + c] = __float2half(v.y);
        q2T[(4*j + 2) * 264 + c] = __float2half(v.z);
        q2T[(4*j + 3) * 264 + c] = __float2half(v.w);
    }
    if (tid < 32) colts[tid] = g_colt[bt * KK + tid];
    __syncthreads();

    // ---- pass 1: scores[k(48), f]; each warp owns 16 f-columns
    float acc1[3][2][4];
    #pragma unroll
    for (int mt = 0; mt < 3; mt++)
        #pragma unroll
        for (int nt = 0; nt < 2; nt++)
            #pragma unroll
            for (int r = 0; r < 4; r++) acc1[mt][nt][r] = 0.f;

    #pragma unroll 1
    for (int ks = 0; ks < 256; ks += 16) {
        unsigned a[3][4];
        #pragma unroll
        for (int mt = 0; mt < 3; mt++)
            ldmx4(a[mt], sptr(&q2T[(mt * 16 + (lane & 15)) * 264 + ks + (lane >> 4) * 8]));
        #pragma unroll
        for (int nt = 0; nt < 2; nt++) {
            unsigned b0, b1;
            ldmx2t(b0, b1, sptr(&Eh[(ks + (lane & 15)) * 264 + warp * 16 + nt * 8]));
            mma_h(acc1[0][nt], a[0], b0, b1);
            mma_h(acc1[1][nt], a[1], b0, b1);
            mma_h(acc1[2][nt], a[2], b0, b1);
        }
    }
    __syncthreads();   // q2T reads complete; region becomes scoresF

    #pragma unroll
    for (int mt = 0; mt < 2; mt++)
        #pragma unroll
        for (int nt = 0; nt < 2; nt++) {
            int row = mt * 16 + group;
            int col = warp * 16 + nt * 8 + tid4 * 2;
            *(float2*)&scoresF[row * 264 + col]       = make_float2(acc1[mt][nt][0], acc1[mt][nt][1]);
            *(float2*)&scoresF[(row + 8) * 264 + col] = make_float2(acc1[mt][nt][2], acc1[mt][nt][3]);
        }
    if (group == 0) {
        #pragma unroll
        for (int nt = 0; nt < 2; nt++) {
            int col = warp * 16 + nt * 8 + tid4 * 2;
            *(float2*)&scoresF[32 * 264 + col] = make_float2(acc1[2][nt][0], acc1[2][nt][1]);
        }
    }
    __syncthreads();

    // ---- softmax per k (2 rows per warp); weights -> Wt[f][k] fp16
    float ss = *ssp, ps = *psp;
    #pragma unroll
    for (int rr = 0; rr < 2; rr++) {
        int k = warp * 2 + rr;
        float cv = colts[k];
        float v[8];
        float m = -1e30f;
        #pragma unroll
        for (int i = 0; i < 8; i++) {
            int f = lane + 32 * i;
            float raw = scoresF[k * 264 + f];
            float uu  = scoresF[32 * 264 + f];
            v[i] = ss * (raw + uu + cv) + rb[k * FF + f] * ps;
            m = fmaxf(m, v[i]);
        }
        #pragma unroll
        for (int o = 16; o; o >>= 1) m = fmaxf(m, __shfl_xor_sync(0xffffffffu, m, o));
        float s = 0.f;
        #pragma unroll
        for (int i = 0; i < 8; i++) { v[i] = __expf(v[i] - m); s += v[i]; }
        #pragma unroll
        for (int o = 16; o; o >>= 1) s += __shfl_xor_sync(0xffffffffu, s, o);
        float inv = 1.f / s;
        #pragma unroll
        for (int i = 0; i < 8; i++) {
            int f = lane + 32 * i;
            Wt[f * 40 + k] = __float2half(v[i] * inv);
        }
    }
    __syncthreads();

    // ---- pass 2: pooled[c, k]; each warp owns 16 c-rows
    float acc2[4][4];
    #pragma unroll
    for (int nt = 0; nt < 4; nt++)
        #pragma unroll
        for (int r = 0; r < 4; r++) acc2[nt][r] = 0.f;

    #pragma unroll 1
    for (int fs = 0; fs < 256; fs += 16) {
        unsigned a[4];
        ldmx4(a, sptr(&Eh[(warp * 16 + (lane & 15)) * 264 + fs + (lane >> 4) * 8]));
        #pragma unroll
        for (int nt = 0; nt < 4; nt++) {
            unsigned b0, b1;
            ldmx2t(b0, b1, sptr(&Wt[(fs + (lane & 15)) * 40 + nt * 8]));
            mma_h(acc2[nt], a, b0, b1);
        }
    }
    __syncthreads();   // scoresF readers done; region becomes poolSm

    #pragma unroll
    for (int nt = 0; nt < 4; nt++) {
        int row = warp * 16 + group;
        int col = nt * 8 + tid4 * 2;
        *(float2*)&poolSm[row * 34 + col]       = make_float2(acc2[nt][0], acc2[nt][1]);
        *(float2*)&poolSm[(row + 8) * 34 + col] = make_float2(acc2[nt][2], acc2[nt][3]);
    }
    __syncthreads();
    #pragma unroll
    for (int i = 0; i < 16; i++) {
        int e = i * 512 + tid;
        int c = e >> 5, k = e & 31;
        pooled[qframe + (size_t)c * TT * KK + k] = poolSm[c * 34 + k];
    }
}

// ---------------- host launcher --------------------------------------------------
extern "C" void kernel_launch(void* const* d_in, const int* in_sizes, int n_in,
                              void* d_out, int out_size) {
    const float* x          = (const float*)d_in[0];
    const float* pre_norm_w = (const float*)d_in[1];
    const float* pre_pw_w   = (const float*)d_in[2];
    const float* pre_pw_b   = (const float*)d_in[3];
    const float* pre_dw_w   = (const float*)d_in[4];
    const float* pre_dw_b   = (const float*)d_in[5];
    const float* q_w        = (const float*)d_in[6];
    const float* q_b        = (const float*)d_in[7];
    const float* k_w        = (const float*)d_in[8];
    const float* k_b        = (const float*)d_in[9];
    const float* v_w        = (const float*)d_in[10];
    const float* v_b        = (const float*)d_in[11];
    const float* out_w      = (const float*)d_in[12];
    const float* out_b      = (const float*)d_in[13];
    const float* ffn_norm_w = (const float*)d_in[14];
    const float* ffn_in_w   = (const float*)d_in[15];
    const float* ffn_in_b   = (const float*)d_in[16];
    const float* ffn_out_w  = (const float*)d_in[17];
    const float* ffn_out_b  = (const float*)d_in[18];
    const float* score_scale= (const float*)d_in[19];
    const float* prior_scale= (const float*)d_in[20];
    const float* query_basis= (const float*)d_in[21];
    const float* routing_bias=(const float*)d_in[22];

    float* out        = (float*)d_out;
    float* out_hidden = out;
    float* out_emb    = out + (size_t)BB * CC * TT * KK;

    float *emb0, *qseed, *q2, *pooled, *hidden, *hffn;
    float *P, *OV, *Wp, *Wf, *bias2;
    __half* embh;
    cudaGetSymbolAddress((void**)&emb0,   g_emb0);
    cudaGetSymbolAddress((void**)&embh,   g_embh);
    cudaGetSymbolAddress((void**)&qseed,  g_qseed);
    cudaGetSymbolAddress((void**)&q2,     g_q2);
    cudaGetSymbolAddress((void**)&pooled, g_pooled);
    cudaGetSymbolAddress((void**)&hidden, g_hidden);
    cudaGetSymbolAddress((void**)&hffn,   g_hffn);
    cudaGetSymbolAddress((void**)&P,      g_P);
    cudaGetSymbolAddress((void**)&OV,     g_OV);
    cudaGetSymbolAddress((void**)&Wp,     g_Wp);
    cudaGetSymbolAddress((void**)&Wf,     g_Wf);
    cudaGetSymbolAddress((void**)&bias2,  g_bias2);

    cudaFuncSetAttribute(attn_mma_kernel,
                         cudaFuncAttributeMaxDynamicSharedMemorySize, ATTN_SMEM);
    cudaFuncSetAttribute(gemm_hs,
                         cudaFuncAttributeMaxDynamicSharedMemorySize, HS_SMEM);

    const int NBT = BB * TT;       // 800
    const int NF  = TT * FF;       // 102400
    const int NK  = TT * KK;       // 12800

    // precompute
    wscale_kernel<<<256, 256>>>(pre_pw_w, pre_norm_w, Wp, CC*CC);
    wscale_kernel<<<512, 256>>>(ffn_in_w, ffn_norm_w, Wf, 2*CC*CC);
    pre_gemms<<<dim3(8, 8, 2), dim3(16, 16)>>>(k_w, q_w, out_w, v_w, P, OV);
    vec_pre_kernel<<<256, 256>>>(q_w, q_b, k_w, k_b, out_w, out_b, v_b);

    // 1. pre pw with fused RMSNorm -> emb0 (fp16 storage)
    gemm_h<<<dim3(NF/128, 1, BB), 512>>>(Wp, pre_pw_b, x, nullptr,
                                         nullptr, (__half*)emb0, nullptr,
                                         1, CC, NF, (long)CC * NF);
    // 2. depthwise conv + SiLU -> emb (fp32 into d_out) + embh (fp16)
    dwconv8_kernel<<<(long)BB*CC*(TT/TB), FF>>>((const __half*)emb0, pre_dw_w, pre_dw_b,
                                                out_emb, embh);
    // 3. qseed = emb @ basis^T (fp16 input)
    qseed_mma_kernel<<<(BB*CC*TT)/128, 256>>>(embh, query_basis, qseed);
    // 4. colt
    colt_kernel<<<NBT, 256>>>(qseed);
    // 5. q2 = P @ qseed
    gemm_h<<<dim3(NK/128, 1, BB), 512>>>(P, nullptr, qseed, nullptr, q2, nullptr, nullptr,
                                         0, CC, NK, (long)CC * NK);
    // 6. fused attention (512 threads)
    attn_mma_kernel<<<NBT, 512, ATTN_SMEM>>>(q2, embh, routing_bias,
                                             score_scale, prior_scale, pooled);
    // 7. hidden = OV @ pooled + bias2   [2-term split]
    gemm_hs<<<dim3(NK/128, 1, BB), 512, HS_SMEM>>>(OV, bias2, pooled, nullptr, hidden, nullptr,
                                                   0, CC, NK, (long)CC * NK);
    // 8. ffn_in with fused RMSNorm       [2-term split]
    gemm_hs<<<dim3(NK/128, 2, BB), 512, HS_SMEM>>>(Wf, ffn_in_b, hidden, nullptr, hffn, nullptr,
                                                   1, 2*CC, NK, (long)CC * NK);
    // 9. ffn_out with fused GLU load + residual -> d_out   [2-term split]
    gemm_hs<<<dim3(NK/128, 1, BB), 512, HS_SMEM>>>(ffn_out_w, ffn_out_b, hffn,
                                                   hffn + (size_t)CC * NK,
                                                   out_hidden, hidden,
                                                   0, CC, NK, (long)2 * CC * NK);
}

// round 12
// speedup vs baseline: 1.1303x; 1.0160x over previous
#include <cuda_runtime.h>
#include <cuda_fp16.h>
#include <math.h>

#define BB 2
#define CC 256
#define TT 400
#define FF 256
#define KK 32
#define EPSV 1e-6f

typedef unsigned long long ull;

// ---------------- scratch ------------------------------------------------------
__device__ float  g_emb0   [(size_t)BB*CC*TT*FF];   // used as fp16 (half the space)
__device__ __half g_embh   [(size_t)BB*CC*TT*FF];   // fp16 copy of emb
__device__ float  g_qseed  [(size_t)BB*CC*TT*KK];
__device__ float  g_q2     [(size_t)BB*CC*TT*KK];
__device__ float  g_pooled [(size_t)BB*CC*TT*KK];
__device__ float  g_hidden [(size_t)BB*CC*TT*KK];
__device__ float  g_hffn   [(size_t)BB*2*CC*TT*KK];
__device__ float  g_P      [CC*CC];
__device__ float  g_OV     [CC*CC];
__device__ float  g_Wp     [CC*CC];
__device__ float  g_Wf     [2*CC*CC];
__device__ float  g_u      [CC];
__device__ float  g_w2     [CC];
__device__ float  g_bias2  [CC];
__device__ float  g_colt   [BB*TT*KK];
__device__ float  g_misc   [4];

// ---------------- helpers ------------------------------------------------------
__device__ __forceinline__ unsigned sptr(const void* p) {
    return (unsigned)__cvta_generic_to_shared(p);
}
__device__ __forceinline__ void ldmx4(unsigned* a, unsigned addr) {
    asm volatile("ldmatrix.sync.aligned.m8n8.x4.shared.b16 {%0,%1,%2,%3}, [%4];"
        : "=r"(a[0]), "=r"(a[1]), "=r"(a[2]), "=r"(a[3]) : "r"(addr));
}
__device__ __forceinline__ void ldmx2t(unsigned& b0, unsigned& b1, unsigned addr) {
    asm volatile("ldmatrix.sync.aligned.m8n8.x2.trans.shared.b16 {%0,%1}, [%2];"
        : "=r"(b0), "=r"(b1) : "r"(addr));
}
__device__ __forceinline__ void mma_h(float* c, const unsigned* a, unsigned b0, unsigned b1) {
    asm volatile("mma.sync.aligned.m16n8k16.row.col.f32.f16.f16.f32 "
        "{%0,%1,%2,%3}, {%4,%5,%6,%7}, {%8,%9}, {%0,%1,%2,%3};"
        : "+f"(c[0]), "+f"(c[1]), "+f"(c[2]), "+f"(c[3])
        : "r"(a[0]), "r"(a[1]), "r"(a[2]), "r"(a[3]), "r"(b0), "r"(b1));
}
__device__ __forceinline__ void split2(float x, float y, __half2& hi, __half2& lo) {
    hi = __floats2half2_rn(x, y);
    float2 hf = __half22float2(hi);
    lo = __floats2half2_rn(x - hf.x, y - hf.y);
}

// ---------------- unified fp16 tensor-core GEMM --------------------------------
__global__ void __launch_bounds__(512, 1)
gemm_h(const float* __restrict__ W, const float* __restrict__ bias,
       const float* __restrict__ X, const float* __restrict__ Xg,
       float* __restrict__ Y, __half* __restrict__ Yh,
       const float* __restrict__ addsrc,
       int invMode, int Cout, int Ntot, long xbstride)
{
    __shared__ __half Wh[2][256][24];
    __shared__ __half Xh[2][16][136];
    __shared__ float invs[128];
    __shared__ float4 part[16][32];

    int b  = blockIdx.z;
    int n0 = blockIdx.x * 128;
    int o0 = blockIdx.y * 256;
    const float* Xb  = X + (size_t)b * xbstride;
    const float* Xgb = Xg ? Xg + (size_t)b * xbstride : nullptr;
    float* Yb  = Y  ? Y  + (size_t)b * (size_t)Cout * Ntot : nullptr;
    __half* Yhb = Yh ? Yh + (size_t)b * (size_t)Cout * Ntot : nullptr;
    const float* Ab = addsrc ? addsrc + (size_t)b * (size_t)Cout * Ntot : nullptr;

    int tid = threadIdx.x;
    int lane = tid & 31, warp = tid >> 5;
    int wm = warp & 7, wn = warp >> 3;
    int group = lane >> 2, tid4 = lane & 3;

    int wm_ld = tid >> 2;
    int wkw   = tid & 3;
    int xk    = tid >> 5;
    int xn4   = (tid & 31) * 4;

    float acc[2][8][4];
    #pragma unroll
    for (int mt = 0; mt < 2; mt++)
        #pragma unroll
        for (int nt = 0; nt < 8; nt++)
            #pragma unroll
            for (int r = 0; r < 4; r++) acc[mt][nt][r] = 0.f;

    float4 ssq = make_float4(0.f, 0.f, 0.f, 0.f);
    float4 wreg0, wreg1, xreg;

    {
        const float* wp = W + (size_t)(o0 + wm_ld) * 256 + wkw * 4;
        wreg0 = *(const float4*)wp;
        wreg1 = *(const float4*)(wp + (size_t)128 * 256);
        xreg = *(const float4*)(Xb + (size_t)xk * Ntot + n0 + xn4);
        if (Xgb) {
            float4 g = *(const float4*)(Xgb + (size_t)xk * Ntot + n0 + xn4);
            xreg.x *= g.x / (1.f + __expf(-g.x));
            xreg.y *= g.y / (1.f + __expf(-g.y));
            xreg.z *= g.z / (1.f + __expf(-g.z));
            xreg.w *= g.w / (1.f + __expf(-g.w));
        }
        if (invMode) {
            ssq.x += xreg.x * xreg.x; ssq.y += xreg.y * xreg.y;
            ssq.z += xreg.z * xreg.z; ssq.w += xreg.w * xreg.w;
        }
    }

    #pragma unroll 1
    for (int kt = 0; kt < 16; kt++) {
        int buf = kt & 1;
        {
            __half2* wr0 = (__half2*)&Wh[buf][wm_ld][0];
            wr0[2 * wkw]     = __floats2half2_rn(wreg0.x, wreg0.y);
            wr0[2 * wkw + 1] = __floats2half2_rn(wreg0.z, wreg0.w);
            __half2* wr1 = (__half2*)&Wh[buf][128 + wm_ld][0];
            wr1[2 * wkw]     = __floats2half2_rn(wreg1.x, wreg1.y);
            wr1[2 * wkw + 1] = __floats2half2_rn(wreg1.z, wreg1.w);
            __half2* xr = (__half2*)&Xh[buf][xk][xn4];
            xr[0] = __floats2half2_rn(xreg.x, xreg.y);
            xr[1] = __floats2half2_rn(xreg.z, xreg.w);
        }
        __syncthreads();
        if (kt < 15) {
            int k0 = (kt + 1) * 16;
            const float* wp = W + (size_t)(o0 + wm_ld) * 256 + k0 + wkw * 4;
            wreg0 = *(const float4*)wp;
            wreg1 = *(const float4*)(wp + (size_t)128 * 256);
            xreg = *(const float4*)(Xb + (size_t)(k0 + xk) * Ntot + n0 + xn4);
            if (Xgb) {
                float4 g = *(const float4*)(Xgb + (size_t)(k0 + xk) * Ntot + n0 + xn4);
                xreg.x *= g.x / (1.f + __expf(-g.x));
                xreg.y *= g.y / (1.f + __expf(-g.y));
                xreg.z *= g.z / (1.f + __expf(-g.z));
                xreg.w *= g.w / (1.f + __expf(-g.w));
            }
            if (invMode) {
                ssq.x += xreg.x * xreg.x; ssq.y += xreg.y * xreg.y;
                ssq.z += xreg.z * xreg.z; ssq.w += xreg.w * xreg.w;
            }
        }
        unsigned a[2][4];
        #pragma unroll
        for (int mt = 0; mt < 2; mt++) {
            int row = wm * 32 + mt * 16 + (lane & 15);
            ldmx4(a[mt], sptr(&Wh[buf][row][(lane >> 4) * 8]));
        }
        #pragma unroll
        for (int nt = 0; nt < 8; nt++) {
            unsigned b0, b1;
            ldmx2t(b0, b1, sptr(&Xh[buf][lane & 15][wn * 64 + nt * 8]));
            mma_h(acc[0][nt], a[0], b0, b1);
            mma_h(acc[1][nt], a[1], b0, b1);
        }
    }

    if (invMode) {
        part[xk][tid & 31] = ssq;
        __syncthreads();
        if (tid < 32) {
            float4 s = part[0][tid];
            #pragma unroll
            for (int r = 1; r < 16; r++) {
                float4 p = part[r][tid];
                s.x += p.x; s.y += p.y; s.z += p.z; s.w += p.w;
            }
            invs[tid * 4 + 0] = rsqrtf(s.x * (1.f / CC) + EPSV);
            invs[tid * 4 + 1] = rsqrtf(s.y * (1.f / CC) + EPSV);
            invs[tid * 4 + 2] = rsqrtf(s.z * (1.f / CC) + EPSV);
            invs[tid * 4 + 3] = rsqrtf(s.w * (1.f / CC) + EPSV);
        }
        __syncthreads();
    }

    #pragma unroll
    for (int mt = 0; mt < 2; mt++) {
        int row = o0 + wm * 32 + mt * 16 + group;
        float bv0 = bias ? bias[row]     : 0.f;
        float bv8 = bias ? bias[row + 8] : 0.f;
        #pragma unroll
        for (int nt = 0; nt < 8; nt++) {
            int cl = wn * 64 + nt * 8 + tid4 * 2;
            int col = n0 + cl;
            size_t i0 = (size_t)row * Ntot + col;
            size_t i8 = (size_t)(row + 8) * Ntot + col;
            float a0 = acc[mt][nt][0], a1 = acc[mt][nt][1];
            float a2 = acc[mt][nt][2], a3 = acc[mt][nt][3];
            if (invMode) {
                float s0 = invs[cl], s1 = invs[cl + 1];
                a0 *= s0; a1 *= s1; a2 *= s0; a3 *= s1;
            }
            float2 v0 = make_float2(a0 + bv0, a1 + bv0);
            float2 v8 = make_float2(a2 + bv8, a3 + bv8);
            if (Ab) {
                float2 r0 = *(const float2*)(Ab + i0);
                float2 r8 = *(const float2*)(Ab + i8);
                v0.x += r0.x; v0.y += r0.y;
                v8.x += r8.x; v8.y += r8.y;
            }
            if (Yhb) {
                *(__half2*)(Yhb + i0) = __floats2half2_rn(v0.x, v0.y);
                *(__half2*)(Yhb + i8) = __floats2half2_rn(v8.x, v8.y);
            } else {
                *(float2*)(Yb + i0) = v0;
                *(float2*)(Yb + i8) = v8;
            }
        }
    }
}

// ---------------- 2-term split GEMM: W split (hi+lo), X plain fp16 --------------
#define HS_WHL   (2*256*24)
#define HS_XH    (2*(2*256*24))
#define HS_HALV  (HS_XH + 2*16*136)
#define HS_PART_B (HS_HALV * 2)
#define HS_INVS_B (HS_PART_B + 16*32*16)
#define HS_SMEM   (HS_INVS_B + 128*4)
__global__ void __launch_bounds__(512, 1)
gemm_hs(const float* __restrict__ W, const float* __restrict__ bias,
        const float* __restrict__ X, const float* __restrict__ Xg,
        float* __restrict__ Y, const float* __restrict__ addsrc,
        int invMode, int Cout, int Ntot, long xbstride)
{
    extern __shared__ __align__(16) char hsm[];
    __half* Whh = (__half*)(hsm);
    __half* Whl = (__half*)(hsm) + HS_WHL;
    __half* Xh  = (__half*)(hsm) + HS_XH;
    float4* part = (float4*)(hsm + HS_PART_B);
    float*  invs = (float*)(hsm + HS_INVS_B);

    int b  = blockIdx.z;
    int n0 = blockIdx.x * 128;
    int o0 = blockIdx.y * 256;
    const float* Xb  = X + (size_t)b * xbstride;
    const float* Xgb = Xg ? Xg + (size_t)b * xbstride : nullptr;
    float* Yb = Y + (size_t)b * (size_t)Cout * Ntot;
    const float* Ab = addsrc ? addsrc + (size_t)b * (size_t)Cout * Ntot : nullptr;

    int tid = threadIdx.x;
    int lane = tid & 31, warp = tid >> 5;
    int wm = warp & 7, wn = warp >> 3;
    int group = lane >> 2, tid4 = lane & 3;

    int wm_ld = tid >> 2;
    int wkw   = tid & 3;
    int xk    = tid >> 5;
    int xn4   = (tid & 31) * 4;

    float acc[2][8][4];
    #pragma unroll
    for (int mt = 0; mt < 2; mt++)
        #pragma unroll
        for (int nt = 0; nt < 8; nt++)
            #pragma unroll
            for (int r = 0; r < 4; r++) acc[mt][nt][r] = 0.f;

    float4 ssq = make_float4(0.f, 0.f, 0.f, 0.f);
    float4 wreg0, wreg1, xreg;

    {
        const float* wp = W + (size_t)(o0 + wm_ld) * 256 + wkw * 4;
        wreg0 = *(const float4*)wp;
        wreg1 = *(const float4*)(wp + (size_t)128 * 256);
        xreg = *(const float4*)(Xb + (size_t)xk * Ntot + n0 + xn4);
        if (Xgb) {
            float4 g = *(const float4*)(Xgb + (size_t)xk * Ntot + n0 + xn4);
            xreg.x *= g.x / (1.f + __expf(-g.x));
            xreg.y *= g.y / (1.f + __expf(-g.y));
            xreg.z *= g.z / (1.f + __expf(-g.z));
            xreg.w *= g.w / (1.f + __expf(-g.w));
        }
        if (invMode) {
            ssq.x += xreg.x * xreg.x; ssq.y += xreg.y * xreg.y;
            ssq.z += xreg.z * xreg.z; ssq.w += xreg.w * xreg.w;
        }
    }

    #pragma unroll 1
    for (int kt = 0; kt < 16; kt++) {
        int buf = kt & 1;
        {
            __half2 hi, lo;
            __half2* wh0 = (__half2*)&Whh[(buf * 256 + wm_ld) * 24];
            __half2* wl0 = (__half2*)&Whl[(buf * 256 + wm_ld) * 24];
            split2(wreg0.x, wreg0.y, hi, lo); wh0[2*wkw]   = hi; wl0[2*wkw]   = lo;
            split2(wreg0.z, wreg0.w, hi, lo); wh0[2*wkw+1] = hi; wl0[2*wkw+1] = lo;
            __half2* wh1 = (__half2*)&Whh[(buf * 256 + 128 + wm_ld) * 24];
            __half2* wl1 = (__half2*)&Whl[(buf * 256 + 128 + wm_ld) * 24];
            split2(wreg1.x, wreg1.y, hi, lo); wh1[2*wkw]   = hi; wl1[2*wkw]   = lo;
            split2(wreg1.z, wreg1.w, hi, lo); wh1[2*wkw+1] = hi; wl1[2*wkw+1] = lo;
            __half2* xr = (__half2*)&Xh[(buf * 16 + xk) * 136 + xn4];
            xr[0] = __floats2half2_rn(xreg.x, xreg.y);
            xr[1] = __floats2half2_rn(xreg.z, xreg.w);
        }
        __syncthreads();
        if (kt < 15) {
            int k0 = (kt + 1) * 16;
            const float* wp = W + (size_t)(o0 + wm_ld) * 256 + k0 + wkw * 4;
            wreg0 = *(const float4*)wp;
            wreg1 = *(const float4*)(wp + (size_t)128 * 256);
            xreg = *(const float4*)(Xb + (size_t)(k0 + xk) * Ntot + n0 + xn4);
            if (Xgb) {
                float4 g = *(const float4*)(Xgb + (size_t)(k0 + xk) * Ntot + n0 + xn4);
                xreg.x *= g.x / (1.f + __expf(-g.x));
                xreg.y *= g.y / (1.f + __expf(-g.y));
                xreg.z *= g.z / (1.f + __expf(-g.z));
                xreg.w *= g.w / (1.f + __expf(-g.w));
            }
            if (invMode) {
                ssq.x += xreg.x * xreg.x; ssq.y += xreg.y * xreg.y;
                ssq.z += xreg.z * xreg.z; ssq.w += xreg.w * xreg.w;
            }
        }
        unsigned ah[2][4], al[2][4];
        #pragma unroll
        for (int mt = 0; mt < 2; mt++) {
            int row = buf * 256 + wm * 32 + mt * 16 + (lane & 15);
            ldmx4(ah[mt], sptr(&Whh[row * 24 + (lane >> 4) * 8]));
            ldmx4(al[mt], sptr(&Whl[row * 24 + (lane >> 4) * 8]));
        }
        #pragma unroll
        for (int nt = 0; nt < 8; nt++) {
            unsigned b0, b1;
            int xrow = buf * 16 + (lane & 15);
            ldmx2t(b0, b1, sptr(&Xh[xrow * 136 + wn * 64 + nt * 8]));
            mma_h(acc[0][nt], ah[0], b0, b1);
            mma_h(acc[0][nt], al[0], b0, b1);
            mma_h(acc[1][nt], ah[1], b0, b1);
            mma_h(acc[1][nt], al[1], b0, b1);
        }
    }

    if (invMode) {
        part[xk * 32 + (tid & 31)] = ssq;
        __syncthreads();
        if (tid < 32) {
            float4 s = part[tid];
            #pragma unroll
            for (int r = 1; r < 16; r++) {
                float4 p = part[r * 32 + tid];
                s.x += p.x; s.y += p.y; s.z += p.z; s.w += p.w;
            }
            invs[tid * 4 + 0] = rsqrtf(s.x * (1.f / CC) + EPSV);
            invs[tid * 4 + 1] = rsqrtf(s.y * (1.f / CC) + EPSV);
            invs[tid * 4 + 2] = rsqrtf(s.z * (1.f / CC) + EPSV);
            invs[tid * 4 + 3] = rsqrtf(s.w * (1.f / CC) + EPSV);
        }
        __syncthreads();
    }

    #pragma unroll
    for (int mt = 0; mt < 2; mt++) {
        int row = o0 + wm * 32 + mt * 16 + group;
        float bv0 = bias ? bias[row]     : 0.f;
        float bv8 = bias ? bias[row + 8] : 0.f;
        #pragma unroll
        for (int nt = 0; nt < 8; nt++) {
            int cl = wn * 64 + nt * 8 + tid4 * 2;
            int col = n0 + cl;
            size_t i0 = (size_t)row * Ntot + col;
            size_t i8 = (size_t)(row + 8) * Ntot + col;
            float a0 = acc[mt][nt][0], a1 = acc[mt][nt][1];
            float a2 = acc[mt][nt][2], a3 = acc[mt][nt][3];
            if (invMode) {
                float s0 = invs[cl], s1 = invs[cl + 1];
                a0 *= s0; a1 *= s1; a2 *= s0; a3 *= s1;
            }
            float2 v0 = make_float2(a0 + bv0, a1 + bv0);
            float2 v8 = make_float2(a2 + bv8, a3 + bv8);
            if (Ab) {
                float2 r0 = *(const float2*)(Ab + i0);
                float2 r8 = *(const float2*)(Ab + i8);
                v0.x += r0.x; v0.y += r0.y;
                v8.x += r8.x; v8.y += r8.y;
            }
            *(float2*)(Yb + i0) = v0;
            *(float2*)(Yb + i8) = v8;
        }
    }
}

// ---------------- W row-scale precompute ----------------------------------------
__global__ void wscale_kernel(const float* __restrict__ W, const float* __restrict__ rs,
                              float* __restrict__ Wo, int n) {
    int i = blockIdx.x * 256 + threadIdx.x;
    if (i < n) Wo[i] = W[i] * rs[i & 255];
}

// ---------------- merged precompute GEMMs: P (tn) and OV (nn) -------------------
__global__ void pre_gemms(const float* __restrict__ kw, const float* __restrict__ qw,
                          const float* __restrict__ ow, const float* __restrict__ vw,
                          float* __restrict__ P, float* __restrict__ OV) {
    __shared__ float As[32][33], Bs[32][33];
    int mode = blockIdx.z;
    int m0 = blockIdx.y * 32, n0 = blockIdx.x * 32;
    int tx = threadIdx.x, ty = threadIdx.y;
    int tid = ty * 16 + tx;
    const float* A = mode ? ow : kw;
    const float* B = mode ? vw : qw;
    float acc[2][2] = {{0.f,0.f},{0.f,0.f}};
    for (int r0 = 0; r0 < CC; r0 += 32) {
        #pragma unroll
        for (int i = 0; i < 4; i++) {
            int e = i * 256 + tid;
            int a = e >> 5, c = e & 31;
            Bs[a][c] = B[(size_t)(r0 + a) * CC + n0 + c];
            As[a][c] = mode ? A[(size_t)(m0 + a) * CC + r0 + c]
                            : A[(size_t)(r0 + a) * CC + m0 + c];
        }
        __syncthreads();
        if (mode) {
            #pragma unroll
            for (int r = 0; r < 32; r++) {
                float a0 = As[ty*2][r], a1 = As[ty*2+1][r];
                float b0 = Bs[r][tx*2], b1 = Bs[r][tx*2+1];
                acc[0][0] += a0*b0; acc[0][1] += a0*b1;
                acc[1][0] += a1*b0; acc[1][1] += a1*b1;
            }
        } else {
            #pragma unroll
            for (int r = 0; r < 32; r++) {
                float a0 = As[r][ty*2], a1 = As[r][ty*2+1];
                float b0 = Bs[r][tx*2], b1 = Bs[r][tx*2+1];
                acc[0][0] += a0*b0; acc[0][1] += a0*b1;
                acc[1][0] += a1*b0; acc[1][1] += a1*b1;
            }
        }
        __syncthreads();
    }
    float* C = mode ? OV : P;
    #pragma unroll
    for (int i = 0; i < 2; i++)
        #pragma unroll
        for (int j = 0; j < 2; j++)
            C[(size_t)(m0 + ty*2 + i) * CC + n0 + tx*2 + j] = acc[i][j];
}

// ---------------- parallel vector precompute -------------------------------------
__global__ void vec_pre_kernel(const float* __restrict__ qw, const float* __restrict__ qb,
                               const float* __restrict__ kw, const float* __restrict__ kb,
                               const float* __restrict__ ow, const float* __restrict__ ob,
                               const float* __restrict__ vb) {
    __shared__ float red[4][8];
    int j = blockIdx.x;
    int o = threadIdx.x;
    float su = qb[o] * kw[(size_t)o * CC + j];
    float sw = qw[(size_t)o * CC + j] * kb[o];
    float sb = ow[(size_t)j * CC + o] * vb[o];
    float s0 = (j == 0) ? qb[o] * kb[o] : 0.f;
    #pragma unroll
    for (int d = 16; d; d >>= 1) {
        su += __shfl_xor_sync(0xffffffffu, su, d);
        sw += __shfl_xor_sync(0xffffffffu, sw, d);
        sb += __shfl_xor_sync(0xffffffffu, sb, d);
        s0 += __shfl_xor_sync(0xffffffffu, s0, d);
    }
    if ((o & 31) == 0) {
        int w = o >> 5;
        red[0][w] = su; red[1][w] = sw; red[2][w] = sb; red[3][w] = s0;
    }
    __syncthreads();
    if (o == 0) {
        float a = 0.f, b2 = 0.f, c = 0.f, d2 = 0.f;
        #pragma unroll
        for (int i = 0; i < 8; i++) {
            a += red[0][i]; b2 += red[1][i]; c += red[2][i]; d2 += red[3][i];
        }
        g_u[j] = a;
        g_w2[j] = b2;
        g_bias2[j] = c + ob[j];
        if (j == 0) g_misc[0] = d2;
    }
}

// ---------------- depthwise 3x3 causal conv + SiLU (fp16 in, fp32+fp16 out) -----
#define TB 16
__global__ void dwconv8_kernel(const __half* __restrict__ src,
                               const float* __restrict__ dww, const float* __restrict__ dwb,
                               float* __restrict__ emb, __half* __restrict__ embh) {
    int nblk = TT / TB;
    long idx = blockIdx.x;
    int tb = (int)(idx % nblk);
    long bc = idx / nblk;
    int c = (int)(bc % CC);
    int t0 = tb * TB;
    int f = threadIdx.x;
    __shared__ float rows[TB + 2][FF + 2];
    size_t chbase = (size_t)bc * TT * FF;
    #pragma unroll
    for (int r = 0; r < TB + 2; r++) {
        int tt = t0 - 2 + r;
        rows[r][f + 1] = (tt >= 0) ? __half2float(src[chbase + (size_t)tt * FF + f]) : 0.f;
        if (f == 0) { rows[r][0] = 0.f; rows[r][FF + 1] = 0.f; }
    }
    __syncthreads();
    float w[9];
    #pragma unroll
    for (int i = 0; i < 9; i++) w[i] = dww[c * 9 + i];
    float bv = dwb[c];
    #pragma unroll
    for (int r = 0; r < TB; r++) {
        float s = bv;
        #pragma unroll
        for (int dt = 0; dt < 3; dt++)
            #pragma unroll
            for (int df = 0; df < 3; df++)
                s += w[dt * 3 + df] * rows[r + dt][f + df];
        s = s / (1.f + __expf(-s));
        emb [chbase + (size_t)(t0 + r) * FF + f] = s;
        embh[chbase + (size_t)(t0 + r) * FF + f] = __float2half(s);
    }
}

// ---------------- qseed: batched skinny GEMM on tensor cores (fp16 input) -------
__global__ void __launch_bounds__(256, 2)
qseed_mma_kernel(const __half* __restrict__ embh, const float* __restrict__ basis,
                 float* __restrict__ Y)
{
    __shared__ __half Ah[2][128][40];
    __shared__ __half Bh[256 * 40];
    long row0 = (long)blockIdx.x * 128;
    int tid = threadIdx.x;
    int lane = tid & 31, warp = tid >> 5;
    int group = lane >> 2, tid4 = lane & 3;

    #pragma unroll
    for (int i = 0; i < 8; i++) {
        int e = i * 256 + tid;
        int k = e >> 6, f4 = e & 63;
        float4 v = *(const float4*)(basis + (size_t)k * 256 + f4 * 4);
        Bh[(f4 * 4 + 0) * 40 + k] = __float2half(v.x);
        Bh[(f4 * 4 + 1) * 40 + k] = __float2half(v.y);
        Bh[(f4 * 4 + 2) * 40 + k] = __float2half(v.z);
        Bh[(f4 * 4 + 3) * 40 + k] = __float2half(v.w);
    }

    float acc[4][4];
    #pragma unroll
    for (int nt = 0; nt < 4; nt++)
        #pragma unroll
        for (int r = 0; r < 4; r++) acc[nt][r] = 0.f;

    uint4 areg[2];
    int am = tid >> 1;
    int aj = (tid & 1) * 16;
    areg[0] = *(const uint4*)(embh + (row0 + am) * 256 + aj);
    areg[1] = *(const uint4*)(embh + (row0 + am) * 256 + aj + 8);

    #pragma unroll 1
    for (int kt = 0; kt < 8; kt++) {
        int buf = kt & 1;
        *(uint4*)&Ah[buf][am][aj]     = areg[0];
        *(uint4*)&Ah[buf][am][aj + 8] = areg[1];
        __syncthreads();
        if (kt < 7) {
            int ksn = (kt + 1) * 32;
            areg[0] = *(const uint4*)(embh + (row0 + am) * 256 + ksn + aj);
            areg[1] = *(const uint4*)(embh + (row0 + am) * 256 + ksn + aj + 8);
        }
        #pragma unroll
        for (int kk = 0; kk < 2; kk++) {
            unsigned a[4];
            ldmx4(a, sptr(&Ah[buf][warp * 16 + (lane & 15)][kk * 16 + (lane >> 4) * 8]));
            #pragma unroll
            for (int nt = 0; nt < 4; nt++) {
                unsigned b0, b1;
                ldmx2t(b0, b1, sptr(&Bh[(kt * 32 + kk * 16 + (lane & 15)) * 40 + nt * 8]));
                mma_h(acc[nt], a, b0, b1);
            }
        }
    }

    long r1 = row0 + warp * 16 + group;
    #pragma unroll
    for (int nt = 0; nt < 4; nt++) {
        int col = nt * 8 + tid4 * 2;
        *(float2*)(Y + r1 * 32 + col)       = make_float2(acc[nt][0], acc[nt][1]);
        *(float2*)(Y + (r1 + 8) * 32 + col) = make_float2(acc[nt][2], acc[nt][3]);
    }
}

// ---------------- colt ------------------------------------------------------------
__global__ void colt_kernel(const float* __restrict__ qs) {
    __shared__ float part[8][32];
    int bt = blockIdx.x;
    int b = bt / TT, t = bt % TT;
    size_t base = ((size_t)b * CC * TT + t) * KK;
    int k = threadIdx.x & 31, cg = threadIdx.x >> 5;
    float s = 0.f;
    for (int c = cg; c < CC; c += 8)
        s += g_w2[c] * qs[base + (size_t)c * TT * KK + k];
    part[cg][k] = s;
    __syncthreads();
    if (threadIdx.x < 32) {
        float tot = g_misc[0];
        #pragma unroll
        for (int i = 0; i < 8; i++) tot += part[i][k];
        g_colt[bt * KK + k] = tot;
    }
}

// ---------------- fused attention (512 threads): scores + softmax + pooled ------
#define ATTN_SMEM (256*264*2 + 34848 + 256*40*2)
__global__ void __launch_bounds__(512, 1)
attn_mma_kernel(const float* __restrict__ Q2, const __half* __restrict__ embh,
                const float* __restrict__ rb,
                const float* __restrict__ ssp, const float* __restrict__ psp,
                float* __restrict__ pooled)
{
    extern __shared__ __align__(16) char sm_[];
    __half* Eh = (__half*)sm_;
    char* regU = sm_ + 256 * 264 * 2;
    __half* q2T = (__half*)regU;
    float* scoresF = (float*)regU;
    float* poolSm = (float*)regU;
    __half* Wt = (__half*)(regU + 34848);
    __shared__ float colts[32];

    int bt = blockIdx.x;
    int b = bt / TT, t = bt % TT;
    size_t qframe = ((size_t)b * CC * TT + t) * KK;
    size_t eframe = ((size_t)b * CC * TT + t) * FF;
    int tid = threadIdx.x;
    int lane = tid & 31, warp = tid >> 5;
    int group = lane >> 2, tid4 = lane & 3;

    #pragma unroll 8
    for (int i = 0; i < 16; i++) {
        int e = i * 512 + tid;
        int c = e >> 5, f8 = e & 31;
        *(uint4*)&Eh[c * 264 + f8 * 8] =
            *(const uint4*)(embh + eframe + (size_t)c * TT * FF + f8 * 8);
    }
    for (int e = tid; e < 16 * 264; e += 512)
        q2T[32 * 264 + e] = __float2half(0.f);
    if (tid < 256) q2T[32 * 264 + tid] = __float2half(g_u[tid]);
    #pragma unroll
    for (int i = 0; i < 4; i++) {
        int e = i * 512 + tid;
        int c = e >> 3, j = e & 7;
        float4 v = *(const float4*)(Q2 + qframe + (size_t)c * TT * KK + j * 4);
        q2T[(4*j + 0) * 264 + c] = __float2half(v.x);
        q2T[(4*j + 1) * 264 + c] = __float2half(v.y);
        q2T[(4*j + 2) * 264 + c] = __float2half(v.z);
        q2T[(4*j + 3) * 264 + c] = __float2half(v.w);
    }
    if (tid < 32) colts[tid] = g_colt[bt * KK + tid];
    __syncthreads();

    float acc1[3][2][4];
    #pragma unroll
    for (int mt = 0; mt < 3; mt++)
        #pragma unroll
        for (int nt = 0; nt < 2; nt++)
            #pragma unroll
            for (int r = 0; r < 4; r++) acc1[mt][nt][r] = 0.f;

    #pragma unroll 1
    for (int ks = 0; ks < 256; ks += 16) {
        unsigned a[3][4];
        #pragma unroll
        for (int mt = 0; mt < 3; mt++)
            ldmx4(a[mt], sptr(&q2T[(mt * 16 + (lane & 15)) * 264 + ks + (lane >> 4) * 8]));
        #pragma unroll
        for (int nt = 0; nt < 2; nt++) {
            unsigned b0, b1;
            ldmx2t(b0, b1, sptr(&Eh[(ks + (lane & 15)) * 264 + warp * 16 + nt * 8]));
            mma_h(acc1[0][nt], a[0], b0, b1);
            mma_h(acc1[1][nt], a[1], b0, b1);
            mma_h(acc1[2][nt], a[2], b0, b1);
        }
    }
    __syncthreads();

    #pragma unroll
    for (int mt = 0; mt < 2; mt++)
        #pragma unroll
        for (int nt = 0; nt < 2; nt++) {
            int row = mt * 16 + group;
            int col = warp * 16 + nt * 8 + tid4 * 2;
            *(float2*)&scoresF[row * 264 + col]       = make_float2(acc1[mt][nt][0], acc1[mt][nt][1]);
            *(float2*)&scoresF[(row + 8) * 264 + col] = make_float2(acc1[mt][nt][2], acc1[mt][nt][3]);
        }
    if (group == 0) {
        #pragma unroll
        for (int nt = 0; nt < 2; nt++) {
            int col = warp * 16 + nt * 8 + tid4 * 2;
            *(float2*)&scoresF[32 * 264 + col] = make_float2(acc1[2][nt][0], acc1[2][nt][1]);
        }
    }
    __syncthreads();

    float ss = *ssp, ps = *psp;
    #pragma unroll
    for (int rr = 0; rr < 2; rr++) {
        int k = warp * 2 + rr;
        float cv = colts[k];
        float v[8];
        float m = -1e30f;
        #pragma unroll
        for (int i = 0; i < 8; i++) {
            int f = lane + 32 * i;
            float raw = scoresF[k * 264 + f];
            float uu  = scoresF[32 * 264 + f];
            v[i] = ss * (raw + uu + cv) + rb[k * FF + f] * ps;
            m = fmaxf(m, v[i]);
        }
        #pragma unroll
        for (int o = 16; o; o >>= 1) m = fmaxf(m, __shfl_xor_sync(0xffffffffu, m, o));
        float s = 0.f;
        #pragma unroll
        for (int i = 0; i < 8; i++) { v[i] = __expf(v[i] - m); s += v[i]; }
        #pragma unroll
        for (int o = 16; o; o >>= 1) s += __shfl_xor_sync(0xffffffffu, s, o);
        float inv = 1.f / s;
        #pragma unroll
        for (int i = 0; i < 8; i++) {
            int f = lane + 32 * i;
            Wt[f * 40 + k] = __float2half(v[i] * inv);
        }
    }
    __syncthreads();

    float acc2[4][4];
    #pragma unroll
    for (int nt = 0; nt < 4; nt++)
        #pragma unroll
        for (int r = 0; r < 4; r++) acc2[nt][r] = 0.f;

    #pragma unroll 1
    for (int fs = 0; fs < 256; fs += 16) {
        unsigned a[4];
        ldmx4(a, sptr(&Eh[(warp * 16 + (lane & 15)) * 264 + fs + (lane >> 4) * 8]));
        #pragma unroll
        for (int nt = 0; nt < 4; nt++) {
            unsigned b0, b1;
            ldmx2t(b0, b1, sptr(&Wt[(fs + (lane & 15)) * 40 + nt * 8]));
            mma_h(acc2[nt], a, b0, b1);
        }
    }
    __syncthreads();

    #pragma unroll
    for (int nt = 0; nt < 4; nt++) {
        int row = warp * 16 + group;
        int col = nt * 8 + tid4 * 2;
        *(float2*)&poolSm[row * 34 + col]       = make_float2(acc2[nt][0], acc2[nt][1]);
        *(float2*)&poolSm[(row + 8) * 34 + col] = make_float2(acc2[nt][2], acc2[nt][3]);
    }
    __syncthreads();
    #pragma unroll
    for (int i = 0; i < 16; i++) {
        int e = i * 512 + tid;
        int c = e >> 5, k = e & 31;
        pooled[qframe + (size_t)c * TT * KK + k] = poolSm[c * 34 + k];
    }
}

// ---------------- host launcher --------------------------------------------------
extern "C" void kernel_launch(void* const* d_in, const int* in_sizes, int n_in,
                              void* d_out, int out_size) {
    const float* x          = (const float*)d_in[0];
    const float* pre_norm_w = (const float*)d_in[1];
    const float* pre_pw_w   = (const float*)d_in[2];
    const float* pre_pw_b   = (const float*)d_in[3];
    const float* pre_dw_w   = (const float*)d_in[4];
    const float* pre_dw_b   = (const float*)d_in[5];
    const float* q_w        = (const float*)d_in[6];
    const float* q_b        = (const float*)d_in[7];
    const float* k_w        = (const float*)d_in[8];
    const float* k_b        = (const float*)d_in[9];
    const float* v_w        = (const float*)d_in[10];
    const float* v_b        = (const float*)d_in[11];
    const float* out_w      = (const float*)d_in[12];
    const float* out_b      = (const float*)d_in[13];
    const float* ffn_norm_w = (const float*)d_in[14];
    const float* ffn_in_w   = (const float*)d_in[15];
    const float* ffn_in_b   = (const float*)d_in[16];
    const float* ffn_out_w  = (const float*)d_in[17];
    const float* ffn_out_b  = (const float*)d_in[18];
    const float* score_scale= (const float*)d_in[19];
    const float* prior_scale= (const float*)d_in[20];
    const float* query_basis= (const float*)d_in[21];
    const float* routing_bias=(const float*)d_in[22];

    float* out        = (float*)d_out;
    float* out_hidden = out;
    float* out_emb    = out + (size_t)BB * CC * TT * KK;

    float *emb0, *qseed, *q2, *pooled, *hidden, *hffn;
    float *P, *OV, *Wp, *Wf, *bias2;
    __half* embh;
    cudaGetSymbolAddress((void**)&emb0,   g_emb0);
    cudaGetSymbolAddress((void**)&embh,   g_embh);
    cudaGetSymbolAddress((void**)&qseed,  g_qseed);
    cudaGetSymbolAddress((void**)&q2,     g_q2);
    cudaGetSymbolAddress((void**)&pooled, g_pooled);
    cudaGetSymbolAddress((void**)&hidden, g_hidden);
    cudaGetSymbolAddress((void**)&hffn,   g_hffn);
    cudaGetSymbolAddress((void**)&P,      g_P);
    cudaGetSymbolAddress((void**)&OV,     g_OV);
    cudaGetSymbolAddress((void**)&Wp,     g_Wp);
    cudaGetSymbolAddress((void**)&Wf,     g_Wf);
    cudaGetSymbolAddress((void**)&bias2,  g_bias2);

    cudaFuncSetAttribute(attn_mma_kernel,
                         cudaFuncAttributeMaxDynamicSharedMemorySize, ATTN_SMEM);
    cudaFuncSetAttribute(gemm_hs,
                         cudaFuncAttributeMaxDynamicSharedMemorySize, HS_SMEM);

    const int NBT = BB * TT;       // 800
    const int NF  = TT * FF;       // 102400
    const int NK  = TT * KK;       // 12800

    // precompute
    wscale_kernel<<<256, 256>>>(pre_pw_w, pre_norm_w, Wp, CC*CC);
    wscale_kernel<<<512, 256>>>(ffn_in_w, ffn_norm_w, Wf, 2*CC*CC);
    pre_gemms<<<dim3(8, 8, 2), dim3(16, 16)>>>(k_w, q_w, out_w, v_w, P, OV);
    vec_pre_kernel<<<256, 256>>>(q_w, q_b, k_w, k_b, out_w, out_b, v_b);

    // 1. pre pw with fused RMSNorm -> emb0 (fp16 storage)
    gemm_h<<<dim3(NF/128, 1, BB), 512>>>(Wp, pre_pw_b, x, nullptr,
                                         nullptr, (__half*)emb0, nullptr,
                                         1, CC, NF, (long)CC * NF);
    // 2. depthwise conv + SiLU -> emb (fp32 into d_out) + embh (fp16)
    dwconv8_kernel<<<(long)BB*CC*(TT/TB), FF>>>((const __half*)emb0, pre_dw_w, pre_dw_b,
                                                out_emb, embh);
    // 3. qseed = emb @ basis^T (fp16 input)
    qseed_mma_kernel<<<(BB*CC*TT)/128, 256>>>(embh, query_basis, qseed);
    // 4. colt
    colt_kernel<<<NBT, 256>>>(qseed);
    // 5. q2 = P @ qseed
    gemm_h<<<dim3(NK/128, 1, BB), 512>>>(P, nullptr, qseed, nullptr, q2, nullptr, nullptr,
                                         0, CC, NK, (long)CC * NK);
    // 6. fused attention (512 threads)
    attn_mma_kernel<<<NBT, 512, ATTN_SMEM>>>(q2, embh, routing_bias,
                                             score_scale, prior_scale, pooled);
    // 7. hidden = OV @ pooled + bias2   [2-term split]
    gemm_hs<<<dim3(NK/128, 1, BB), 512, HS_SMEM>>>(OV, bias2, pooled, nullptr, hidden, nullptr,
                                                   0, CC, NK, (long)CC * NK);
    // 8. ffn_in with fused RMSNorm       [2-term split]
    gemm_hs<<<dim3(NK/128, 2, BB), 512, HS_SMEM>>>(Wf, ffn_in_b, hidden, nullptr, hffn, nullptr,
                                                   1, 2*CC, NK, (long)CC * NK);
    // 9. ffn_out with fused GLU load + residual -> d_out   [2-term split]
    gemm_hs<<<dim3(NK/128, 1, BB), 512, HS_SMEM>>>(ffn_out_w, ffn_out_b, hffn,
                                                   hffn + (size_t)CC * NK,
                                                   out_hidden, hidden,
                                                   0, CC, NK, (long)2 * CC * NK);
}

// round 13
// speedup vs baseline: 1.1484x; 1.0161x over previous
#include <cuda_runtime.h>
#include <cuda_fp16.h>
#include <math.h>

#define BB 2
#define CC 256
#define TT 400
#define FF 256
#define KK 32
#define EPSV 1e-6f

typedef unsigned long long ull;

// ---------------- scratch ------------------------------------------------------
__device__ float  g_emb0   [(size_t)BB*CC*TT*FF];   // used as fp16 (half the space)
__device__ __half g_embh   [(size_t)BB*CC*TT*FF];   // fp16 copy of emb
__device__ __half g_basish [256*40];                // basis transposed fp16 [f][40]
__device__ float  g_qseed  [(size_t)BB*CC*TT*KK];
__device__ float  g_q2     [(size_t)BB*CC*TT*KK];
__device__ float  g_pooled [(size_t)BB*CC*TT*KK];
__device__ float  g_hidden [(size_t)BB*CC*TT*KK];
__device__ float  g_hffn   [(size_t)BB*2*CC*TT*KK];
__device__ float  g_P      [CC*CC];
__device__ float  g_OV     [CC*CC];
__device__ float  g_Wp     [CC*CC];
__device__ float  g_Wf     [2*CC*CC];
__device__ float  g_u      [CC];
__device__ float  g_w2     [CC];
__device__ float  g_bias2  [CC];
__device__ float  g_colt   [BB*TT*KK];
__device__ float  g_misc   [4];

// ---------------- helpers ------------------------------------------------------
__device__ __forceinline__ unsigned sptr(const void* p) {
    return (unsigned)__cvta_generic_to_shared(p);
}
__device__ __forceinline__ void ldmx4(unsigned* a, unsigned addr) {
    asm volatile("ldmatrix.sync.aligned.m8n8.x4.shared.b16 {%0,%1,%2,%3}, [%4];"
        : "=r"(a[0]), "=r"(a[1]), "=r"(a[2]), "=r"(a[3]) : "r"(addr));
}
__device__ __forceinline__ void ldmx2t(unsigned& b0, unsigned& b1, unsigned addr) {
    asm volatile("ldmatrix.sync.aligned.m8n8.x2.trans.shared.b16 {%0,%1}, [%2];"
        : "=r"(b0), "=r"(b1) : "r"(addr));
}
__device__ __forceinline__ void mma_h(float* c, const unsigned* a, unsigned b0, unsigned b1) {
    asm volatile("mma.sync.aligned.m16n8k16.row.col.f32.f16.f16.f32 "
        "{%0,%1,%2,%3}, {%4,%5,%6,%7}, {%8,%9}, {%0,%1,%2,%3};"
        : "+f"(c[0]), "+f"(c[1]), "+f"(c[2]), "+f"(c[3])
        : "r"(a[0]), "r"(a[1]), "r"(a[2]), "r"(a[3]), "r"(b0), "r"(b1));
}
__device__ __forceinline__ void split2(float x, float y, __half2& hi, __half2& lo) {
    hi = __floats2half2_rn(x, y);
    float2 hf = __half22float2(hi);
    lo = __floats2half2_rn(x - hf.x, y - hf.y);
}

// ---------------- unified fp16 tensor-core GEMM --------------------------------
__global__ void __launch_bounds__(512, 1)
gemm_h(const float* __restrict__ W, const float* __restrict__ bias,
       const float* __restrict__ X, const float* __restrict__ Xg,
       float* __restrict__ Y, __half* __restrict__ Yh,
       const float* __restrict__ addsrc,
       int invMode, int Cout, int Ntot, long xbstride)
{
    __shared__ __half Wh[2][256][24];
    __shared__ __half Xh[2][16][136];
    __shared__ float invs[128];
    __shared__ float4 part[16][32];

    int b  = blockIdx.z;
    int n0 = blockIdx.x * 128;
    int o0 = blockIdx.y * 256;
    const float* Xb  = X + (size_t)b * xbstride;
    const float* Xgb = Xg ? Xg + (size_t)b * xbstride : nullptr;
    float* Yb  = Y  ? Y  + (size_t)b * (size_t)Cout * Ntot : nullptr;
    __half* Yhb = Yh ? Yh + (size_t)b * (size_t)Cout * Ntot : nullptr;
    const float* Ab = addsrc ? addsrc + (size_t)b * (size_t)Cout * Ntot : nullptr;

    int tid = threadIdx.x;
    int lane = tid & 31, warp = tid >> 5;
    int wm = warp & 7, wn = warp >> 3;
    int group = lane >> 2, tid4 = lane & 3;

    int wm_ld = tid >> 2;
    int wkw   = tid & 3;
    int xk    = tid >> 5;
    int xn4   = (tid & 31) * 4;

    float acc[2][8][4];
    #pragma unroll
    for (int mt = 0; mt < 2; mt++)
        #pragma unroll
        for (int nt = 0; nt < 8; nt++)
            #pragma unroll
            for (int r = 0; r < 4; r++) acc[mt][nt][r] = 0.f;

    float4 ssq = make_float4(0.f, 0.f, 0.f, 0.f);
    float4 wreg0, wreg1, xreg;

    {
        const float* wp = W + (size_t)(o0 + wm_ld) * 256 + wkw * 4;
        wreg0 = *(const float4*)wp;
        wreg1 = *(const float4*)(wp + (size_t)128 * 256);
        xreg = *(const float4*)(Xb + (size_t)xk * Ntot + n0 + xn4);
        if (Xgb) {
            float4 g = *(const float4*)(Xgb + (size_t)xk * Ntot + n0 + xn4);
            xreg.x *= g.x / (1.f + __expf(-g.x));
            xreg.y *= g.y / (1.f + __expf(-g.y));
            xreg.z *= g.z / (1.f + __expf(-g.z));
            xreg.w *= g.w / (1.f + __expf(-g.w));
        }
        if (invMode) {
            ssq.x += xreg.x * xreg.x; ssq.y += xreg.y * xreg.y;
            ssq.z += xreg.z * xreg.z; ssq.w += xreg.w * xreg.w;
        }
    }

    #pragma unroll 1
    for (int kt = 0; kt < 16; kt++) {
        int buf = kt & 1;
        {
            __half2* wr0 = (__half2*)&Wh[buf][wm_ld][0];
            wr0[2 * wkw]     = __floats2half2_rn(wreg0.x, wreg0.y);
            wr0[2 * wkw + 1] = __floats2half2_rn(wreg0.z, wreg0.w);
            __half2* wr1 = (__half2*)&Wh[buf][128 + wm_ld][0];
            wr1[2 * wkw]     = __floats2half2_rn(wreg1.x, wreg1.y);
            wr1[2 * wkw + 1] = __floats2half2_rn(wreg1.z, wreg1.w);
            __half2* xr = (__half2*)&Xh[buf][xk][xn4];
            xr[0] = __floats2half2_rn(xreg.x, xreg.y);
            xr[1] = __floats2half2_rn(xreg.z, xreg.w);
        }
        __syncthreads();
        if (kt < 15) {
            int k0 = (kt + 1) * 16;
            const float* wp = W + (size_t)(o0 + wm_ld) * 256 + k0 + wkw * 4;
            wreg0 = *(const float4*)wp;
            wreg1 = *(const float4*)(wp + (size_t)128 * 256);
            xreg = *(const float4*)(Xb + (size_t)(k0 + xk) * Ntot + n0 + xn4);
            if (Xgb) {
                float4 g = *(const float4*)(Xgb + (size_t)(k0 + xk) * Ntot + n0 + xn4);
                xreg.x *= g.x / (1.f + __expf(-g.x));
                xreg.y *= g.y / (1.f + __expf(-g.y));
                xreg.z *= g.z / (1.f + __expf(-g.z));
                xreg.w *= g.w / (1.f + __expf(-g.w));
            }
            if (invMode) {
                ssq.x += xreg.x * xreg.x; ssq.y += xreg.y * xreg.y;
                ssq.z += xreg.z * xreg.z; ssq.w += xreg.w * xreg.w;
            }
        }
        unsigned a[2][4];
        #pragma unroll
        for (int mt = 0; mt < 2; mt++) {
            int row = wm * 32 + mt * 16 + (lane & 15);
            ldmx4(a[mt], sptr(&Wh[buf][row][(lane >> 4) * 8]));
        }
        #pragma unroll
        for (int nt = 0; nt < 8; nt++) {
            unsigned b0, b1;
            ldmx2t(b0, b1, sptr(&Xh[buf][lane & 15][wn * 64 + nt * 8]));
            mma_h(acc[0][nt], a[0], b0, b1);
            mma_h(acc[1][nt], a[1], b0, b1);
        }
    }

    if (invMode) {
        part[xk][tid & 31] = ssq;
        __syncthreads();
        if (tid < 32) {
            float4 s = part[0][tid];
            #pragma unroll
            for (int r = 1; r < 16; r++) {
                float4 p = part[r][tid];
                s.x += p.x; s.y += p.y; s.z += p.z; s.w += p.w;
            }
            invs[tid * 4 + 0] = rsqrtf(s.x * (1.f / CC) + EPSV);
            invs[tid * 4 + 1] = rsqrtf(s.y * (1.f / CC) + EPSV);
            invs[tid * 4 + 2] = rsqrtf(s.z * (1.f / CC) + EPSV);
            invs[tid * 4 + 3] = rsqrtf(s.w * (1.f / CC) + EPSV);
        }
        __syncthreads();
    }

    #pragma unroll
    for (int mt = 0; mt < 2; mt++) {
        int row = o0 + wm * 32 + mt * 16 + group;
        float bv0 = bias ? bias[row]     : 0.f;
        float bv8 = bias ? bias[row + 8] : 0.f;
        #pragma unroll
        for (int nt = 0; nt < 8; nt++) {
            int cl = wn * 64 + nt * 8 + tid4 * 2;
            int col = n0 + cl;
            size_t i0 = (size_t)row * Ntot + col;
            size_t i8 = (size_t)(row + 8) * Ntot + col;
            float a0 = acc[mt][nt][0], a1 = acc[mt][nt][1];
            float a2 = acc[mt][nt][2], a3 = acc[mt][nt][3];
            if (invMode) {
                float s0 = invs[cl], s1 = invs[cl + 1];
                a0 *= s0; a1 *= s1; a2 *= s0; a3 *= s1;
            }
            float2 v0 = make_float2(a0 + bv0, a1 + bv0);
            float2 v8 = make_float2(a2 + bv8, a3 + bv8);
            if (Ab) {
                float2 r0 = *(const float2*)(Ab + i0);
                float2 r8 = *(const float2*)(Ab + i8);
                v0.x += r0.x; v0.y += r0.y;
                v8.x += r8.x; v8.y += r8.y;
            }
            if (Yhb) {
                *(__half2*)(Yhb + i0) = __floats2half2_rn(v0.x, v0.y);
                *(__half2*)(Yhb + i8) = __floats2half2_rn(v8.x, v8.y);
            } else {
                *(float2*)(Yb + i0) = v0;
                *(float2*)(Yb + i8) = v8;
            }
        }
    }
}

// ---------------- 2-term split GEMM: W split (hi+lo), X plain fp16 --------------
#define HS_WHL   (2*256*24)
#define HS_XH    (2*(2*256*24))
#define HS_HALV  (HS_XH + 2*16*136)
#define HS_PART_B (HS_HALV * 2)
#define HS_INVS_B (HS_PART_B + 16*32*16)
#define HS_SMEM   (HS_INVS_B + 128*4)
__global__ void __launch_bounds__(512, 1)
gemm_hs(const float* __restrict__ W, const float* __restrict__ bias,
        const float* __restrict__ X, const float* __restrict__ Xg,
        float* __restrict__ Y, const float* __restrict__ addsrc,
        int invMode, int Cout, int Ntot, long xbstride)
{
    extern __shared__ __align__(16) char hsm[];
    __half* Whh = (__half*)(hsm);
    __half* Whl = (__half*)(hsm) + HS_WHL;
    __half* Xh  = (__half*)(hsm) + HS_XH;
    float4* part = (float4*)(hsm + HS_PART_B);
    float*  invs = (float*)(hsm + HS_INVS_B);

    int b  = blockIdx.z;
    int n0 = blockIdx.x * 128;
    int o0 = blockIdx.y * 256;
    const float* Xb  = X + (size_t)b * xbstride;
    const float* Xgb = Xg ? Xg + (size_t)b * xbstride : nullptr;
    float* Yb = Y + (size_t)b * (size_t)Cout * Ntot;
    const float* Ab = addsrc ? addsrc + (size_t)b * (size_t)Cout * Ntot : nullptr;

    int tid = threadIdx.x;
    int lane = tid & 31, warp = tid >> 5;
    int wm = warp & 7, wn = warp >> 3;
    int group = lane >> 2, tid4 = lane & 3;

    int wm_ld = tid >> 2;
    int wkw   = tid & 3;
    int xk    = tid >> 5;
    int xn4   = (tid & 31) * 4;

    float acc[2][8][4];
    #pragma unroll
    for (int mt = 0; mt < 2; mt++)
        #pragma unroll
        for (int nt = 0; nt < 8; nt++)
            #pragma unroll
            for (int r = 0; r < 4; r++) acc[mt][nt][r] = 0.f;

    float4 ssq = make_float4(0.f, 0.f, 0.f, 0.f);
    float4 wreg0, wreg1, xreg;

    {
        const float* wp = W + (size_t)(o0 + wm_ld) * 256 + wkw * 4;
        wreg0 = *(const float4*)wp;
        wreg1 = *(const float4*)(wp + (size_t)128 * 256);
        xreg = *(const float4*)(Xb + (size_t)xk * Ntot + n0 + xn4);
        if (Xgb) {
            float4 g = *(const float4*)(Xgb + (size_t)xk * Ntot + n0 + xn4);
            xreg.x *= g.x / (1.f + __expf(-g.x));
            xreg.y *= g.y / (1.f + __expf(-g.y));
            xreg.z *= g.z / (1.f + __expf(-g.z));
            xreg.w *= g.w / (1.f + __expf(-g.w));
        }
        if (invMode) {
            ssq.x += xreg.x * xreg.x; ssq.y += xreg.y * xreg.y;
            ssq.z += xreg.z * xreg.z; ssq.w += xreg.w * xreg.w;
        }
    }

    #pragma unroll 1
    for (int kt = 0; kt < 16; kt++) {
        int buf = kt & 1;
        {
            __half2 hi, lo;
            __half2* wh0 = (__half2*)&Whh[(buf * 256 + wm_ld) * 24];
            __half2* wl0 = (__half2*)&Whl[(buf * 256 + wm_ld) * 24];
            split2(wreg0.x, wreg0.y, hi, lo); wh0[2*wkw]   = hi; wl0[2*wkw]   = lo;
            split2(wreg0.z, wreg0.w, hi, lo); wh0[2*wkw+1] = hi; wl0[2*wkw+1] = lo;
            __half2* wh1 = (__half2*)&Whh[(buf * 256 + 128 + wm_ld) * 24];
            __half2* wl1 = (__half2*)&Whl[(buf * 256 + 128 + wm_ld) * 24];
            split2(wreg1.x, wreg1.y, hi, lo); wh1[2*wkw]   = hi; wl1[2*wkw]   = lo;
            split2(wreg1.z, wreg1.w, hi, lo); wh1[2*wkw+1] = hi; wl1[2*wkw+1] = lo;
            __half2* xr = (__half2*)&Xh[(buf * 16 + xk) * 136 + xn4];
            xr[0] = __floats2half2_rn(xreg.x, xreg.y);
            xr[1] = __floats2half2_rn(xreg.z, xreg.w);
        }
        __syncthreads();
        if (kt < 15) {
            int k0 = (kt + 1) * 16;
            const float* wp = W + (size_t)(o0 + wm_ld) * 256 + k0 + wkw * 4;
            wreg0 = *(const float4*)wp;
            wreg1 = *(const float4*)(wp + (size_t)128 * 256);
            xreg = *(const float4*)(Xb + (size_t)(k0 + xk) * Ntot + n0 + xn4);
            if (Xgb) {
                float4 g = *(const float4*)(Xgb + (size_t)(k0 + xk) * Ntot + n0 + xn4);
                xreg.x *= g.x / (1.f + __expf(-g.x));
                xreg.y *= g.y / (1.f + __expf(-g.y));
                xreg.z *= g.z / (1.f + __expf(-g.z));
                xreg.w *= g.w / (1.f + __expf(-g.w));
            }
            if (invMode) {
                ssq.x += xreg.x * xreg.x; ssq.y += xreg.y * xreg.y;
                ssq.z += xreg.z * xreg.z; ssq.w += xreg.w * xreg.w;
            }
        }
        unsigned ah[2][4], al[2][4];
        #pragma unroll
        for (int mt = 0; mt < 2; mt++) {
            int row = buf * 256 + wm * 32 + mt * 16 + (lane & 15);
            ldmx4(ah[mt], sptr(&Whh[row * 24 + (lane >> 4) * 8]));
            ldmx4(al[mt], sptr(&Whl[row * 24 + (lane >> 4) * 8]));
        }
        #pragma unroll
        for (int nt = 0; nt < 8; nt++) {
            unsigned b0, b1;
            int xrow = buf * 16 + (lane & 15);
            ldmx2t(b0, b1, sptr(&Xh[xrow * 136 + wn * 64 + nt * 8]));
            mma_h(acc[0][nt], ah[0], b0, b1);
            mma_h(acc[0][nt], al[0], b0, b1);
            mma_h(acc[1][nt], ah[1], b0, b1);
            mma_h(acc[1][nt], al[1], b0, b1);
        }
    }

    if (invMode) {
        part[xk * 32 + (tid & 31)] = ssq;
        __syncthreads();
        if (tid < 32) {
            float4 s = part[tid];
            #pragma unroll
            for (int r = 1; r < 16; r++) {
                float4 p = part[r * 32 + tid];
                s.x += p.x; s.y += p.y; s.z += p.z; s.w += p.w;
            }
            invs[tid * 4 + 0] = rsqrtf(s.x * (1.f / CC) + EPSV);
            invs[tid * 4 + 1] = rsqrtf(s.y * (1.f / CC) + EPSV);
            invs[tid * 4 + 2] = rsqrtf(s.z * (1.f / CC) + EPSV);
            invs[tid * 4 + 3] = rsqrtf(s.w * (1.f / CC) + EPSV);
        }
        __syncthreads();
    }

    #pragma unroll
    for (int mt = 0; mt < 2; mt++) {
        int row = o0 + wm * 32 + mt * 16 + group;
        float bv0 = bias ? bias[row]     : 0.f;
        float bv8 = bias ? bias[row + 8] : 0.f;
        #pragma unroll
        for (int nt = 0; nt < 8; nt++) {
            int cl = wn * 64 + nt * 8 + tid4 * 2;
            int col = n0 + cl;
            size_t i0 = (size_t)row * Ntot + col;
            size_t i8 = (size_t)(row + 8) * Ntot + col;
            float a0 = acc[mt][nt][0], a1 = acc[mt][nt][1];
            float a2 = acc[mt][nt][2], a3 = acc[mt][nt][3];
            if (invMode) {
                float s0 = invs[cl], s1 = invs[cl + 1];
                a0 *= s0; a1 *= s1; a2 *= s0; a3 *= s1;
            }
            float2 v0 = make_float2(a0 + bv0, a1 + bv0);
            float2 v8 = make_float2(a2 + bv8, a3 + bv8);
            if (Ab) {
                float2 r0 = *(const float2*)(Ab + i0);
                float2 r8 = *(const float2*)(Ab + i8);
                v0.x += r0.x; v0.y += r0.y;
                v8.x += r8.x; v8.y += r8.y;
            }
            *(float2*)(Yb + i0) = v0;
            *(float2*)(Yb + i8) = v8;
        }
    }
}

// ---------------- unified precompute kernel -------------------------------------
// blocks 0..255: Wp scale | 256..767: Wf scale | 768..895: P/OV gemms
// 896..1151: u/w2/bias2/s0 vectors | 1152..1191: basis fp16 transpose
__global__ void prep_kernel(const float* __restrict__ pw, const float* __restrict__ pnw,
                            const float* __restrict__ fw, const float* __restrict__ fnw,
                            const float* __restrict__ kw, const float* __restrict__ qw,
                            const float* __restrict__ ow, const float* __restrict__ vw,
                            const float* __restrict__ qb, const float* __restrict__ kb,
                            const float* __restrict__ ob, const float* __restrict__ vb,
                            const float* __restrict__ basis)
{
    __shared__ float As[32][33], Bs[32][33];
    __shared__ float red[4][8];
    int blk = blockIdx.x;
    int tid = threadIdx.x;

    if (blk < 256) {                       // Wp = pre_pw_w * pre_norm_w[col]
        int i = blk * 256 + tid;
        g_Wp[i] = pw[i] * pnw[i & 255];
    } else if (blk < 768) {                // Wf = ffn_in_w * ffn_norm_w[col]
        int i = (blk - 256) * 256 + tid;
        g_Wf[i] = fw[i] * fnw[i & 255];
    } else if (blk < 896) {                // P (tn) / OV (nn), double-buffered
        int bid = blk - 768;
        int mode = bid >> 6;
        int rem = bid & 63;
        int m0 = (rem >> 3) * 32, n0 = (rem & 7) * 32;
        int tx = tid & 15, ty = tid >> 4;
        const float* A = mode ? ow : kw;
        const float* B = mode ? vw : qw;
        float acc[2][2] = {{0.f,0.f},{0.f,0.f}};
        float aval[4], bval[4];
        #pragma unroll
        for (int i = 0; i < 4; i++) {
            int e = i * 256 + tid;
            int a = e >> 5, c = e & 31;
            bval[i] = B[(size_t)a * CC + n0 + c];
            aval[i] = mode ? A[(size_t)(m0 + a) * CC + c]
                           : A[(size_t)a * CC + m0 + c];
        }
        #pragma unroll 1
        for (int r0 = 0; r0 < CC; r0 += 32) {
            #pragma unroll
            for (int i = 0; i < 4; i++) {
                int e = i * 256 + tid;
                int a = e >> 5, c = e & 31;
                As[a][c] = aval[i];
                Bs[a][c] = bval[i];
            }
            __syncthreads();
            if (r0 + 32 < CC) {
                int r1 = r0 + 32;
                #pragma unroll
                for (int i = 0; i < 4; i++) {
                    int e = i * 256 + tid;
                    int a = e >> 5, c = e & 31;
                    bval[i] = B[(size_t)(r1 + a) * CC + n0 + c];
                    aval[i] = mode ? A[(size_t)(m0 + a) * CC + r1 + c]
                                   : A[(size_t)(r1 + a) * CC + m0 + c];
                }
            }
            if (mode) {
                #pragma unroll
                for (int r = 0; r < 32; r++) {
                    float a0 = As[ty*2][r], a1 = As[ty*2+1][r];
                    float b0 = Bs[r][tx*2], b1 = Bs[r][tx*2+1];
                    acc[0][0] += a0*b0; acc[0][1] += a0*b1;
                    acc[1][0] += a1*b0; acc[1][1] += a1*b1;
                }
            } else {
                #pragma unroll
                for (int r = 0; r < 32; r++) {
                    float a0 = As[r][ty*2], a1 = As[r][ty*2+1];
                    float b0 = Bs[r][tx*2], b1 = Bs[r][tx*2+1];
                    acc[0][0] += a0*b0; acc[0][1] += a0*b1;
                    acc[1][0] += a1*b0; acc[1][1] += a1*b1;
                }
            }
            __syncthreads();
        }
        float* C = mode ? g_OV : g_P;
        #pragma unroll
        for (int i = 0; i < 2; i++)
            #pragma unroll
            for (int j = 0; j < 2; j++)
                C[(size_t)(m0 + ty*2 + i) * CC + n0 + tx*2 + j] = acc[i][j];
    } else if (blk < 1152) {               // u / w2 / bias2 / s0
        int j = blk - 896;
        int o = tid;
        float su = qb[o] * kw[(size_t)o * CC + j];
        float sw = qw[(size_t)o * CC + j] * kb[o];
        float sb = ow[(size_t)j * CC + o] * vb[o];
        float s0 = (j == 0) ? qb[o] * kb[o] : 0.f;
        #pragma unroll
        for (int d = 16; d; d >>= 1) {
            su += __shfl_xor_sync(0xffffffffu, su, d);
            sw += __shfl_xor_sync(0xffffffffu, sw, d);
            sb += __shfl_xor_sync(0xffffffffu, sb, d);
            s0 += __shfl_xor_sync(0xffffffffu, s0, d);
        }
        if ((o & 31) == 0) {
            int w = o >> 5;
            red[0][w] = su; red[1][w] = sw; red[2][w] = sb; red[3][w] = s0;
        }
        __syncthreads();
        if (o == 0) {
            float a = 0.f, b2 = 0.f, c = 0.f, d2 = 0.f;
            #pragma unroll
            for (int i = 0; i < 8; i++) {
                a += red[0][i]; b2 += red[1][i]; c += red[2][i]; d2 += red[3][i];
            }
            g_u[j] = a;
            g_w2[j] = b2;
            g_bias2[j] = c + ob[j];
            if (j == 0) g_misc[0] = d2;
        }
    } else {                               // basis -> g_basish[f*40 + k] fp16
        int idx = (blk - 1152) * 256 + tid;
        if (idx < 256 * 40) {
            int f = idx / 40, k = idx % 40;
            g_basish[idx] = (k < 32) ? __float2half(basis[(size_t)k * 256 + f])
                                     : __float2half(0.f);
        }
    }
}

// ------- depthwise 3x3 causal conv + SiLU + fused qseed MMA ----------------------
#define TB 16
__global__ void __launch_bounds__(256)
dwconv_qseed(const __half* __restrict__ src,
             const float* __restrict__ dww, const float* __restrict__ dwb,
             float* __restrict__ emb, __half* __restrict__ embh,
             const __half* __restrict__ basish, float* __restrict__ Y)
{
    __shared__ float rows[TB + 2][FF + 2];
    __shared__ __half As[TB][264];
    __shared__ __half Bh[256 * 40];
    int nblk = TT / TB;
    long idx = blockIdx.x;
    int tb = (int)(idx % nblk);
    long bc = idx / nblk;
    int c = (int)(bc % CC);
    int t0 = tb * TB;
    int f = threadIdx.x;
    int lane = f & 31, warp = f >> 5;
    size_t chbase = (size_t)bc * TT * FF;

    // basis copy (L2-resident)
    {
        const uint4* bsrc = (const uint4*)basish;
        uint4* bdst = (uint4*)Bh;
        #pragma unroll
        for (int i = 0; i < 5; i++) {
            int e = i * 256 + f;
            if (e < 1280) bdst[e] = bsrc[e];
        }
    }
    #pragma unroll
    for (int r = 0; r < TB + 2; r++) {
        int tt = t0 - 2 + r;
        rows[r][f + 1] = (tt >= 0) ? __half2float(src[chbase + (size_t)tt * FF + f]) : 0.f;
        if (f == 0) { rows[r][0] = 0.f; rows[r][FF + 1] = 0.f; }
    }
    __syncthreads();
    float w[9];
    #pragma unroll
    for (int i = 0; i < 9; i++) w[i] = dww[c * 9 + i];
    float bv = dwb[c];
    #pragma unroll
    for (int r = 0; r < TB; r++) {
        float s = bv;
        #pragma unroll
        for (int dt = 0; dt < 3; dt++)
            #pragma unroll
            for (int df = 0; df < 3; df++)
                s += w[dt * 3 + df] * rows[r + dt][f + df];
        s = s / (1.f + __expf(-s));
        __half h = __float2half(s);
        emb [chbase + (size_t)(t0 + r) * FF + f] = s;
        embh[chbase + (size_t)(t0 + r) * FF + f] = h;
        As[r][f] = h;
    }
    __syncthreads();

    // qseed MMA: M=16 (t), N=32 (k), K=256 (f); warps 0-3 own 8 k-cols each
    if (warp < 4) {
        float acc[4] = {0.f, 0.f, 0.f, 0.f};
        #pragma unroll
        for (int ks = 0; ks < 16; ks++) {
            unsigned a[4];
            ldmx4(a, sptr(&As[lane & 15][ks * 16 + (lane >> 4) * 8]));
            unsigned b0, b1;
            ldmx2t(b0, b1, sptr(&Bh[(ks * 16 + (lane & 15)) * 40 + warp * 8]));
            mma_h(acc, a, b0, b1);
        }
        int group = lane >> 2, tid4 = lane & 3;
        int col = warp * 8 + tid4 * 2;
        long rbase = bc * TT + t0;
        *(float2*)(Y + (rbase + group) * 32 + col)     = make_float2(acc[0], acc[1]);
        *(float2*)(Y + (rbase + group + 8) * 32 + col) = make_float2(acc[2], acc[3]);
    }
}

// ---------------- colt ------------------------------------------------------------
__global__ void colt_kernel(const float* __restrict__ qs) {
    __shared__ float part[8][32];
    int bt = blockIdx.x;
    int b = bt / TT, t = bt % TT;
    size_t base = ((size_t)b * CC * TT + t) * KK;
    int k = threadIdx.x & 31, cg = threadIdx.x >> 5;
    float s = 0.f;
    for (int c = cg; c < CC; c += 8)
        s += g_w2[c] * qs[base + (size_t)c * TT * KK + k];
    part[cg][k] = s;
    __syncthreads();
    if (threadIdx.x < 32) {
        float tot = g_misc[0];
        #pragma unroll
        for (int i = 0; i < 8; i++) tot += part[i][k];
        g_colt[bt * KK + k] = tot;
    }
}

// ---------------- fused attention (512 threads): scores + softmax + pooled ------
#define ATTN_SMEM (256*264*2 + 34848 + 256*40*2)
__global__ void __launch_bounds__(512, 1)
attn_mma_kernel(const float* __restrict__ Q2, const __half* __restrict__ embh,
                const float* __restrict__ rb,
                const float* __restrict__ ssp, const float* __restrict__ psp,
                float* __restrict__ pooled)
{
    extern __shared__ __align__(16) char sm_[];
    __half* Eh = (__half*)sm_;
    char* regU = sm_ + 256 * 264 * 2;
    __half* q2T = (__half*)regU;
    float* scoresF = (float*)regU;
    float* poolSm = (float*)regU;
    __half* Wt = (__half*)(regU + 34848);
    __shared__ float colts[32];

    int bt = blockIdx.x;
    int b = bt / TT, t = bt % TT;
    size_t qframe = ((size_t)b * CC * TT + t) * KK;
    size_t eframe = ((size_t)b * CC * TT + t) * FF;
    int tid = threadIdx.x;
    int lane = tid & 31, warp = tid >> 5;
    int group = lane >> 2, tid4 = lane & 3;

    #pragma unroll 8
    for (int i = 0; i < 16; i++) {
        int e = i * 512 + tid;
        int c = e >> 5, f8 = e & 31;
        *(uint4*)&Eh[c * 264 + f8 * 8] =
            *(const uint4*)(embh + eframe + (size_t)c * TT * FF + f8 * 8);
    }
    for (int e = tid; e < 16 * 264; e += 512)
        q2T[32 * 264 + e] = __float2half(0.f);
    if (tid < 256) q2T[32 * 264 + tid] = __float2half(g_u[tid]);
    #pragma unroll
    for (int i = 0; i < 4; i++) {
        int e = i * 512 + tid;
        int c = e >> 3, j = e & 7;
        float4 v = *(const float4*)(Q2 + qframe + (size_t)c * TT * KK + j * 4);
        q2T[(4*j + 0) * 264 + c] = __float2half(v.x);
        q2T[(4*j + 1) * 264 + c] = __float2half(v.y);
        q2T[(4*j + 2) * 264 + c] = __float2half(v.z);
        q2T[(4*j + 3) * 264 + c] = __float2half(v.w);
    }
    if (tid < 32) colts[tid] = g_colt[bt * KK + tid];
    __syncthreads();

    float acc1[3][2][4];
    #pragma unroll
    for (int mt = 0; mt < 3; mt++)
        #pragma unroll
        for (int nt = 0; nt < 2; nt++)
            #pragma unroll
            for (int r = 0; r < 4; r++) acc1[mt][nt][r] = 0.f;

    #pragma unroll 1
    for (int ks = 0; ks < 256; ks += 16) {
        unsigned a[3][4];
        #pragma unroll
        for (int mt = 0; mt < 3; mt++)
            ldmx4(a[mt], sptr(&q2T[(mt * 16 + (lane & 15)) * 264 + ks + (lane >> 4) * 8]));
        #pragma unroll
        for (int nt = 0; nt < 2; nt++) {
            unsigned b0, b1;
            ldmx2t(b0, b1, sptr(&Eh[(ks + (lane & 15)) * 264 + warp * 16 + nt * 8]));
            mma_h(acc1[0][nt], a[0], b0, b1);
            mma_h(acc1[1][nt], a[1], b0, b1);
            mma_h(acc1[2][nt], a[2], b0, b1);
        }
    }
    __syncthreads();

    #pragma unroll
    for (int mt = 0; mt < 2; mt++)
        #pragma unroll
        for (int nt = 0; nt < 2; nt++) {
            int row = mt * 16 + group;
            int col = warp * 16 + nt * 8 + tid4 * 2;
            *(float2*)&scoresF[row * 264 + col]       = make_float2(acc1[mt][nt][0], acc1[mt][nt][1]);
            *(float2*)&scoresF[(row + 8) * 264 + col] = make_float2(acc1[mt][nt][2], acc1[mt][nt][3]);
        }
    if (group == 0) {
        #pragma unroll
        for (int nt = 0; nt < 2; nt++) {
            int col = warp * 16 + nt * 8 + tid4 * 2;
            *(float2*)&scoresF[32 * 264 + col] = make_float2(acc1[2][nt][0], acc1[2][nt][1]);
        }
    }
    __syncthreads();

    float ss = *ssp, ps = *psp;
    #pragma unroll
    for (int rr = 0; rr < 2; rr++) {
        int k = warp * 2 + rr;
        float cv = colts[k];
        float v[8];
        float m = -1e30f;
        #pragma unroll
        for (int i = 0; i < 8; i++) {
            int f = lane + 32 * i;
            float raw = scoresF[k * 264 + f];
            float uu  = scoresF[32 * 264 + f];
            v[i] = ss * (raw + uu + cv) + rb[k * FF + f] * ps;
            m = fmaxf(m, v[i]);
        }
        #pragma unroll
        for (int o = 16; o; o >>= 1) m = fmaxf(m, __shfl_xor_sync(0xffffffffu, m, o));
        float s = 0.f;
        #pragma unroll
        for (int i = 0; i < 8; i++) { v[i] = __expf(v[i] - m); s += v[i]; }
        #pragma unroll
        for (int o = 16; o; o >>= 1) s += __shfl_xor_sync(0xffffffffu, s, o);
        float inv = 1.f / s;
        #pragma unroll
        for (int i = 0; i < 8; i++) {
            int f = lane + 32 * i;
            Wt[f * 40 + k] = __float2half(v[i] * inv);
        }
    }
    __syncthreads();

    float acc2[4][4];
    #pragma unroll
    for (int nt = 0; nt < 4; nt++)
        #pragma unroll
        for (int r = 0; r < 4; r++) acc2[nt][r] = 0.f;

    #pragma unroll 1
    for (int fs = 0; fs < 256; fs += 16) {
        unsigned a[4];
        ldmx4(a, sptr(&Eh[(warp * 16 + (lane & 15)) * 264 + fs + (lane >> 4) * 8]));
        #pragma unroll
        for (int nt = 0; nt < 4; nt++) {
            unsigned b0, b1;
            ldmx2t(b0, b1, sptr(&Wt[(fs + (lane & 15)) * 40 + nt * 8]));
            mma_h(acc2[nt], a, b0, b1);
        }
    }
    __syncthreads();

    #pragma unroll
    for (int nt = 0; nt < 4; nt++) {
        int row = warp * 16 + group;
        int col = nt * 8 + tid4 * 2;
        *(float2*)&poolSm[row * 34 + col]       = make_float2(acc2[nt][0], acc2[nt][1]);
        *(float2*)&poolSm[(row + 8) * 34 + col] = make_float2(acc2[nt][2], acc2[nt][3]);
    }
    __syncthreads();
    #pragma unroll
    for (int i = 0; i < 16; i++) {
        int e = i * 512 + tid;
        int c = e >> 5, k = e & 31;
        pooled[qframe + (size_t)c * TT * KK + k] = poolSm[c * 34 + k];
    }
}

// ---------------- host launcher --------------------------------------------------
extern "C" void kernel_launch(void* const* d_in, const int* in_sizes, int n_in,
                              void* d_out, int out_size) {
    const float* x          = (const float*)d_in[0];
    const float* pre_norm_w = (const float*)d_in[1];
    const float* pre_pw_w   = (const float*)d_in[2];
    const float* pre_pw_b   = (const float*)d_in[3];
    const float* pre_dw_w   = (const float*)d_in[4];
    const float* pre_dw_b   = (const float*)d_in[5];
    const float* q_w        = (const float*)d_in[6];
    const float* q_b        = (const float*)d_in[7];
    const float* k_w        = (const float*)d_in[8];
    const float* k_b        = (const float*)d_in[9];
    const float* v_w        = (const float*)d_in[10];
    const float* v_b        = (const float*)d_in[11];
    const float* out_w      = (const float*)d_in[12];
    const float* out_b      = (const float*)d_in[13];
    const float* ffn_norm_w = (const float*)d_in[14];
    const float* ffn_in_w   = (const float*)d_in[15];
    const float* ffn_in_b   = (const float*)d_in[16];
    const float* ffn_out_w  = (const float*)d_in[17];
    const float* ffn_out_b  = (const float*)d_in[18];
    const float* score_scale= (const float*)d_in[19];
    const float* prior_scale= (const float*)d_in[20];
    const float* query_basis= (const float*)d_in[21];
    const float* routing_bias=(const float*)d_in[22];

    float* out        = (float*)d_out;
    float* out_hidden = out;
    float* out_emb    = out + (size_t)BB * CC * TT * KK;

    float *emb0, *qseed, *q2, *pooled, *hidden, *hffn;
    float *P, *OV, *Wp, *Wf, *bias2;
    __half *embh, *basish;
    cudaGetSymbolAddress((void**)&emb0,   g_emb0);
    cudaGetSymbolAddress((void**)&embh,   g_embh);
    cudaGetSymbolAddress((void**)&basish, g_basish);
    cudaGetSymbolAddress((void**)&qseed,  g_qseed);
    cudaGetSymbolAddress((void**)&q2,     g_q2);
    cudaGetSymbolAddress((void**)&pooled, g_pooled);
    cudaGetSymbolAddress((void**)&hidden, g_hidden);
    cudaGetSymbolAddress((void**)&hffn,   g_hffn);
    cudaGetSymbolAddress((void**)&P,      g_P);
    cudaGetSymbolAddress((void**)&OV,     g_OV);
    cudaGetSymbolAddress((void**)&Wp,     g_Wp);
    cudaGetSymbolAddress((void**)&Wf,     g_Wf);
    cudaGetSymbolAddress((void**)&bias2,  g_bias2);

    cudaFuncSetAttribute(attn_mma_kernel,
                         cudaFuncAttributeMaxDynamicSharedMemorySize, ATTN_SMEM);
    cudaFuncSetAttribute(gemm_hs,
                         cudaFuncAttributeMaxDynamicSharedMemorySize, HS_SMEM);

    const int NBT = BB * TT;       // 800
    const int NF  = TT * FF;       // 102400
    const int NK  = TT * KK;       // 12800

    // 0. unified precompute (Wp, Wf, P, OV, u/w2/bias2/s0, basis fp16)
    prep_kernel<<<1192, 256>>>(pre_pw_w, pre_norm_w, ffn_in_w, ffn_norm_w,
                               k_w, q_w, out_w, v_w,
                               q_b, k_b, out_b, v_b, query_basis);

    // 1. pre pw with fused RMSNorm -> emb0 (fp16 storage)
    gemm_h<<<dim3(NF/128, 1, BB), 512>>>(Wp, pre_pw_b, x, nullptr,
                                         nullptr, (__half*)emb0, nullptr,
                                         1, CC, NF, (long)CC * NF);
    // 2. depthwise conv + SiLU -> emb (fp32), embh (fp16), qseed (fused MMA)
    dwconv_qseed<<<(long)BB*CC*(TT/TB), 256>>>((const __half*)emb0, pre_dw_w, pre_dw_b,
                                               out_emb, embh, basish, qseed);
    // 3. colt
    colt_kernel<<<NBT, 256>>>(qseed);
    // 4. q2 = P @ qseed
    gemm_h<<<dim3(NK/128, 1, BB), 512>>>(P, nullptr, qseed, nullptr, q2, nullptr, nullptr,
                                         0, CC, NK, (long)CC * NK);
    // 5. fused attention (512 threads)
    attn_mma_kernel<<<NBT, 512, ATTN_SMEM>>>(q2, embh, routing_bias,
                                             score_scale, prior_scale, pooled);
    // 6. hidden = OV @ pooled + bias2   [2-term split]
    gemm_hs<<<dim3(NK/128, 1, BB), 512, HS_SMEM>>>(OV, bias2, pooled, nullptr, hidden, nullptr,
                                                   0, CC, NK, (long)CC * NK);
    // 7. ffn_in with fused RMSNorm       [2-term split]
    gemm_hs<<<dim3(NK/128, 2, BB), 512, HS_SMEM>>>(Wf, ffn_in_b, hidden, nullptr, hffn, nullptr,
                                                   1, 2*CC, NK, (long)CC * NK);
    // 8. ffn_out with fused GLU load + residual -> d_out   [2-term split]
    gemm_hs<<<dim3(NK/128, 1, BB), 512, HS_SMEM>>>(ffn_out_w, ffn_out_b, hffn,
                                                   hffn + (size_t)CC * NK,
                                                   out_hidden, hidden,
                                                   0, CC, NK, (long)2 * CC * NK);
}

// round 14
// speedup vs baseline: 1.1590x; 1.0092x over previous
#include <cuda_runtime.h>
#include <cuda_fp16.h>
#include <math.h>

#define BB 2
#define CC 256
#define TT 400
#define FF 256
#define KK 32
#define EPSV 1e-6f

typedef unsigned long long ull;

// ---------------- scratch ------------------------------------------------------
__device__ float  g_emb0   [(size_t)BB*CC*TT*FF];   // used as fp16 (half the space)
__device__ __half g_embh   [(size_t)BB*CC*TT*FF];   // fp16 copy of emb
__device__ __half g_basish [256*40];                // basis transposed fp16 [f][40]
__device__ float  g_qseed  [(size_t)BB*CC*TT*KK];
__device__ float  g_q2     [(size_t)BB*CC*TT*KK];
__device__ float  g_pooled [(size_t)BB*CC*TT*KK];
__device__ float  g_hidden [(size_t)BB*CC*TT*KK];
__device__ float  g_hffn   [(size_t)BB*2*CC*TT*KK];
__device__ float  g_P      [CC*CC];
__device__ float  g_OV     [CC*CC];
__device__ float  g_Wp     [CC*CC];
__device__ float  g_Wf     [2*CC*CC];
__device__ float  g_u      [CC];
__device__ float  g_bias2  [CC];

// ---------------- helpers ------------------------------------------------------
__device__ __forceinline__ unsigned sptr(const void* p) {
    return (unsigned)__cvta_generic_to_shared(p);
}
__device__ __forceinline__ void ldmx4(unsigned* a, unsigned addr) {
    asm volatile("ldmatrix.sync.aligned.m8n8.x4.shared.b16 {%0,%1,%2,%3}, [%4];"
        : "=r"(a[0]), "=r"(a[1]), "=r"(a[2]), "=r"(a[3]) : "r"(addr));
}
__device__ __forceinline__ void ldmx2t(unsigned& b0, unsigned& b1, unsigned addr) {
    asm volatile("ldmatrix.sync.aligned.m8n8.x2.trans.shared.b16 {%0,%1}, [%2];"
        : "=r"(b0), "=r"(b1) : "r"(addr));
}
__device__ __forceinline__ void mma_h(float* c, const unsigned* a, unsigned b0, unsigned b1) {
    asm volatile("mma.sync.aligned.m16n8k16.row.col.f32.f16.f16.f32 "
        "{%0,%1,%2,%3}, {%4,%5,%6,%7}, {%8,%9}, {%0,%1,%2,%3};"
        : "+f"(c[0]), "+f"(c[1]), "+f"(c[2]), "+f"(c[3])
        : "r"(a[0]), "r"(a[1]), "r"(a[2]), "r"(a[3]), "r"(b0), "r"(b1));
}
__device__ __forceinline__ void split2(float x, float y, __half2& hi, __half2& lo) {
    hi = __floats2half2_rn(x, y);
    float2 hf = __half22float2(hi);
    lo = __floats2half2_rn(x - hf.x, y - hf.y);
}

// ---------------- unified fp16 tensor-core GEMM --------------------------------
__global__ void __launch_bounds__(512, 1)
gemm_h(const float* __restrict__ W, const float* __restrict__ bias,
       const float* __restrict__ X, const float* __restrict__ Xg,
       float* __restrict__ Y, __half* __restrict__ Yh,
       const float* __restrict__ addsrc,
       int invMode, int Cout, int Ntot, long xbstride)
{
    __shared__ __half Wh[2][256][24];
    __shared__ __half Xh[2][16][136];
    __shared__ float invs[128];
    __shared__ float4 part[16][32];

    int b  = blockIdx.z;
    int n0 = blockIdx.x * 128;
    int o0 = blockIdx.y * 256;
    const float* Xb  = X + (size_t)b * xbstride;
    const float* Xgb = Xg ? Xg + (size_t)b * xbstride : nullptr;
    float* Yb  = Y  ? Y  + (size_t)b * (size_t)Cout * Ntot : nullptr;
    __half* Yhb = Yh ? Yh + (size_t)b * (size_t)Cout * Ntot : nullptr;
    const float* Ab = addsrc ? addsrc + (size_t)b * (size_t)Cout * Ntot : nullptr;

    int tid = threadIdx.x;
    int lane = tid & 31, warp = tid >> 5;
    int wm = warp & 7, wn = warp >> 3;
    int group = lane >> 2, tid4 = lane & 3;

    int wm_ld = tid >> 2;
    int wkw   = tid & 3;
    int xk    = tid >> 5;
    int xn4   = (tid & 31) * 4;

    float acc[2][8][4];
    #pragma unroll
    for (int mt = 0; mt < 2; mt++)
        #pragma unroll
        for (int nt = 0; nt < 8; nt++)
            #pragma unroll
            for (int r = 0; r < 4; r++) acc[mt][nt][r] = 0.f;

    float4 ssq = make_float4(0.f, 0.f, 0.f, 0.f);
    float4 wreg0, wreg1, xreg;

    {
        const float* wp = W + (size_t)(o0 + wm_ld) * 256 + wkw * 4;
        wreg0 = *(const float4*)wp;
        wreg1 = *(const float4*)(wp + (size_t)128 * 256);
        xreg = *(const float4*)(Xb + (size_t)xk * Ntot + n0 + xn4);
        if (Xgb) {
            float4 g = *(const float4*)(Xgb + (size_t)xk * Ntot + n0 + xn4);
            xreg.x *= g.x / (1.f + __expf(-g.x));
            xreg.y *= g.y / (1.f + __expf(-g.y));
            xreg.z *= g.z / (1.f + __expf(-g.z));
            xreg.w *= g.w / (1.f + __expf(-g.w));
        }
        if (invMode) {
            ssq.x += xreg.x * xreg.x; ssq.y += xreg.y * xreg.y;
            ssq.z += xreg.z * xreg.z; ssq.w += xreg.w * xreg.w;
        }
    }

    #pragma unroll 1
    for (int kt = 0; kt < 16; kt++) {
        int buf = kt & 1;
        {
            __half2* wr0 = (__half2*)&Wh[buf][wm_ld][0];
            wr0[2 * wkw]     = __floats2half2_rn(wreg0.x, wreg0.y);
            wr0[2 * wkw + 1] = __floats2half2_rn(wreg0.z, wreg0.w);
            __half2* wr1 = (__half2*)&Wh[buf][128 + wm_ld][0];
            wr1[2 * wkw]     = __floats2half2_rn(wreg1.x, wreg1.y);
            wr1[2 * wkw + 1] = __floats2half2_rn(wreg1.z, wreg1.w);
            __half2* xr = (__half2*)&Xh[buf][xk][xn4];
            xr[0] = __floats2half2_rn(xreg.x, xreg.y);
            xr[1] = __floats2half2_rn(xreg.z, xreg.w);
        }
        __syncthreads();
        if (kt < 15) {
            int k0 = (kt + 1) * 16;
            const float* wp = W + (size_t)(o0 + wm_ld) * 256 + k0 + wkw * 4;
            wreg0 = *(const float4*)wp;
            wreg1 = *(const float4*)(wp + (size_t)128 * 256);
            xreg = *(const float4*)(Xb + (size_t)(k0 + xk) * Ntot + n0 + xn4);
            if (Xgb) {
                float4 g = *(const float4*)(Xgb + (size_t)(k0 + xk) * Ntot + n0 + xn4);
                xreg.x *= g.x / (1.f + __expf(-g.x));
                xreg.y *= g.y / (1.f + __expf(-g.y));
                xreg.z *= g.z / (1.f + __expf(-g.z));
                xreg.w *= g.w / (1.f + __expf(-g.w));
            }
            if (invMode) {
                ssq.x += xreg.x * xreg.x; ssq.y += xreg.y * xreg.y;
                ssq.z += xreg.z * xreg.z; ssq.w += xreg.w * xreg.w;
            }
        }
        unsigned a[2][4];
        #pragma unroll
        for (int mt = 0; mt < 2; mt++) {
            int row = wm * 32 + mt * 16 + (lane & 15);
            ldmx4(a[mt], sptr(&Wh[buf][row][(lane >> 4) * 8]));
        }
        #pragma unroll
        for (int nt = 0; nt < 8; nt++) {
            unsigned b0, b1;
            ldmx2t(b0, b1, sptr(&Xh[buf][lane & 15][wn * 64 + nt * 8]));
            mma_h(acc[0][nt], a[0], b0, b1);
            mma_h(acc[1][nt], a[1], b0, b1);
        }
    }

    if (invMode) {
        part[xk][tid & 31] = ssq;
        __syncthreads();
        if (tid < 32) {
            float4 s = part[0][tid];
            #pragma unroll
            for (int r = 1; r < 16; r++) {
                float4 p = part[r][tid];
                s.x += p.x; s.y += p.y; s.z += p.z; s.w += p.w;
            }
            invs[tid * 4 + 0] = rsqrtf(s.x * (1.f / CC) + EPSV);
            invs[tid * 4 + 1] = rsqrtf(s.y * (1.f / CC) + EPSV);
            invs[tid * 4 + 2] = rsqrtf(s.z * (1.f / CC) + EPSV);
            invs[tid * 4 + 3] = rsqrtf(s.w * (1.f / CC) + EPSV);
        }
        __syncthreads();
    }

    #pragma unroll
    for (int mt = 0; mt < 2; mt++) {
        int row = o0 + wm * 32 + mt * 16 + group;
        float bv0 = bias ? bias[row]     : 0.f;
        float bv8 = bias ? bias[row + 8] : 0.f;
        #pragma unroll
        for (int nt = 0; nt < 8; nt++) {
            int cl = wn * 64 + nt * 8 + tid4 * 2;
            int col = n0 + cl;
            size_t i0 = (size_t)row * Ntot + col;
            size_t i8 = (size_t)(row + 8) * Ntot + col;
            float a0 = acc[mt][nt][0], a1 = acc[mt][nt][1];
            float a2 = acc[mt][nt][2], a3 = acc[mt][nt][3];
            if (invMode) {
                float s0 = invs[cl], s1 = invs[cl + 1];
                a0 *= s0; a1 *= s1; a2 *= s0; a3 *= s1;
            }
            float2 v0 = make_float2(a0 + bv0, a1 + bv0);
            float2 v8 = make_float2(a2 + bv8, a3 + bv8);
            if (Ab) {
                float2 r0 = *(const float2*)(Ab + i0);
                float2 r8 = *(const float2*)(Ab + i8);
                v0.x += r0.x; v0.y += r0.y;
                v8.x += r8.x; v8.y += r8.y;
            }
            if (Yhb) {
                *(__half2*)(Yhb + i0) = __floats2half2_rn(v0.x, v0.y);
                *(__half2*)(Yhb + i8) = __floats2half2_rn(v8.x, v8.y);
            } else {
                *(float2*)(Yb + i0) = v0;
                *(float2*)(Yb + i8) = v8;
            }
        }
    }
}

// ---------------- 2-term split GEMM: W split (hi+lo), X plain fp16 --------------
#define HS_WHL   (2*256*24)
#define HS_XH    (2*(2*256*24))
#define HS_HALV  (HS_XH + 2*16*136)
#define HS_PART_B (HS_HALV * 2)
#define HS_INVS_B (HS_PART_B + 16*32*16)
#define HS_SMEM   (HS_INVS_B + 128*4)
__global__ void __launch_bounds__(512, 1)
gemm_hs(const float* __restrict__ W, const float* __restrict__ bias,
        const float* __restrict__ X, const float* __restrict__ Xg,
        float* __restrict__ Y, const float* __restrict__ addsrc,
        int invMode, int Cout, int Ntot, long xbstride)
{
    extern __shared__ __align__(16) char hsm[];
    __half* Whh = (__half*)(hsm);
    __half* Whl = (__half*)(hsm) + HS_WHL;
    __half* Xh  = (__half*)(hsm) + HS_XH;
    float4* part = (float4*)(hsm + HS_PART_B);
    float*  invs = (float*)(hsm + HS_INVS_B);

    int b  = blockIdx.z;
    int n0 = blockIdx.x * 128;
    int o0 = blockIdx.y * 256;
    const float* Xb  = X + (size_t)b * xbstride;
    const float* Xgb = Xg ? Xg + (size_t)b * xbstride : nullptr;
    float* Yb = Y + (size_t)b * (size_t)Cout * Ntot;
    const float* Ab = addsrc ? addsrc + (size_t)b * (size_t)Cout * Ntot : nullptr;

    int tid = threadIdx.x;
    int lane = tid & 31, warp = tid >> 5;
    int wm = warp & 7, wn = warp >> 3;
    int group = lane >> 2, tid4 = lane & 3;

    int wm_ld = tid >> 2;
    int wkw   = tid & 3;
    int xk    = tid >> 5;
    int xn4   = (tid & 31) * 4;

    float acc[2][8][4];
    #pragma unroll
    for (int mt = 0; mt < 2; mt++)
        #pragma unroll
        for (int nt = 0; nt < 8; nt++)
            #pragma unroll
            for (int r = 0; r < 4; r++) acc[mt][nt][r] = 0.f;

    float4 ssq = make_float4(0.f, 0.f, 0.f, 0.f);
    float4 wreg0, wreg1, xreg;

    {
        const float* wp = W + (size_t)(o0 + wm_ld) * 256 + wkw * 4;
        wreg0 = *(const float4*)wp;
        wreg1 = *(const float4*)(wp + (size_t)128 * 256);
        xreg = *(const float4*)(Xb + (size_t)xk * Ntot + n0 + xn4);
        if (Xgb) {
            float4 g = *(const float4*)(Xgb + (size_t)xk * Ntot + n0 + xn4);
            xreg.x *= g.x / (1.f + __expf(-g.x));
            xreg.y *= g.y / (1.f + __expf(-g.y));
            xreg.z *= g.z / (1.f + __expf(-g.z));
            xreg.w *= g.w / (1.f + __expf(-g.w));
        }
        if (invMode) {
            ssq.x += xreg.x * xreg.x; ssq.y += xreg.y * xreg.y;
            ssq.z += xreg.z * xreg.z; ssq.w += xreg.w * xreg.w;
        }
    }

    #pragma unroll 1
    for (int kt = 0; kt < 16; kt++) {
        int buf = kt & 1;
        {
            __half2 hi, lo;
            __half2* wh0 = (__half2*)&Whh[(buf * 256 + wm_ld) * 24];
            __half2* wl0 = (__half2*)&Whl[(buf * 256 + wm_ld) * 24];
            split2(wreg0.x, wreg0.y, hi, lo); wh0[2*wkw]   = hi; wl0[2*wkw]   = lo;
            split2(wreg0.z, wreg0.w, hi, lo); wh0[2*wkw+1] = hi; wl0[2*wkw+1] = lo;
            __half2* wh1 = (__half2*)&Whh[(buf * 256 + 128 + wm_ld) * 24];
            __half2* wl1 = (__half2*)&Whl[(buf * 256 + 128 + wm_ld) * 24];
            split2(wreg1.x, wreg1.y, hi, lo); wh1[2*wkw]   = hi; wl1[2*wkw]   = lo;
            split2(wreg1.z, wreg1.w, hi, lo); wh1[2*wkw+1] = hi; wl1[2*wkw+1] = lo;
            __half2* xr = (__half2*)&Xh[(buf * 16 + xk) * 136 + xn4];
            xr[0] = __floats2half2_rn(xreg.x, xreg.y);
            xr[1] = __floats2half2_rn(xreg.z, xreg.w);
        }
        __syncthreads();
        if (kt < 15) {
            int k0 = (kt + 1) * 16;
            const float* wp = W + (size_t)(o0 + wm_ld) * 256 + k0 + wkw * 4;
            wreg0 = *(const float4*)wp;
            wreg1 = *(const float4*)(wp + (size_t)128 * 256);
            xreg = *(const float4*)(Xb + (size_t)(k0 + xk) * Ntot + n0 + xn4);
            if (Xgb) {
                float4 g = *(const float4*)(Xgb + (size_t)(k0 + xk) * Ntot + n0 + xn4);
                xreg.x *= g.x / (1.f + __expf(-g.x));
                xreg.y *= g.y / (1.f + __expf(-g.y));
                xreg.z *= g.z / (1.f + __expf(-g.z));
                xreg.w *= g.w / (1.f + __expf(-g.w));
            }
            if (invMode) {
                ssq.x += xreg.x * xreg.x; ssq.y += xreg.y * xreg.y;
                ssq.z += xreg.z * xreg.z; ssq.w += xreg.w * xreg.w;
            }
        }
        unsigned ah[2][4], al[2][4];
        #pragma unroll
        for (int mt = 0; mt < 2; mt++) {
            int row = buf * 256 + wm * 32 + mt * 16 + (lane & 15);
            ldmx4(ah[mt], sptr(&Whh[row * 24 + (lane >> 4) * 8]));
            ldmx4(al[mt], sptr(&Whl[row * 24 + (lane >> 4) * 8]));
        }
        #pragma unroll
        for (int nt = 0; nt < 8; nt++) {
            unsigned b0, b1;
            int xrow = buf * 16 + (lane & 15);
            ldmx2t(b0, b1, sptr(&Xh[xrow * 136 + wn * 64 + nt * 8]));
            mma_h(acc[0][nt], ah[0], b0, b1);
            mma_h(acc[0][nt], al[0], b0, b1);
            mma_h(acc[1][nt], ah[1], b0, b1);
            mma_h(acc[1][nt], al[1], b0, b1);
        }
    }

    if (invMode) {
        part[xk * 32 + (tid & 31)] = ssq;
        __syncthreads();
        if (tid < 32) {
            float4 s = part[tid];
            #pragma unroll
            for (int r = 1; r < 16; r++) {
                float4 p = part[r * 32 + tid];
                s.x += p.x; s.y += p.y; s.z += p.z; s.w += p.w;
            }
            invs[tid * 4 + 0] = rsqrtf(s.x * (1.f / CC) + EPSV);
            invs[tid * 4 + 1] = rsqrtf(s.y * (1.f / CC) + EPSV);
            invs[tid * 4 + 2] = rsqrtf(s.z * (1.f / CC) + EPSV);
            invs[tid * 4 + 3] = rsqrtf(s.w * (1.f / CC) + EPSV);
        }
        __syncthreads();
    }

    #pragma unroll
    for (int mt = 0; mt < 2; mt++) {
        int row = o0 + wm * 32 + mt * 16 + group;
        float bv0 = bias ? bias[row]     : 0.f;
        float bv8 = bias ? bias[row + 8] : 0.f;
        #pragma unroll
        for (int nt = 0; nt < 8; nt++) {
            int cl = wn * 64 + nt * 8 + tid4 * 2;
            int col = n0 + cl;
            size_t i0 = (size_t)row * Ntot + col;
            size_t i8 = (size_t)(row + 8) * Ntot + col;
            float a0 = acc[mt][nt][0], a1 = acc[mt][nt][1];
            float a2 = acc[mt][nt][2], a3 = acc[mt][nt][3];
            if (invMode) {
                float s0 = invs[cl], s1 = invs[cl + 1];
                a0 *= s0; a1 *= s1; a2 *= s0; a3 *= s1;
            }
            float2 v0 = make_float2(a0 + bv0, a1 + bv0);
            float2 v8 = make_float2(a2 + bv8, a3 + bv8);
            if (Ab) {
                float2 r0 = *(const float2*)(Ab + i0);
                float2 r8 = *(const float2*)(Ab + i8);
                v0.x += r0.x; v0.y += r0.y;
                v8.x += r8.x; v8.y += r8.y;
            }
            *(float2*)(Yb + i0) = v0;
            *(float2*)(Yb + i8) = v8;
        }
    }
}

// ---------------- unified precompute kernel -------------------------------------
// blocks 0..255: Wp scale | 256..767: Wf scale | 768..895: P/OV gemms
// 896..1151: u/bias2 vectors | 1152..1191: basis fp16 transpose
__global__ void prep_kernel(const float* __restrict__ pw, const float* __restrict__ pnw,
                            const float* __restrict__ fw, const float* __restrict__ fnw,
                            const float* __restrict__ kw, const float* __restrict__ qw,
                            const float* __restrict__ ow, const float* __restrict__ vw,
                            const float* __restrict__ qb, const float* __restrict__ kb,
                            const float* __restrict__ ob, const float* __restrict__ vb,
                            const float* __restrict__ basis)
{
    __shared__ float As[32][33], Bs[32][33];
    __shared__ float red[2][8];
    int blk = blockIdx.x;
    int tid = threadIdx.x;

    if (blk < 256) {
        int i = blk * 256 + tid;
        g_Wp[i] = pw[i] * pnw[i & 255];
    } else if (blk < 768) {
        int i = (blk - 256) * 256 + tid;
        g_Wf[i] = fw[i] * fnw[i & 255];
    } else if (blk < 896) {
        int bid = blk - 768;
        int mode = bid >> 6;
        int rem = bid & 63;
        int m0 = (rem >> 3) * 32, n0 = (rem & 7) * 32;
        int tx = tid & 15, ty = tid >> 4;
        const float* A = mode ? ow : kw;
        const float* B = mode ? vw : qw;
        float acc[2][2] = {{0.f,0.f},{0.f,0.f}};
        float aval[4], bval[4];
        #pragma unroll
        for (int i = 0; i < 4; i++) {
            int e = i * 256 + tid;
            int a = e >> 5, c = e & 31;
            bval[i] = B[(size_t)a * CC + n0 + c];
            aval[i] = mode ? A[(size_t)(m0 + a) * CC + c]
                           : A[(size_t)a * CC + m0 + c];
        }
        #pragma unroll 1
        for (int r0 = 0; r0 < CC; r0 += 32) {
            #pragma unroll
            for (int i = 0; i < 4; i++) {
                int e = i * 256 + tid;
                int a = e >> 5, c = e & 31;
                As[a][c] = aval[i];
                Bs[a][c] = bval[i];
            }
            __syncthreads();
            if (r0 + 32 < CC) {
                int r1 = r0 + 32;
                #pragma unroll
                for (int i = 0; i < 4; i++) {
                    int e = i * 256 + tid;
                    int a = e >> 5, c = e & 31;
                    bval[i] = B[(size_t)(r1 + a) * CC + n0 + c];
                    aval[i] = mode ? A[(size_t)(m0 + a) * CC + r1 + c]
                                   : A[(size_t)(r1 + a) * CC + m0 + c];
                }
            }
            if (mode) {
                #pragma unroll
                for (int r = 0; r < 32; r++) {
                    float a0 = As[ty*2][r], a1 = As[ty*2+1][r];
                    float b0 = Bs[r][tx*2], b1 = Bs[r][tx*2+1];
                    acc[0][0] += a0*b0; acc[0][1] += a0*b1;
                    acc[1][0] += a1*b0; acc[1][1] += a1*b1;
                }
            } else {
                #pragma unroll
                for (int r = 0; r < 32; r++) {
                    float a0 = As[r][ty*2], a1 = As[r][ty*2+1];
                    float b0 = Bs[r][tx*2], b1 = Bs[r][tx*2+1];
                    acc[0][0] += a0*b0; acc[0][1] += a0*b1;
                    acc[1][0] += a1*b0; acc[1][1] += a1*b1;
                }
            }
            __syncthreads();
        }
        float* C = mode ? g_OV : g_P;
        #pragma unroll
        for (int i = 0; i < 2; i++)
            #pragma unroll
            for (int j = 0; j < 2; j++)
                C[(size_t)(m0 + ty*2 + i) * CC + n0 + tx*2 + j] = acc[i][j];
    } else if (blk < 1152) {               // u / bias2
        int j = blk - 896;
        int o = tid;
        float su = qb[o] * kw[(size_t)o * CC + j];
        float sb = ow[(size_t)j * CC + o] * vb[o];
        #pragma unroll
        for (int d = 16; d; d >>= 1) {
            su += __shfl_xor_sync(0xffffffffu, su, d);
            sb += __shfl_xor_sync(0xffffffffu, sb, d);
        }
        if ((o & 31) == 0) {
            int w = o >> 5;
            red[0][w] = su; red[1][w] = sb;
        }
        __syncthreads();
        if (o == 0) {
            float a = 0.f, c = 0.f;
            #pragma unroll
            for (int i = 0; i < 8; i++) { a += red[0][i]; c += red[1][i]; }
            g_u[j] = a;
            g_bias2[j] = c + ob[j];
        }
    } else {
        int idx = (blk - 1152) * 256 + tid;
        if (idx < 256 * 40) {
            int f = idx / 40, k = idx % 40;
            g_basish[idx] = (k < 32) ? __float2half(basis[(size_t)k * 256 + f])
                                     : __float2half(0.f);
        }
    }
}

// ------- depthwise 3x3 causal conv + SiLU + fused qseed MMA ----------------------
#define TB 16
__global__ void __launch_bounds__(256)
dwconv_qseed(const __half* __restrict__ src,
             const float* __restrict__ dww, const float* __restrict__ dwb,
             float* __restrict__ emb, __half* __restrict__ embh,
             const __half* __restrict__ basish, float* __restrict__ Y)
{
    __shared__ float rows[TB + 2][FF + 2];
    __shared__ __half As[TB][264];
    __shared__ __half Bh[256 * 40];
    int nblk = TT / TB;
    long idx = blockIdx.x;
    int tb = (int)(idx % nblk);
    long bc = idx / nblk;
    int c = (int)(bc % CC);
    int t0 = tb * TB;
    int f = threadIdx.x;
    int lane = f & 31, warp = f >> 5;
    size_t chbase = (size_t)bc * TT * FF;

    {
        const uint4* bsrc = (const uint4*)basish;
        uint4* bdst = (uint4*)Bh;
        #pragma unroll
        for (int i = 0; i < 5; i++) {
            int e = i * 256 + f;
            if (e < 1280) bdst[e] = bsrc[e];
        }
    }
    #pragma unroll
    for (int r = 0; r < TB + 2; r++) {
        int tt = t0 - 2 + r;
        rows[r][f + 1] = (tt >= 0) ? __half2float(src[chbase + (size_t)tt * FF + f]) : 0.f;
        if (f == 0) { rows[r][0] = 0.f; rows[r][FF + 1] = 0.f; }
    }
    __syncthreads();
    float w[9];
    #pragma unroll
    for (int i = 0; i < 9; i++) w[i] = dww[c * 9 + i];
    float bv = dwb[c];
    #pragma unroll
    for (int r = 0; r < TB; r++) {
        float s = bv;
        #pragma unroll
        for (int dt = 0; dt < 3; dt++)
            #pragma unroll
            for (int df = 0; df < 3; df++)
                s += w[dt * 3 + df] * rows[r + dt][f + df];
        s = s / (1.f + __expf(-s));
        __half h = __float2half(s);
        emb [chbase + (size_t)(t0 + r) * FF + f] = s;
        embh[chbase + (size_t)(t0 + r) * FF + f] = h;
        As[r][f] = h;
    }
    __syncthreads();

    if (warp < 4) {
        float acc[4] = {0.f, 0.f, 0.f, 0.f};
        #pragma unroll
        for (int ks = 0; ks < 16; ks++) {
            unsigned a[4];
            ldmx4(a, sptr(&As[lane & 15][ks * 16 + (lane >> 4) * 8]));
            unsigned b0, b1;
            ldmx2t(b0, b1, sptr(&Bh[(ks * 16 + (lane & 15)) * 40 + warp * 8]));
            mma_h(acc, a, b0, b1);
        }
        int group = lane >> 2, tid4 = lane & 3;
        int col = warp * 8 + tid4 * 2;
        long rbase = bc * TT + t0;
        *(float2*)(Y + (rbase + group) * 32 + col)     = make_float2(acc[0], acc[1]);
        *(float2*)(Y + (rbase + group + 8) * 32 + col) = make_float2(acc[2], acc[3]);
    }
}

// ---------------- fused attention (512 threads): scores + softmax + pooled ------
// colt / s0 terms dropped: constant per (bt,k) row => softmax shift-invariant
#define ATTN_SMEM (256*264*2 + 34848 + 256*40*2)
__global__ void __launch_bounds__(512, 1)
attn_mma_kernel(const float* __restrict__ Q2, const __half* __restrict__ embh,
                const float* __restrict__ rb,
                const float* __restrict__ ssp, const float* __restrict__ psp,
                float* __restrict__ pooled)
{
    extern __shared__ __align__(16) char sm_[];
    __half* Eh = (__half*)sm_;
    char* regU = sm_ + 256 * 264 * 2;
    __half* q2T = (__half*)regU;
    float* scoresF = (float*)regU;
    float* poolSm = (float*)regU;
    __half* Wt = (__half*)(regU + 34848);

    int bt = blockIdx.x;
    int b = bt / TT, t = bt % TT;
    size_t qframe = ((size_t)b * CC * TT + t) * KK;
    size_t eframe = ((size_t)b * CC * TT + t) * FF;
    int tid = threadIdx.x;
    int lane = tid & 31, warp = tid >> 5;
    int group = lane >> 2, tid4 = lane & 3;

    #pragma unroll 8
    for (int i = 0; i < 16; i++) {
        int e = i * 512 + tid;
        int c = e >> 5, f8 = e & 31;
        *(uint4*)&Eh[c * 264 + f8 * 8] =
            *(const uint4*)(embh + eframe + (size_t)c * TT * FF + f8 * 8);
    }
    for (int e = tid; e < 16 * 264; e += 512)
        q2T[32 * 264 + e] = __float2half(0.f);
    if (tid < 256) q2T[32 * 264 + tid] = __float2half(g_u[tid]);
    #pragma unroll
    for (int i = 0; i < 4; i++) {
        int e = i * 512 + tid;
        int c = e >> 3, j = e & 7;
        float4 v = *(const float4*)(Q2 + qframe + (size_t)c * TT * KK + j * 4);
        q2T[(4*j + 0) * 264 + c] = __float2half(v.x);
        q2T[(4*j + 1) * 264 + c] = __float2half(v.y);
        q2T[(4*j + 2) * 264 + c] = __float2half(v.z);
        q2T[(4*j + 3) * 264 + c] = __float2half(v.w);
    }
    __syncthreads();

    float acc1[3][2][4];
    #pragma unroll
    for (int mt = 0; mt < 3; mt++)
        #pragma unroll
        for (int nt = 0; nt < 2; nt++)
            #pragma unroll
            for (int r = 0; r < 4; r++) acc1[mt][nt][r] = 0.f;

    #pragma unroll 1
    for (int ks = 0; ks < 256; ks += 16) {
        unsigned a[3][4];
        #pragma unroll
        for (int mt = 0; mt < 3; mt++)
            ldmx4(a[mt], sptr(&q2T[(mt * 16 + (lane & 15)) * 264 + ks + (lane >> 4) * 8]));
        #pragma unroll
        for (int nt = 0; nt < 2; nt++) {
            unsigned b0, b1;
            ldmx2t(b0, b1, sptr(&Eh[(ks + (lane & 15)) * 264 + warp * 16 + nt * 8]));
            mma_h(acc1[0][nt], a[0], b0, b1);
            mma_h(acc1[1][nt], a[1], b0, b1);
            mma_h(acc1[2][nt], a[2], b0, b1);
        }
    }
    __syncthreads();

    #pragma unroll
    for (int mt = 0; mt < 2; mt++)
        #pragma unroll
        for (int nt = 0; nt < 2; nt++) {
            int row = mt * 16 + group;
            int col = warp * 16 + nt * 8 + tid4 * 2;
            *(float2*)&scoresF[row * 264 + col]       = make_float2(acc1[mt][nt][0], acc1[mt][nt][1]);
            *(float2*)&scoresF[(row + 8) * 264 + col] = make_float2(acc1[mt][nt][2], acc1[mt][nt][3]);
        }
    if (group == 0) {
        #pragma unroll
        for (int nt = 0; nt < 2; nt++) {
            int col = warp * 16 + nt * 8 + tid4 * 2;
            *(float2*)&scoresF[32 * 264 + col] = make_float2(acc1[2][nt][0], acc1[2][nt][1]);
        }
    }
    __syncthreads();

    float ss = *ssp, ps = *psp;
    #pragma unroll
    for (int rr = 0; rr < 2; rr++) {
        int k = warp * 2 + rr;
        float v[8];
        float m = -1e30f;
        #pragma unroll
        for (int i = 0; i < 8; i++) {
            int f = lane + 32 * i;
            float raw = scoresF[k * 264 + f];
            float uu  = scoresF[32 * 264 + f];
            v[i] = ss * (raw + uu) + rb[k * FF + f] * ps;
            m = fmaxf(m, v[i]);
        }
        #pragma unroll
        for (int o = 16; o; o >>= 1) m = fmaxf(m, __shfl_xor_sync(0xffffffffu, m, o));
        float s = 0.f;
        #pragma unroll
        for (int i = 0; i < 8; i++) { v[i] = __expf(v[i] - m); s += v[i]; }
        #pragma unroll
        for (int o = 16; o; o >>= 1) s += __shfl_xor_sync(0xffffffffu, s, o);
        float inv = 1.f / s;
        #pragma unroll
        for (int i = 0; i < 8; i++) {
            int f = lane + 32 * i;
            Wt[f * 40 + k] = __float2half(v[i] * inv);
        }
    }
    __syncthreads();

    float acc2[4][4];
    #pragma unroll
    for (int nt = 0; nt < 4; nt++)
        #pragma unroll
        for (int r = 0; r < 4; r++) acc2[nt][r] = 0.f;

    #pragma unroll 1
    for (int fs = 0; fs < 256; fs += 16) {
        unsigned a[4];
        ldmx4(a, sptr(&Eh[(warp * 16 + (lane & 15)) * 264 + fs + (lane >> 4) * 8]));
        #pragma unroll
        for (int nt = 0; nt < 4; nt++) {
            unsigned b0, b1;
            ldmx2t(b0, b1, sptr(&Wt[(fs + (lane & 15)) * 40 + nt * 8]));
            mma_h(acc2[nt], a, b0, b1);
        }
    }
    __syncthreads();

    #pragma unroll
    for (int nt = 0; nt < 4; nt++) {
        int row = warp * 16 + group;
        int col = nt * 8 + tid4 * 2;
        *(float2*)&poolSm[row * 34 + col]       = make_float2(acc2[nt][0], acc2[nt][1]);
        *(float2*)&poolSm[(row + 8) * 34 + col] = make_float2(acc2[nt][2], acc2[nt][3]);
    }
    __syncthreads();
    #pragma unroll
    for (int i = 0; i < 16; i++) {
        int e = i * 512 + tid;
        int c = e >> 5, k = e & 31;
        pooled[qframe + (size_t)c * TT * KK + k] = poolSm[c * 34 + k];
    }
}

// ---------------- host launcher --------------------------------------------------
extern "C" void kernel_launch(void* const* d_in, const int* in_sizes, int n_in,
                              void* d_out, int out_size) {
    const float* x          = (const float*)d_in[0];
    const float* pre_norm_w = (const float*)d_in[1];
    const float* pre_pw_w   = (const float*)d_in[2];
    const float* pre_pw_b   = (const float*)d_in[3];
    const float* pre_dw_w   = (const float*)d_in[4];
    const float* pre_dw_b   = (const float*)d_in[5];
    const float* q_w        = (const float*)d_in[6];
    const float* q_b        = (const float*)d_in[7];
    const float* k_w        = (const float*)d_in[8];
    const float* k_b        = (const float*)d_in[9];
    const float* v_w        = (const float*)d_in[10];
    const float* v_b        = (const float*)d_in[11];
    const float* out_w      = (const float*)d_in[12];
    const float* out_b      = (const float*)d_in[13];
    const float* ffn_norm_w = (const float*)d_in[14];
    const float* ffn_in_w   = (const float*)d_in[15];
    const float* ffn_in_b   = (const float*)d_in[16];
    const float* ffn_out_w  = (const float*)d_in[17];
    const float* ffn_out_b  = (const float*)d_in[18];
    const float* score_scale= (const float*)d_in[19];
    const float* prior_scale= (const float*)d_in[20];
    const float* query_basis= (const float*)d_in[21];
    const float* routing_bias=(const float*)d_in[22];

    float* out        = (float*)d_out;
    float* out_hidden = out;
    float* out_emb    = out + (size_t)BB * CC * TT * KK;

    float *emb0, *qseed, *q2, *pooled, *hidden, *hffn;
    float *P, *OV, *Wp, *Wf, *bias2;
    __half *embh, *basish;
    cudaGetSymbolAddress((void**)&emb0,   g_emb0);
    cudaGetSymbolAddress((void**)&embh,   g_embh);
    cudaGetSymbolAddress((void**)&basish, g_basish);
    cudaGetSymbolAddress((void**)&qseed,  g_qseed);
    cudaGetSymbolAddress((void**)&q2,     g_q2);
    cudaGetSymbolAddress((void**)&pooled, g_pooled);
    cudaGetSymbolAddress((void**)&hidden, g_hidden);
    cudaGetSymbolAddress((void**)&hffn,   g_hffn);
    cudaGetSymbolAddress((void**)&P,      g_P);
    cudaGetSymbolAddress((void**)&OV,     g_OV);
    cudaGetSymbolAddress((void**)&Wp,     g_Wp);
    cudaGetSymbolAddress((void**)&Wf,     g_Wf);
    cudaGetSymbolAddress((void**)&bias2,  g_bias2);

    cudaFuncSetAttribute(attn_mma_kernel,
                         cudaFuncAttributeMaxDynamicSharedMemorySize, ATTN_SMEM);
    cudaFuncSetAttribute(gemm_hs,
                         cudaFuncAttributeMaxDynamicSharedMemorySize, HS_SMEM);

    const int NBT = BB * TT;       // 800
    const int NF  = TT * FF;       // 102400
    const int NK  = TT * KK;       // 12800

    // 0. unified precompute
    prep_kernel<<<1192, 256>>>(pre_pw_w, pre_norm_w, ffn_in_w, ffn_norm_w,
                               k_w, q_w, out_w, v_w,
                               q_b, k_b, out_b, v_b, query_basis);

    // 1. pre pw with fused RMSNorm -> emb0 (fp16 storage)
    gemm_h<<<dim3(NF/128, 1, BB), 512>>>(Wp, pre_pw_b, x, nullptr,
                                         nullptr, (__half*)emb0, nullptr,
                                         1, CC, NF, (long)CC * NF);
    // 2. depthwise conv + SiLU -> emb (fp32), embh (fp16), qseed (fused MMA)
    dwconv_qseed<<<(long)BB*CC*(TT/TB), 256>>>((const __half*)emb0, pre_dw_w, pre_dw_b,
                                               out_emb, embh, basish, qseed);
    // 3. q2 = P @ qseed
    gemm_h<<<dim3(NK/128, 1, BB), 512>>>(P, nullptr, qseed, nullptr, q2, nullptr, nullptr,
                                         0, CC, NK, (long)CC * NK);
    // 4. fused attention (colt/s0 dropped: softmax shift-invariance)
    attn_mma_kernel<<<NBT, 512, ATTN_SMEM>>>(q2, embh, routing_bias,
                                             score_scale, prior_scale, pooled);
    // 5. hidden = OV @ pooled + bias2   [2-term split]
    gemm_hs<<<dim3(NK/128, 1, BB), 512, HS_SMEM>>>(OV, bias2, pooled, nullptr, hidden, nullptr,
                                                   0, CC, NK, (long)CC * NK);
    // 6. ffn_in with fused RMSNorm       [2-term split]
    gemm_hs<<<dim3(NK/128, 2, BB), 512, HS_SMEM>>>(Wf, ffn_in_b, hidden, nullptr, hffn, nullptr,
                                                   1, 2*CC, NK, (long)CC * NK);
    // 7. ffn_out with fused GLU load + residual -> d_out   [2-term split]
    gemm_hs<<<dim3(NK/128, 1, BB), 512, HS_SMEM>>>(ffn_out_w, ffn_out_b, hffn,
                                                   hffn + (size_t)CC * NK,
                                                   out_hidden, hidden,
                                                   0, CC, NK, (long)2 * CC * NK);
}

// round 15
// speedup vs baseline: 1.1597x; 1.0006x over previous
#include <cuda_runtime.h>
#include <cuda_fp16.h>
#include <math.h>

#define BB 2
#define CC 256
#define TT 400
#define FF 256
#define KK 32
#define EPSV 1e-6f

typedef unsigned long long ull;

// ---------------- scratch ------------------------------------------------------
__device__ float  g_emb0   [(size_t)BB*CC*TT*FF];   // used as fp16 (half the space)
__device__ __half g_embh   [(size_t)BB*CC*TT*FF];   // fp16 copy of emb
__device__ __half g_basish [256*40];                // basis transposed fp16 [f][40]
__device__ float  g_qseed  [(size_t)BB*CC*TT*KK];
__device__ float  g_q2     [(size_t)BB*CC*TT*KK];
__device__ float  g_pooled [(size_t)BB*CC*TT*KK];
__device__ float  g_hidden [(size_t)BB*CC*TT*KK];
__device__ float  g_hffn   [(size_t)BB*2*CC*TT*KK];
__device__ float  g_P      [CC*CC];
__device__ float  g_OV     [CC*CC];
__device__ float  g_Wp     [CC*CC];
__device__ float  g_Wf     [2*CC*CC];
__device__ float  g_u      [CC];
__device__ float  g_bias2  [CC];

// ---------------- helpers ------------------------------------------------------
__device__ __forceinline__ unsigned sptr(const void* p) {
    return (unsigned)__cvta_generic_to_shared(p);
}
__device__ __forceinline__ void ldmx4(unsigned* a, unsigned addr) {
    asm volatile("ldmatrix.sync.aligned.m8n8.x4.shared.b16 {%0,%1,%2,%3}, [%4];"
        : "=r"(a[0]), "=r"(a[1]), "=r"(a[2]), "=r"(a[3]) : "r"(addr));
}
__device__ __forceinline__ void ldmx2t(unsigned& b0, unsigned& b1, unsigned addr) {
    asm volatile("ldmatrix.sync.aligned.m8n8.x2.trans.shared.b16 {%0,%1}, [%2];"
        : "=r"(b0), "=r"(b1) : "r"(addr));
}
__device__ __forceinline__ void mma_h(float* c, const unsigned* a, unsigned b0, unsigned b1) {
    asm volatile("mma.sync.aligned.m16n8k16.row.col.f32.f16.f16.f32 "
        "{%0,%1,%2,%3}, {%4,%5,%6,%7}, {%8,%9}, {%0,%1,%2,%3};"
        : "+f"(c[0]), "+f"(c[1]), "+f"(c[2]), "+f"(c[3])
        : "r"(a[0]), "r"(a[1]), "r"(a[2]), "r"(a[3]), "r"(b0), "r"(b1));
}
__device__ __forceinline__ void split2(float x, float y, __half2& hi, __half2& lo) {
    hi = __floats2half2_rn(x, y);
    float2 hf = __half22float2(hi);
    lo = __floats2half2_rn(x - hf.x, y - hf.y);
}

// ---------------- unified fp16 tensor-core GEMM (BM=256, pre_pw only) ----------
__global__ void __launch_bounds__(512, 1)
gemm_h(const float* __restrict__ W, const float* __restrict__ bias,
       const float* __restrict__ X, const float* __restrict__ Xg,
       float* __restrict__ Y, __half* __restrict__ Yh,
       const float* __restrict__ addsrc,
       int invMode, int Cout, int Ntot, long xbstride)
{
    __shared__ __half Wh[2][256][24];
    __shared__ __half Xh[2][16][136];
    __shared__ float invs[128];
    __shared__ float4 part[16][32];

    int b  = blockIdx.z;
    int n0 = blockIdx.x * 128;
    int o0 = blockIdx.y * 256;
    const float* Xb  = X + (size_t)b * xbstride;
    const float* Xgb = Xg ? Xg + (size_t)b * xbstride : nullptr;
    float* Yb  = Y  ? Y  + (size_t)b * (size_t)Cout * Ntot : nullptr;
    __half* Yhb = Yh ? Yh + (size_t)b * (size_t)Cout * Ntot : nullptr;
    const float* Ab = addsrc ? addsrc + (size_t)b * (size_t)Cout * Ntot : nullptr;

    int tid = threadIdx.x;
    int lane = tid & 31, warp = tid >> 5;
    int wm = warp & 7, wn = warp >> 3;
    int group = lane >> 2, tid4 = lane & 3;

    int wm_ld = tid >> 2;
    int wkw   = tid & 3;
    int xk    = tid >> 5;
    int xn4   = (tid & 31) * 4;

    float acc[2][8][4];
    #pragma unroll
    for (int mt = 0; mt < 2; mt++)
        #pragma unroll
        for (int nt = 0; nt < 8; nt++)
            #pragma unroll
            for (int r = 0; r < 4; r++) acc[mt][nt][r] = 0.f;

    float4 ssq = make_float4(0.f, 0.f, 0.f, 0.f);
    float4 wreg0, wreg1, xreg;

    {
        const float* wp = W + (size_t)(o0 + wm_ld) * 256 + wkw * 4;
        wreg0 = *(const float4*)wp;
        wreg1 = *(const float4*)(wp + (size_t)128 * 256);
        xreg = *(const float4*)(Xb + (size_t)xk * Ntot + n0 + xn4);
        if (Xgb) {
            float4 g = *(const float4*)(Xgb + (size_t)xk * Ntot + n0 + xn4);
            xreg.x *= g.x / (1.f + __expf(-g.x));
            xreg.y *= g.y / (1.f + __expf(-g.y));
            xreg.z *= g.z / (1.f + __expf(-g.z));
            xreg.w *= g.w / (1.f + __expf(-g.w));
        }
        if (invMode) {
            ssq.x += xreg.x * xreg.x; ssq.y += xreg.y * xreg.y;
            ssq.z += xreg.z * xreg.z; ssq.w += xreg.w * xreg.w;
        }
    }

    #pragma unroll 1
    for (int kt = 0; kt < 16; kt++) {
        int buf = kt & 1;
        {
            __half2* wr0 = (__half2*)&Wh[buf][wm_ld][0];
            wr0[2 * wkw]     = __floats2half2_rn(wreg0.x, wreg0.y);
            wr0[2 * wkw + 1] = __floats2half2_rn(wreg0.z, wreg0.w);
            __half2* wr1 = (__half2*)&Wh[buf][128 + wm_ld][0];
            wr1[2 * wkw]     = __floats2half2_rn(wreg1.x, wreg1.y);
            wr1[2 * wkw + 1] = __floats2half2_rn(wreg1.z, wreg1.w);
            __half2* xr = (__half2*)&Xh[buf][xk][xn4];
            xr[0] = __floats2half2_rn(xreg.x, xreg.y);
            xr[1] = __floats2half2_rn(xreg.z, xreg.w);
        }
        __syncthreads();
        if (kt < 15) {
            int k0 = (kt + 1) * 16;
            const float* wp = W + (size_t)(o0 + wm_ld) * 256 + k0 + wkw * 4;
            wreg0 = *(const float4*)wp;
            wreg1 = *(const float4*)(wp + (size_t)128 * 256);
            xreg = *(const float4*)(Xb + (size_t)(k0 + xk) * Ntot + n0 + xn4);
            if (Xgb) {
                float4 g = *(const float4*)(Xgb + (size_t)(k0 + xk) * Ntot + n0 + xn4);
                xreg.x *= g.x / (1.f + __expf(-g.x));
                xreg.y *= g.y / (1.f + __expf(-g.y));
                xreg.z *= g.z / (1.f + __expf(-g.z));
                xreg.w *= g.w / (1.f + __expf(-g.w));
            }
            if (invMode) {
                ssq.x += xreg.x * xreg.x; ssq.y += xreg.y * xreg.y;
                ssq.z += xreg.z * xreg.z; ssq.w += xreg.w * xreg.w;
            }
        }
        unsigned a[2][4];
        #pragma unroll
        for (int mt = 0; mt < 2; mt++) {
            int row = wm * 32 + mt * 16 + (lane & 15);
            ldmx4(a[mt], sptr(&Wh[buf][row][(lane >> 4) * 8]));
        }
        #pragma unroll
        for (int nt = 0; nt < 8; nt++) {
            unsigned b0, b1;
            ldmx2t(b0, b1, sptr(&Xh[buf][lane & 15][wn * 64 + nt * 8]));
            mma_h(acc[0][nt], a[0], b0, b1);
            mma_h(acc[1][nt], a[1], b0, b1);
        }
    }

    if (invMode) {
        part[xk][tid & 31] = ssq;
        __syncthreads();
        if (tid < 32) {
            float4 s = part[0][tid];
            #pragma unroll
            for (int r = 1; r < 16; r++) {
                float4 p = part[r][tid];
                s.x += p.x; s.y += p.y; s.z += p.z; s.w += p.w;
            }
            invs[tid * 4 + 0] = rsqrtf(s.x * (1.f / CC) + EPSV);
            invs[tid * 4 + 1] = rsqrtf(s.y * (1.f / CC) + EPSV);
            invs[tid * 4 + 2] = rsqrtf(s.z * (1.f / CC) + EPSV);
            invs[tid * 4 + 3] = rsqrtf(s.w * (1.f / CC) + EPSV);
        }
        __syncthreads();
    }

    #pragma unroll
    for (int mt = 0; mt < 2; mt++) {
        int row = o0 + wm * 32 + mt * 16 + group;
        float bv0 = bias ? bias[row]     : 0.f;
        float bv8 = bias ? bias[row + 8] : 0.f;
        #pragma unroll
        for (int nt = 0; nt < 8; nt++) {
            int cl = wn * 64 + nt * 8 + tid4 * 2;
            int col = n0 + cl;
            size_t i0 = (size_t)row * Ntot + col;
            size_t i8 = (size_t)(row + 8) * Ntot + col;
            float a0 = acc[mt][nt][0], a1 = acc[mt][nt][1];
            float a2 = acc[mt][nt][2], a3 = acc[mt][nt][3];
            if (invMode) {
                float s0 = invs[cl], s1 = invs[cl + 1];
                a0 *= s0; a1 *= s1; a2 *= s0; a3 *= s1;
            }
            float2 v0 = make_float2(a0 + bv0, a1 + bv0);
            float2 v8 = make_float2(a2 + bv8, a3 + bv8);
            if (Ab) {
                float2 r0 = *(const float2*)(Ab + i0);
                float2 r8 = *(const float2*)(Ab + i8);
                v0.x += r0.x; v0.y += r0.y;
                v8.x += r8.x; v8.y += r8.y;
            }
            if (Yhb) {
                *(__half2*)(Yhb + i0) = __floats2half2_rn(v0.x, v0.y);
                *(__half2*)(Yhb + i8) = __floats2half2_rn(v8.x, v8.y);
            } else {
                *(float2*)(Yb + i0) = v0;
                *(float2*)(Yb + i8) = v8;
            }
        }
    }
}

// ------- 2-term split GEMM, BM=128, 256 threads, 2 CTAs/SM (NK GEMMs) -----------
__global__ void __launch_bounds__(256, 2)
gemm_hs2(const float* __restrict__ W, const float* __restrict__ bias,
         const float* __restrict__ X, const float* __restrict__ Xg,
         float* __restrict__ Y, const float* __restrict__ addsrc,
         int invMode, int Cout, int Ntot, long xbstride)
{
    __shared__ __half Whh[2][128][24];
    __shared__ __half Whl[2][128][24];
    __shared__ __half Xh[2][16][136];
    __shared__ float4 part[8][32];
    __shared__ float invs[128];

    int b  = blockIdx.z;
    int n0 = blockIdx.x * 128;
    int o0 = blockIdx.y * 128;
    const float* Xb  = X + (size_t)b * xbstride;
    const float* Xgb = Xg ? Xg + (size_t)b * xbstride : nullptr;
    float* Yb = Y + (size_t)b * (size_t)Cout * Ntot;
    const float* Ab = addsrc ? addsrc + (size_t)b * (size_t)Cout * Ntot : nullptr;

    int tid = threadIdx.x;
    int lane = tid & 31, warp = tid >> 5;
    int wm = warp & 3, wn = warp >> 2;      // 4 x 2 warp grid, warp tile 32x64
    int group = lane >> 2, tid4 = lane & 3;

    // load slots (2 per thread)
    int wrow0 = tid >> 1;                  // slot i=0: row, kw
    int wkw0  = (tid & 1) * 2;             // kw in float4 units: slots row=slot>>2, kw=slot&3
    // recompute generically below via slot arithmetic

    float acc[2][8][4];
    #pragma unroll
    for (int mt = 0; mt < 2; mt++)
        #pragma unroll
        for (int nt = 0; nt < 8; nt++)
            #pragma unroll
            for (int r = 0; r < 4; r++) acc[mt][nt][r] = 0.f;

    float4 ssq = make_float4(0.f, 0.f, 0.f, 0.f);
    float4 wreg[2], xreg[2];

    // prologue: tile 0
    #pragma unroll
    for (int i = 0; i < 2; i++) {
        int ws = i * 256 + tid;
        int wr = ws >> 2, wk = (ws & 3) * 4;
        wreg[i] = *(const float4*)(W + (size_t)(o0 + wr) * 256 + wk);
        int xs = i * 256 + tid;
        int xk = xs >> 5, xn = (xs & 31) * 4;
        float4 v = *(const float4*)(Xb + (size_t)xk * Ntot + n0 + xn);
        if (Xgb) {
            float4 g = *(const float4*)(Xgb + (size_t)xk * Ntot + n0 + xn);
            v.x *= g.x / (1.f + __expf(-g.x));
            v.y *= g.y / (1.f + __expf(-g.y));
            v.z *= g.z / (1.f + __expf(-g.z));
            v.w *= g.w / (1.f + __expf(-g.w));
        }
        if (invMode) {
            ssq.x += v.x*v.x; ssq.y += v.y*v.y; ssq.z += v.z*v.z; ssq.w += v.w*v.w;
        }
        xreg[i] = v;
    }

    #pragma unroll 1
    for (int kt = 0; kt < 16; kt++) {
        int buf = kt & 1;
        // store staged tile to smem
        #pragma unroll
        for (int i = 0; i < 2; i++) {
            int ws = i * 256 + tid;
            int wr = ws >> 2, wk = (ws & 3) * 2;    // __half2 index
            __half2 hi, lo;
            __half2* wh = (__half2*)&Whh[buf][wr][0];
            __half2* wl = (__half2*)&Whl[buf][wr][0];
            split2(wreg[i].x, wreg[i].y, hi, lo); wh[wk]   = hi; wl[wk]   = lo;
            split2(wreg[i].z, wreg[i].w, hi, lo); wh[wk+1] = hi; wl[wk+1] = lo;
            int xs = i * 256 + tid;
            int xk = xs >> 5, xn = (xs & 31) * 4;
            __half2* xr = (__half2*)&Xh[buf][xk][xn];
            xr[0] = __floats2half2_rn(xreg[i].x, xreg[i].y);
            xr[1] = __floats2half2_rn(xreg[i].z, xreg[i].w);
        }
        __syncthreads();
        // prefetch next tile
        if (kt < 15) {
            int k0 = (kt + 1) * 16;
            #pragma unroll
            for (int i = 0; i < 2; i++) {
                int ws = i * 256 + tid;
                int wr = ws >> 2, wk = (ws & 3) * 4;
                wreg[i] = *(const float4*)(W + (size_t)(o0 + wr) * 256 + k0 + wk);
                int xs = i * 256 + tid;
                int xk = xs >> 5, xn = (xs & 31) * 4;
                float4 v = *(const float4*)(Xb + (size_t)(k0 + xk) * Ntot + n0 + xn);
                if (Xgb) {
                    float4 g = *(const float4*)(Xgb + (size_t)(k0 + xk) * Ntot + n0 + xn);
                    v.x *= g.x / (1.f + __expf(-g.x));
                    v.y *= g.y / (1.f + __expf(-g.y));
                    v.z *= g.z / (1.f + __expf(-g.z));
                    v.w *= g.w / (1.f + __expf(-g.w));
                }
                if (invMode) {
                    ssq.x += v.x*v.x; ssq.y += v.y*v.y; ssq.z += v.z*v.z; ssq.w += v.w*v.w;
                }
                xreg[i] = v;
            }
        }
        // fragments + MMA
        unsigned ah[2][4], al[2][4];
        #pragma unroll
        for (int mt = 0; mt < 2; mt++) {
            int row = wm * 32 + mt * 16 + (lane & 15);
            ldmx4(ah[mt], sptr(&Whh[buf][row][(lane >> 4) * 8]));
            ldmx4(al[mt], sptr(&Whl[buf][row][(lane >> 4) * 8]));
        }
        #pragma unroll
        for (int nt = 0; nt < 8; nt++) {
            unsigned b0, b1;
            ldmx2t(b0, b1, sptr(&Xh[buf][lane & 15][wn * 64 + nt * 8]));
            mma_h(acc[0][nt], ah[0], b0, b1);
            mma_h(acc[0][nt], al[0], b0, b1);
            mma_h(acc[1][nt], ah[1], b0, b1);
            mma_h(acc[1][nt], al[1], b0, b1);
        }
    }

    if (invMode) {
        part[warp][lane] = ssq;
        __syncthreads();
        if (tid < 32) {
            float4 s = part[0][tid];
            #pragma unroll
            for (int r = 1; r < 8; r++) {
                float4 p = part[r][tid];
                s.x += p.x; s.y += p.y; s.z += p.z; s.w += p.w;
            }
            invs[tid * 4 + 0] = rsqrtf(s.x * (1.f / CC) + EPSV);
            invs[tid * 4 + 1] = rsqrtf(s.y * (1.f / CC) + EPSV);
            invs[tid * 4 + 2] = rsqrtf(s.z * (1.f / CC) + EPSV);
            invs[tid * 4 + 3] = rsqrtf(s.w * (1.f / CC) + EPSV);
        }
        __syncthreads();
    }

    #pragma unroll
    for (int mt = 0; mt < 2; mt++) {
        int row = o0 + wm * 32 + mt * 16 + group;
        float bv0 = bias ? bias[row]     : 0.f;
        float bv8 = bias ? bias[row + 8] : 0.f;
        #pragma unroll
        for (int nt = 0; nt < 8; nt++) {
            int cl = wn * 64 + nt * 8 + tid4 * 2;
            int col = n0 + cl;
            size_t i0 = (size_t)row * Ntot + col;
            size_t i8 = (size_t)(row + 8) * Ntot + col;
            float a0 = acc[mt][nt][0], a1 = acc[mt][nt][1];
            float a2 = acc[mt][nt][2], a3 = acc[mt][nt][3];
            if (invMode) {
                float s0 = invs[cl], s1 = invs[cl + 1];
                a0 *= s0; a1 *= s1; a2 *= s0; a3 *= s1;
            }
            float2 v0 = make_float2(a0 + bv0, a1 + bv0);
            float2 v8 = make_float2(a2 + bv8, a3 + bv8);
            if (Ab) {
                float2 r0 = *(const float2*)(Ab + i0);
                float2 r8 = *(const float2*)(Ab + i8);
                v0.x += r0.x; v0.y += r0.y;
                v8.x += r8.x; v8.y += r8.y;
            }
            *(float2*)(Yb + i0) = v0;
            *(float2*)(Yb + i8) = v8;
        }
    }
}

// ---------------- unified precompute kernel -------------------------------------
__global__ void prep_kernel(const float* __restrict__ pw, const float* __restrict__ pnw,
                            const float* __restrict__ fw, const float* __restrict__ fnw,
                            const float* __restrict__ kw, const float* __restrict__ qw,
                            const float* __restrict__ ow, const float* __restrict__ vw,
                            const float* __restrict__ qb, const float* __restrict__ kb,
                            const float* __restrict__ ob, const float* __restrict__ vb,
                            const float* __restrict__ basis)
{
    __shared__ float As[32][33], Bs[32][33];
    __shared__ float red[2][8];
    int blk = blockIdx.x;
    int tid = threadIdx.x;

    if (blk < 256) {
        int i = blk * 256 + tid;
        g_Wp[i] = pw[i] * pnw[i & 255];
    } else if (blk < 768) {
        int i = (blk - 256) * 256 + tid;
        g_Wf[i] = fw[i] * fnw[i & 255];
    } else if (blk < 896) {
        int bid = blk - 768;
        int mode = bid >> 6;
        int rem = bid & 63;
        int m0 = (rem >> 3) * 32, n0 = (rem & 7) * 32;
        int tx = tid & 15, ty = tid >> 4;
        const float* A = mode ? ow : kw;
        const float* B = mode ? vw : qw;
        float acc[2][2] = {{0.f,0.f},{0.f,0.f}};
        float aval[4], bval[4];
        #pragma unroll
        for (int i = 0; i < 4; i++) {
            int e = i * 256 + tid;
            int a = e >> 5, c = e & 31;
            bval[i] = B[(size_t)a * CC + n0 + c];
            aval[i] = mode ? A[(size_t)(m0 + a) * CC + c]
                           : A[(size_t)a * CC + m0 + c];
        }
        #pragma unroll 1
        for (int r0 = 0; r0 < CC; r0 += 32) {
            #pragma unroll
            for (int i = 0; i < 4; i++) {
                int e = i * 256 + tid;
                int a = e >> 5, c = e & 31;
                As[a][c] = aval[i];
                Bs[a][c] = bval[i];
            }
            __syncthreads();
            if (r0 + 32 < CC) {
                int r1 = r0 + 32;
                #pragma unroll
                for (int i = 0; i < 4; i++) {
                    int e = i * 256 + tid;
                    int a = e >> 5, c = e & 31;
                    bval[i] = B[(size_t)(r1 + a) * CC + n0 + c];
                    aval[i] = mode ? A[(size_t)(m0 + a) * CC + r1 + c]
                                   : A[(size_t)(r1 + a) * CC + m0 + c];
                }
            }
            if (mode) {
                #pragma unroll
                for (int r = 0; r < 32; r++) {
                    float a0 = As[ty*2][r], a1 = As[ty*2+1][r];
                    float b0 = Bs[r][tx*2], b1 = Bs[r][tx*2+1];
                    acc[0][0] += a0*b0; acc[0][1] += a0*b1;
                    acc[1][0] += a1*b0; acc[1][1] += a1*b1;
                }
            } else {
                #pragma unroll
                for (int r = 0; r < 32; r++) {
                    float a0 = As[r][ty*2], a1 = As[r][ty*2+1];
                    float b0 = Bs[r][tx*2], b1 = Bs[r][tx*2+1];
                    acc[0][0] += a0*b0; acc[0][1] += a0*b1;
                    acc[1][0] += a1*b0; acc[1][1] += a1*b1;
                }
            }
            __syncthreads();
        }
        float* C = mode ? g_OV : g_P;
        #pragma unroll
        for (int i = 0; i < 2; i++)
            #pragma unroll
            for (int j = 0; j < 2; j++)
                C[(size_t)(m0 + ty*2 + i) * CC + n0 + tx*2 + j] = acc[i][j];
    } else if (blk < 1152) {               // u / bias2
        int j = blk - 896;
        int o = tid;
        float su = qb[o] * kw[(size_t)o * CC + j];
        float sb = ow[(size_t)j * CC + o] * vb[o];
        #pragma unroll
        for (int d = 16; d; d >>= 1) {
            su += __shfl_xor_sync(0xffffffffu, su, d);
            sb += __shfl_xor_sync(0xffffffffu, sb, d);
        }
        if ((o & 31) == 0) {
            int w = o >> 5;
            red[0][w] = su; red[1][w] = sb;
        }
        __syncthreads();
        if (o == 0) {
            float a = 0.f, c = 0.f;
            #pragma unroll
            for (int i = 0; i < 8; i++) { a += red[0][i]; c += red[1][i]; }
            g_u[j] = a;
            g_bias2[j] = c + ob[j];
        }
    } else {
        int idx = (blk - 1152) * 256 + tid;
        if (idx < 256 * 40) {
            int f = idx / 40, k = idx % 40;
            g_basish[idx] = (k < 32) ? __float2half(basis[(size_t)k * 256 + f])
                                     : __float2half(0.f);
        }
    }
}

// ------- depthwise 3x3 causal conv + SiLU + fused qseed MMA ----------------------
#define TB 16
__global__ void __launch_bounds__(256)
dwconv_qseed(const __half* __restrict__ src,
             const float* __restrict__ dww, const float* __restrict__ dwb,
             float* __restrict__ emb, __half* __restrict__ embh,
             const __half* __restrict__ basish, float* __restrict__ Y)
{
    __shared__ float rows[TB + 2][FF + 2];
    __shared__ __half As[TB][264];
    __shared__ __half Bh[256 * 40];
    int nblk = TT / TB;
    long idx = blockIdx.x;
    int tb = (int)(idx % nblk);
    long bc = idx / nblk;
    int c = (int)(bc % CC);
    int t0 = tb * TB;
    int f = threadIdx.x;
    int lane = f & 31, warp = f >> 5;
    size_t chbase = (size_t)bc * TT * FF;

    {
        const uint4* bsrc = (const uint4*)basish;
        uint4* bdst = (uint4*)Bh;
        #pragma unroll
        for (int i = 0; i < 5; i++) {
            int e = i * 256 + f;
            if (e < 1280) bdst[e] = bsrc[e];
        }
    }
    #pragma unroll
    for (int r = 0; r < TB + 2; r++) {
        int tt = t0 - 2 + r;
        rows[r][f + 1] = (tt >= 0) ? __half2float(src[chbase + (size_t)tt * FF + f]) : 0.f;
        if (f == 0) { rows[r][0] = 0.f; rows[r][FF + 1] = 0.f; }
    }
    __syncthreads();
    float w[9];
    #pragma unroll
    for (int i = 0; i < 9; i++) w[i] = dww[c * 9 + i];
    float bv = dwb[c];
    #pragma unroll
    for (int r = 0; r < TB; r++) {
        float s = bv;
        #pragma unroll
        for (int dt = 0; dt < 3; dt++)
            #pragma unroll
            for (int df = 0; df < 3; df++)
                s += w[dt * 3 + df] * rows[r + dt][f + df];
        s = s / (1.f + __expf(-s));
        __half h = __float2half(s);
        emb [chbase + (size_t)(t0 + r) * FF + f] = s;
        embh[chbase + (size_t)(t0 + r) * FF + f] = h;
        As[r][f] = h;
    }
    __syncthreads();

    if (warp < 4) {
        float acc[4] = {0.f, 0.f, 0.f, 0.f};
        #pragma unroll
        for (int ks = 0; ks < 16; ks++) {
            unsigned a[4];
            ldmx4(a, sptr(&As[lane & 15][ks * 16 + (lane >> 4) * 8]));
            unsigned b0, b1;
            ldmx2t(b0, b1, sptr(&Bh[(ks * 16 + (lane & 15)) * 40 + warp * 8]));
            mma_h(acc, a, b0, b1);
        }
        int group = lane >> 2, tid4 = lane & 3;
        int col = warp * 8 + tid4 * 2;
        long rbase = bc * TT + t0;
        *(float2*)(Y + (rbase + group) * 32 + col)     = make_float2(acc[0], acc[1]);
        *(float2*)(Y + (rbase + group + 8) * 32 + col) = make_float2(acc[2], acc[3]);
    }
}

// ---------------- fused attention (512 threads): scores + softmax + pooled ------
#define ATTN_SMEM (256*264*2 + 34848 + 256*40*2)
__global__ void __launch_bounds__(512, 1)
attn_mma_kernel(const float* __restrict__ Q2, const __half* __restrict__ embh,
                const float* __restrict__ rb,
                const float* __restrict__ ssp, const float* __restrict__ psp,
                float* __restrict__ pooled)
{
    extern __shared__ __align__(16) char sm_[];
    __half* Eh = (__half*)sm_;
    char* regU = sm_ + 256 * 264 * 2;
    __half* q2T = (__half*)regU;
    float* scoresF = (float*)regU;
    float* poolSm = (float*)regU;
    __half* Wt = (__half*)(regU + 34848);

    int bt = blockIdx.x;
    int b = bt / TT, t = bt % TT;
    size_t qframe = ((size_t)b * CC * TT + t) * KK;
    size_t eframe = ((size_t)b * CC * TT + t) * FF;
    int tid = threadIdx.x;
    int lane = tid & 31, warp = tid >> 5;
    int group = lane >> 2, tid4 = lane & 3;

    #pragma unroll 8
    for (int i = 0; i < 16; i++) {
        int e = i * 512 + tid;
        int c = e >> 5, f8 = e & 31;
        *(uint4*)&Eh[c * 264 + f8 * 8] =
            *(const uint4*)(embh + eframe + (size_t)c * TT * FF + f8 * 8);
    }
    for (int e = tid; e < 16 * 264; e += 512)
        q2T[32 * 264 + e] = __float2half(0.f);
    if (tid < 256) q2T[32 * 264 + tid] = __float2half(g_u[tid]);
    #pragma unroll
    for (int i = 0; i < 4; i++) {
        int e = i * 512 + tid;
        int c = e >> 3, j = e & 7;
        float4 v = *(const float4*)(Q2 + qframe + (size_t)c * TT * KK + j * 4);
        q2T[(4*j + 0) * 264 + c] = __float2half(v.x);
        q2T[(4*j + 1) * 264 + c] = __float2half(v.y);
        q2T[(4*j + 2) * 264 + c] = __float2half(v.z);
        q2T[(4*j + 3) * 264 + c] = __float2half(v.w);
    }
    __syncthreads();

    float acc1[3][2][4];
    #pragma unroll
    for (int mt = 0; mt < 3; mt++)
        #pragma unroll
        for (int nt = 0; nt < 2; nt++)
            #pragma unroll
            for (int r = 0; r < 4; r++) acc1[mt][nt][r] = 0.f;

    #pragma unroll 1
    for (int ks = 0; ks < 256; ks += 16) {
        unsigned a[3][4];
        #pragma unroll
        for (int mt = 0; mt < 3; mt++)
            ldmx4(a[mt], sptr(&q2T[(mt * 16 + (lane & 15)) * 264 + ks + (lane >> 4) * 8]));
        #pragma unroll
        for (int nt = 0; nt < 2; nt++) {
            unsigned b0, b1;
            ldmx2t(b0, b1, sptr(&Eh[(ks + (lane & 15)) * 264 + warp * 16 + nt * 8]));
            mma_h(acc1[0][nt], a[0], b0, b1);
            mma_h(acc1[1][nt], a[1], b0, b1);
            mma_h(acc1[2][nt], a[2], b0, b1);
        }
    }
    __syncthreads();

    #pragma unroll
    for (int mt = 0; mt < 2; mt++)
        #pragma unroll
        for (int nt = 0; nt < 2; nt++) {
            int row = mt * 16 + group;
            int col = warp * 16 + nt * 8 + tid4 * 2;
            *(float2*)&scoresF[row * 264 + col]       = make_float2(acc1[mt][nt][0], acc1[mt][nt][1]);
            *(float2*)&scoresF[(row + 8) * 264 + col] = make_float2(acc1[mt][nt][2], acc1[mt][nt][3]);
        }
    if (group == 0) {
        #pragma unroll
        for (int nt = 0; nt < 2; nt++) {
            int col = warp * 16 + nt * 8 + tid4 * 2;
            *(float2*)&scoresF[32 * 264 + col] = make_float2(acc1[2][nt][0], acc1[2][nt][1]);
        }
    }
    __syncthreads();

    float ss = *ssp, ps = *psp;
    #pragma unroll
    for (int rr = 0; rr < 2; rr++) {
        int k = warp * 2 + rr;
        float v[8];
        float m = -1e30f;
        #pragma unroll
        for (int i = 0; i < 8; i++) {
            int f = lane + 32 * i;
            float raw = scoresF[k * 264 + f];
            float uu  = scoresF[32 * 264 + f];
            v[i] = ss * (raw + uu) + rb[k * FF + f] * ps;
            m = fmaxf(m, v[i]);
        }
        #pragma unroll
        for (int o = 16; o; o >>= 1) m = fmaxf(m, __shfl_xor_sync(0xffffffffu, m, o));
        float s = 0.f;
        #pragma unroll
        for (int i = 0; i < 8; i++) { v[i] = __expf(v[i] - m); s += v[i]; }
        #pragma unroll
        for (int o = 16; o; o >>= 1) s += __shfl_xor_sync(0xffffffffu, s, o);
        float inv = 1.f / s;
        #pragma unroll
        for (int i = 0; i < 8; i++) {
            int f = lane + 32 * i;
            Wt[f * 40 + k] = __float2half(v[i] * inv);
        }
    }
    __syncthreads();

    float acc2[4][4];
    #pragma unroll
    for (int nt = 0; nt < 4; nt++)
        #pragma unroll
        for (int r = 0; r < 4; r++) acc2[nt][r] = 0.f;

    #pragma unroll 1
    for (int fs = 0; fs < 256; fs += 16) {
        unsigned a[4];
        ldmx4(a, sptr(&Eh[(warp * 16 + (lane & 15)) * 264 + fs + (lane >> 4) * 8]));
        #pragma unroll
        for (int nt = 0; nt < 4; nt++) {
            unsigned b0, b1;
            ldmx2t(b0, b1, sptr(&Wt[(fs + (lane & 15)) * 40 + nt * 8]));
            mma_h(acc2[nt], a, b0, b1);
        }
    }
    __syncthreads();

    #pragma unroll
    for (int nt = 0; nt < 4; nt++) {
        int row = warp * 16 + group;
        int col = nt * 8 + tid4 * 2;
        *(float2*)&poolSm[row * 34 + col]       = make_float2(acc2[nt][0], acc2[nt][1]);
        *(float2*)&poolSm[(row + 8) * 34 + col] = make_float2(acc2[nt][2], acc2[nt][3]);
    }
    __syncthreads();
    #pragma unroll
    for (int i = 0; i < 16; i++) {
        int e = i * 512 + tid;
        int c = e >> 5, k = e & 31;
        pooled[qframe + (size_t)c * TT * KK + k] = poolSm[c * 34 + k];
    }
}

// ---------------- host launcher --------------------------------------------------
extern "C" void kernel_launch(void* const* d_in, const int* in_sizes, int n_in,
                              void* d_out, int out_size) {
    const float* x          = (const float*)d_in[0];
    const float* pre_norm_w = (const float*)d_in[1];
    const float* pre_pw_w   = (const float*)d_in[2];
    const float* pre_pw_b   = (const float*)d_in[3];
    const float* pre_dw_w   = (const float*)d_in[4];
    const float* pre_dw_b   = (const float*)d_in[5];
    const float* q_w        = (const float*)d_in[6];
    const float* q_b        = (const float*)d_in[7];
    const float* k_w        = (const float*)d_in[8];
    const float* k_b        = (const float*)d_in[9];
    const float* v_w        = (const float*)d_in[10];
    const float* v_b        = (const float*)d_in[11];
    const float* out_w      = (const float*)d_in[12];
    const float* out_b      = (const float*)d_in[13];
    const float* ffn_norm_w = (const float*)d_in[14];
    const float* ffn_in_w   = (const float*)d_in[15];
    const float* ffn_in_b   = (const float*)d_in[16];
    const float* ffn_out_w  = (const float*)d_in[17];
    const float* ffn_out_b  = (const float*)d_in[18];
    const float* score_scale= (const float*)d_in[19];
    const float* prior_scale= (const float*)d_in[20];
    const float* query_basis= (const float*)d_in[21];
    const float* routing_bias=(const float*)d_in[22];

    float* out        = (float*)d_out;
    float* out_hidden = out;
    float* out_emb    = out + (size_t)BB * CC * TT * KK;

    float *emb0, *qseed, *q2, *pooled, *hidden, *hffn;
    float *P, *OV, *Wp, *Wf, *bias2;
    __half *embh, *basish;
    cudaGetSymbolAddress((void**)&emb0,   g_emb0);
    cudaGetSymbolAddress((void**)&embh,   g_embh);
    cudaGetSymbolAddress((void**)&basish, g_basish);
    cudaGetSymbolAddress((void**)&qseed,  g_qseed);
    cudaGetSymbolAddress((void**)&q2,     g_q2);
    cudaGetSymbolAddress((void**)&pooled, g_pooled);
    cudaGetSymbolAddress((void**)&hidden, g_hidden);
    cudaGetSymbolAddress((void**)&hffn,   g_hffn);
    cudaGetSymbolAddress((void**)&P,      g_P);
    cudaGetSymbolAddress((void**)&OV,     g_OV);
    cudaGetSymbolAddress((void**)&Wp,     g_Wp);
    cudaGetSymbolAddress((void**)&Wf,     g_Wf);
    cudaGetSymbolAddress((void**)&bias2,  g_bias2);

    cudaFuncSetAttribute(attn_mma_kernel,
                         cudaFuncAttributeMaxDynamicSharedMemorySize, ATTN_SMEM);

    const int NBT = BB * TT;       // 800
    const int NF  = TT * FF;       // 102400
    const int NK  = TT * KK;       // 12800

    // 0. unified precompute
    prep_kernel<<<1192, 256>>>(pre_pw_w, pre_norm_w, ffn_in_w, ffn_norm_w,
                               k_w, q_w, out_w, v_w,
                               q_b, k_b, out_b, v_b, query_basis);

    // 1. pre pw with fused RMSNorm -> emb0 (fp16 storage)
    gemm_h<<<dim3(NF/128, 1, BB), 512>>>(Wp, pre_pw_b, x, nullptr,
                                         nullptr, (__half*)emb0, nullptr,
                                         1, CC, NF, (long)CC * NF);
    // 2. depthwise conv + SiLU -> emb (fp32), embh (fp16), qseed (fused MMA)
    dwconv_qseed<<<(long)BB*CC*(TT/TB), 256>>>((const __half*)emb0, pre_dw_w, pre_dw_b,
                                               out_emb, embh, basish, qseed);
    // 3. q2 = P @ qseed   [BM=128, 2 CTAs/SM]
    gemm_hs2<<<dim3(NK/128, 2, BB), 256>>>(P, nullptr, qseed, nullptr, q2, nullptr,
                                           0, CC, NK, (long)CC * NK);
    // 4. fused attention
    attn_mma_kernel<<<NBT, 512, ATTN_SMEM>>>(q2, embh, routing_bias,
                                             score_scale, prior_scale, pooled);
    // 5. hidden = OV @ pooled + bias2
    gemm_hs2<<<dim3(NK/128, 2, BB), 256>>>(OV, bias2, pooled, nullptr, hidden, nullptr,
                                           0, CC, NK, (long)CC * NK);
    // 6. ffn_in with fused RMSNorm
    gemm_hs2<<<dim3(NK/128, 4, BB), 256>>>(Wf, ffn_in_b, hidden, nullptr, hffn, nullptr,
                                           1, 2*CC, NK, (long)CC * NK);
    // 7. ffn_out with fused GLU load + residual -> d_out
    gemm_hs2<<<dim3(NK/128, 2, BB), 256>>>(ffn_out_w, ffn_out_b, hffn,
                                           hffn + (size_t)CC * NK,
                                           out_hidden, hidden,
                                           0, CC, NK, (long)2 * CC * NK);
}

// round 16
// speedup vs baseline: 1.1924x; 1.0282x over previous
#include <cuda_runtime.h>
#include <cuda_fp16.h>
#include <math.h>

#define BB 2
#define CC 256
#define TT 400
#define FF 256
#define KK 32
#define EPSV 1e-6f

typedef unsigned long long ull;

// ---------------- scratch ------------------------------------------------------
__device__ float  g_emb0   [(size_t)BB*CC*TT*FF];   // used as fp16 (half the space)
__device__ __half g_embh   [(size_t)BB*CC*TT*FF];   // fp16 copy of emb
__device__ __half g_basish [256*40];                // basis transposed fp16 [f][40]
__device__ float  g_qseed  [(size_t)BB*CC*TT*KK];
__device__ float  g_q2     [(size_t)BB*CC*TT*KK];
__device__ float  g_pooled [(size_t)BB*CC*TT*KK];
__device__ float  g_hidden [(size_t)BB*CC*TT*KK];
__device__ float  g_hffn   [(size_t)BB*2*CC*TT*KK];
__device__ float  g_P      [CC*CC];
__device__ float  g_OV     [CC*CC];
__device__ float  g_Wp     [CC*CC];
__device__ float  g_Wf     [2*CC*CC];
__device__ float  g_u      [CC];
__device__ float  g_bias2  [CC];

// ---------------- helpers ------------------------------------------------------
__device__ __forceinline__ unsigned sptr(const void* p) {
    return (unsigned)__cvta_generic_to_shared(p);
}
__device__ __forceinline__ void ldmx4(unsigned* a, unsigned addr) {
    asm volatile("ldmatrix.sync.aligned.m8n8.x4.shared.b16 {%0,%1,%2,%3}, [%4];"
        : "=r"(a[0]), "=r"(a[1]), "=r"(a[2]), "=r"(a[3]) : "r"(addr));
}
__device__ __forceinline__ void ldmx2t(unsigned& b0, unsigned& b1, unsigned addr) {
    asm volatile("ldmatrix.sync.aligned.m8n8.x2.trans.shared.b16 {%0,%1}, [%2];"
        : "=r"(b0), "=r"(b1) : "r"(addr));
}
__device__ __forceinline__ void mma_h(float* c, const unsigned* a, unsigned b0, unsigned b1) {
    asm volatile("mma.sync.aligned.m16n8k16.row.col.f32.f16.f16.f32 "
        "{%0,%1,%2,%3}, {%4,%5,%6,%7}, {%8,%9}, {%0,%1,%2,%3};"
        : "+f"(c[0]), "+f"(c[1]), "+f"(c[2]), "+f"(c[3])
        : "r"(a[0]), "r"(a[1]), "r"(a[2]), "r"(a[3]), "r"(b0), "r"(b1));
}
__device__ __forceinline__ void split2(float x, float y, __half2& hi, __half2& lo) {
    hi = __floats2half2_rn(x, y);
    float2 hf = __half22float2(hi);
    lo = __floats2half2_rn(x - hf.x, y - hf.y);
}

// ------- plain fp16 GEMM, BM=128, 256 threads, 2 CTAs/SM (pre_pw) ---------------
// Y = (W @ Xeff) [* invrms[n]] + bias; fp16 or fp32 out
__global__ void __launch_bounds__(256, 2)
gemm_h2(const float* __restrict__ W, const float* __restrict__ bias,
        const float* __restrict__ X, float* __restrict__ Y, __half* __restrict__ Yh,
        int invMode, int Cout, int Ntot, long xbstride)
{
    __shared__ __half Wh[2][128][24];
    __shared__ __half Xh[2][16][136];
    __shared__ float4 part[8][32];
    __shared__ float invs[128];

    int b  = blockIdx.z;
    int n0 = blockIdx.x * 128;
    int o0 = blockIdx.y * 128;
    const float* Xb = X + (size_t)b * xbstride;
    float* Yb   = Y  ? Y  + (size_t)b * (size_t)Cout * Ntot : nullptr;
    __half* Yhb = Yh ? Yh + (size_t)b * (size_t)Cout * Ntot : nullptr;

    int tid = threadIdx.x;
    int lane = tid & 31, warp = tid >> 5;
    int wm = warp & 3, wn = warp >> 2;
    int group = lane >> 2, tid4 = lane & 3;

    float acc[2][8][4];
    #pragma unroll
    for (int mt = 0; mt < 2; mt++)
        #pragma unroll
        for (int nt = 0; nt < 8; nt++)
            #pragma unroll
            for (int r = 0; r < 4; r++) acc[mt][nt][r] = 0.f;

    float4 ssq = make_float4(0.f, 0.f, 0.f, 0.f);
    float4 wreg[2], xreg[2];

    #pragma unroll
    for (int i = 0; i < 2; i++) {
        int ws = i * 256 + tid;
        int wr = ws >> 2, wk = (ws & 3) * 4;
        wreg[i] = *(const float4*)(W + (size_t)(o0 + wr) * 256 + wk);
        int xs = i * 256 + tid;
        int xk = xs >> 5, xn = (xs & 31) * 4;
        float4 v = *(const float4*)(Xb + (size_t)xk * Ntot + n0 + xn);
        if (invMode) {
            ssq.x += v.x*v.x; ssq.y += v.y*v.y; ssq.z += v.z*v.z; ssq.w += v.w*v.w;
        }
        xreg[i] = v;
    }

    #pragma unroll 1
    for (int kt = 0; kt < 16; kt++) {
        int buf = kt & 1;
        #pragma unroll
        for (int i = 0; i < 2; i++) {
            int ws = i * 256 + tid;
            int wr = ws >> 2, wk = (ws & 3) * 2;
            __half2* wh = (__half2*)&Wh[buf][wr][0];
            wh[wk]   = __floats2half2_rn(wreg[i].x, wreg[i].y);
            wh[wk+1] = __floats2half2_rn(wreg[i].z, wreg[i].w);
            int xs = i * 256 + tid;
            int xk = xs >> 5, xn = (xs & 31) * 4;
            __half2* xr = (__half2*)&Xh[buf][xk][xn];
            xr[0] = __floats2half2_rn(xreg[i].x, xreg[i].y);
            xr[1] = __floats2half2_rn(xreg[i].z, xreg[i].w);
        }
        __syncthreads();
        if (kt < 15) {
            int k0 = (kt + 1) * 16;
            #pragma unroll
            for (int i = 0; i < 2; i++) {
                int ws = i * 256 + tid;
                int wr = ws >> 2, wk = (ws & 3) * 4;
                wreg[i] = *(const float4*)(W + (size_t)(o0 + wr) * 256 + k0 + wk);
                int xs = i * 256 + tid;
                int xk = xs >> 5, xn = (xs & 31) * 4;
                float4 v = *(const float4*)(Xb + (size_t)(k0 + xk) * Ntot + n0 + xn);
                if (invMode) {
                    ssq.x += v.x*v.x; ssq.y += v.y*v.y; ssq.z += v.z*v.z; ssq.w += v.w*v.w;
                }
                xreg[i] = v;
            }
        }
        unsigned a[2][4];
        #pragma unroll
        for (int mt = 0; mt < 2; mt++) {
            int row = wm * 32 + mt * 16 + (lane & 15);
            ldmx4(a[mt], sptr(&Wh[buf][row][(lane >> 4) * 8]));
        }
        #pragma unroll
        for (int nt = 0; nt < 8; nt++) {
            unsigned b0, b1;
            ldmx2t(b0, b1, sptr(&Xh[buf][lane & 15][wn * 64 + nt * 8]));
            mma_h(acc[0][nt], a[0], b0, b1);
            mma_h(acc[1][nt], a[1], b0, b1);
        }
    }

    if (invMode) {
        part[warp][lane] = ssq;
        __syncthreads();
        if (tid < 32) {
            float4 s = part[0][tid];
            #pragma unroll
            for (int r = 1; r < 8; r++) {
                float4 p = part[r][tid];
                s.x += p.x; s.y += p.y; s.z += p.z; s.w += p.w;
            }
            invs[tid * 4 + 0] = rsqrtf(s.x * (1.f / CC) + EPSV);
            invs[tid * 4 + 1] = rsqrtf(s.y * (1.f / CC) + EPSV);
            invs[tid * 4 + 2] = rsqrtf(s.z * (1.f / CC) + EPSV);
            invs[tid * 4 + 3] = rsqrtf(s.w * (1.f / CC) + EPSV);
        }
        __syncthreads();
    }

    #pragma unroll
    for (int mt = 0; mt < 2; mt++) {
        int row = o0 + wm * 32 + mt * 16 + group;
        float bv0 = bias ? bias[row]     : 0.f;
        float bv8 = bias ? bias[row + 8] : 0.f;
        #pragma unroll
        for (int nt = 0; nt < 8; nt++) {
            int cl = wn * 64 + nt * 8 + tid4 * 2;
            int col = n0 + cl;
            size_t i0 = (size_t)row * Ntot + col;
            size_t i8 = (size_t)(row + 8) * Ntot + col;
            float a0 = acc[mt][nt][0], a1 = acc[mt][nt][1];
            float a2 = acc[mt][nt][2], a3 = acc[mt][nt][3];
            if (invMode) {
                float s0 = invs[cl], s1 = invs[cl + 1];
                a0 *= s0; a1 *= s1; a2 *= s0; a3 *= s1;
            }
            float2 v0 = make_float2(a0 + bv0, a1 + bv0);
            float2 v8 = make_float2(a2 + bv8, a3 + bv8);
            if (Yhb) {
                *(__half2*)(Yhb + i0) = __floats2half2_rn(v0.x, v0.y);
                *(__half2*)(Yhb + i8) = __floats2half2_rn(v8.x, v8.y);
            } else {
                *(float2*)(Yb + i0) = v0;
                *(float2*)(Yb + i8) = v8;
            }
        }
    }
}

// ------- 2-term split GEMM, BM=128, 256 threads, 2 CTAs/SM (NK GEMMs) -----------
__global__ void __launch_bounds__(256, 2)
gemm_hs2(const float* __restrict__ W, const float* __restrict__ bias,
         const float* __restrict__ X, const float* __restrict__ Xg,
         float* __restrict__ Y, const float* __restrict__ addsrc,
         int invMode, int Cout, int Ntot, long xbstride)
{
    __shared__ __half Whh[2][128][24];
    __shared__ __half Whl[2][128][24];
    __shared__ __half Xh[2][16][136];
    __shared__ float4 part[8][32];
    __shared__ float invs[128];

    int b  = blockIdx.z;
    int n0 = blockIdx.x * 128;
    int o0 = blockIdx.y * 128;
    const float* Xb  = X + (size_t)b * xbstride;
    const float* Xgb = Xg ? Xg + (size_t)b * xbstride : nullptr;
    float* Yb = Y + (size_t)b * (size_t)Cout * Ntot;
    const float* Ab = addsrc ? addsrc + (size_t)b * (size_t)Cout * Ntot : nullptr;

    int tid = threadIdx.x;
    int lane = tid & 31, warp = tid >> 5;
    int wm = warp & 3, wn = warp >> 2;
    int group = lane >> 2, tid4 = lane & 3;

    float acc[2][8][4];
    #pragma unroll
    for (int mt = 0; mt < 2; mt++)
        #pragma unroll
        for (int nt = 0; nt < 8; nt++)
            #pragma unroll
            for (int r = 0; r < 4; r++) acc[mt][nt][r] = 0.f;

    float4 ssq = make_float4(0.f, 0.f, 0.f, 0.f);
    float4 wreg[2], xreg[2];

    #pragma unroll
    for (int i = 0; i < 2; i++) {
        int ws = i * 256 + tid;
        int wr = ws >> 2, wk = (ws & 3) * 4;
        wreg[i] = *(const float4*)(W + (size_t)(o0 + wr) * 256 + wk);
        int xs = i * 256 + tid;
        int xk = xs >> 5, xn = (xs & 31) * 4;
        float4 v = *(const float4*)(Xb + (size_t)xk * Ntot + n0 + xn);
        if (Xgb) {
            float4 g = *(const float4*)(Xgb + (size_t)xk * Ntot + n0 + xn);
            v.x *= g.x / (1.f + __expf(-g.x));
            v.y *= g.y / (1.f + __expf(-g.y));
            v.z *= g.z / (1.f + __expf(-g.z));
            v.w *= g.w / (1.f + __expf(-g.w));
        }
        if (invMode) {
            ssq.x += v.x*v.x; ssq.y += v.y*v.y; ssq.z += v.z*v.z; ssq.w += v.w*v.w;
        }
        xreg[i] = v;
    }

    #pragma unroll 1
    for (int kt = 0; kt < 16; kt++) {
        int buf = kt & 1;
        #pragma unroll
        for (int i = 0; i < 2; i++) {
            int ws = i * 256 + tid;
            int wr = ws >> 2, wk = (ws & 3) * 2;
            __half2 hi, lo;
            __half2* wh = (__half2*)&Whh[buf][wr][0];
            __half2* wl = (__half2*)&Whl[buf][wr][0];
            split2(wreg[i].x, wreg[i].y, hi, lo); wh[wk]   = hi; wl[wk]   = lo;
            split2(wreg[i].z, wreg[i].w, hi, lo); wh[wk+1] = hi; wl[wk+1] = lo;
            int xs = i * 256 + tid;
            int xk = xs >> 5, xn = (xs & 31) * 4;
            __half2* xr = (__half2*)&Xh[buf][xk][xn];
            xr[0] = __floats2half2_rn(xreg[i].x, xreg[i].y);
            xr[1] = __floats2half2_rn(xreg[i].z, xreg[i].w);
        }
        __syncthreads();
        if (kt < 15) {
            int k0 = (kt + 1) * 16;
            #pragma unroll
            for (int i = 0; i < 2; i++) {
                int ws = i * 256 + tid;
                int wr = ws >> 2, wk = (ws & 3) * 4;
                wreg[i] = *(const float4*)(W + (size_t)(o0 + wr) * 256 + k0 + wk);
                int xs = i * 256 + tid;
                int xk = xs >> 5, xn = (xs & 31) * 4;
                float4 v = *(const float4*)(Xb + (size_t)(k0 + xk) * Ntot + n0 + xn);
                if (Xgb) {
                    float4 g = *(const float4*)(Xgb + (size_t)(k0 + xk) * Ntot + n0 + xn);
                    v.x *= g.x / (1.f + __expf(-g.x));
                    v.y *= g.y / (1.f + __expf(-g.y));
                    v.z *= g.z / (1.f + __expf(-g.z));
                    v.w *= g.w / (1.f + __expf(-g.w));
                }
                if (invMode) {
                    ssq.x += v.x*v.x; ssq.y += v.y*v.y; ssq.z += v.z*v.z; ssq.w += v.w*v.w;
                }
                xreg[i] = v;
            }
        }
        unsigned ah[2][4], al[2][4];
        #pragma unroll
        for (int mt = 0; mt < 2; mt++) {
            int row = wm * 32 + mt * 16 + (lane & 15);
            ldmx4(ah[mt], sptr(&Whh[buf][row][(lane >> 4) * 8]));
            ldmx4(al[mt], sptr(&Whl[buf][row][(lane >> 4) * 8]));
        }
        #pragma unroll
        for (int nt = 0; nt < 8; nt++) {
            unsigned b0, b1;
            ldmx2t(b0, b1, sptr(&Xh[buf][lane & 15][wn * 64 + nt * 8]));
            mma_h(acc[0][nt], ah[0], b0, b1);
            mma_h(acc[0][nt], al[0], b0, b1);
            mma_h(acc[1][nt], ah[1], b0, b1);
            mma_h(acc[1][nt], al[1], b0, b1);
        }
    }

    if (invMode) {
        part[warp][lane] = ssq;
        __syncthreads();
        if (tid < 32) {
            float4 s = part[0][tid];
            #pragma unroll
            for (int r = 1; r < 8; r++) {
                float4 p = part[r][tid];
                s.x += p.x; s.y += p.y; s.z += p.z; s.w += p.w;
            }
            invs[tid * 4 + 0] = rsqrtf(s.x * (1.f / CC) + EPSV);
            invs[tid * 4 + 1] = rsqrtf(s.y * (1.f / CC) + EPSV);
            invs[tid * 4 + 2] = rsqrtf(s.z * (1.f / CC) + EPSV);
            invs[tid * 4 + 3] = rsqrtf(s.w * (1.f / CC) + EPSV);
        }
        __syncthreads();
    }

    #pragma unroll
    for (int mt = 0; mt < 2; mt++) {
        int row = o0 + wm * 32 + mt * 16 + group;
        float bv0 = bias ? bias[row]     : 0.f;
        float bv8 = bias ? bias[row + 8] : 0.f;
        #pragma unroll
        for (int nt = 0; nt < 8; nt++) {
            int cl = wn * 64 + nt * 8 + tid4 * 2;
            int col = n0 + cl;
            size_t i0 = (size_t)row * Ntot + col;
            size_t i8 = (size_t)(row + 8) * Ntot + col;
            float a0 = acc[mt][nt][0], a1 = acc[mt][nt][1];
            float a2 = acc[mt][nt][2], a3 = acc[mt][nt][3];
            if (invMode) {
                float s0 = invs[cl], s1 = invs[cl + 1];
                a0 *= s0; a1 *= s1; a2 *= s0; a3 *= s1;
            }
            float2 v0 = make_float2(a0 + bv0, a1 + bv0);
            float2 v8 = make_float2(a2 + bv8, a3 + bv8);
            if (Ab) {
                float2 r0 = *(const float2*)(Ab + i0);
                float2 r8 = *(const float2*)(Ab + i8);
                v0.x += r0.x; v0.y += r0.y;
                v8.x += r8.x; v8.y += r8.y;
            }
            *(float2*)(Yb + i0) = v0;
            *(float2*)(Yb + i8) = v8;
        }
    }
}

// ---------------- unified precompute kernel -------------------------------------
__global__ void prep_kernel(const float* __restrict__ pw, const float* __restrict__ pnw,
                            const float* __restrict__ fw, const float* __restrict__ fnw,
                            const float* __restrict__ kw, const float* __restrict__ qw,
                            const float* __restrict__ ow, const float* __restrict__ vw,
                            const float* __restrict__ qb, const float* __restrict__ kb,
                            const float* __restrict__ ob, const float* __restrict__ vb,
                            const float* __restrict__ basis)
{
    __shared__ float As[32][33], Bs[32][33];
    __shared__ float red[2][8];
    int blk = blockIdx.x;
    int tid = threadIdx.x;

    if (blk < 256) {
        int i = blk * 256 + tid;
        g_Wp[i] = pw[i] * pnw[i & 255];
    } else if (blk < 768) {
        int i = (blk - 256) * 256 + tid;
        g_Wf[i] = fw[i] * fnw[i & 255];
    } else if (blk < 896) {
        int bid = blk - 768;
        int mode = bid >> 6;
        int rem = bid & 63;
        int m0 = (rem >> 3) * 32, n0 = (rem & 7) * 32;
        int tx = tid & 15, ty = tid >> 4;
        const float* A = mode ? ow : kw;
        const float* B = mode ? vw : qw;
        float acc[2][2] = {{0.f,0.f},{0.f,0.f}};
        float aval[4], bval[4];
        #pragma unroll
        for (int i = 0; i < 4; i++) {
            int e = i * 256 + tid;
            int a = e >> 5, c = e & 31;
            bval[i] = B[(size_t)a * CC + n0 + c];
            aval[i] = mode ? A[(size_t)(m0 + a) * CC + c]
                           : A[(size_t)a * CC + m0 + c];
        }
        #pragma unroll 1
        for (int r0 = 0; r0 < CC; r0 += 32) {
            #pragma unroll
            for (int i = 0; i < 4; i++) {
                int e = i * 256 + tid;
                int a = e >> 5, c = e & 31;
                As[a][c] = aval[i];
                Bs[a][c] = bval[i];
            }
            __syncthreads();
            if (r0 + 32 < CC) {
                int r1 = r0 + 32;
                #pragma unroll
                for (int i = 0; i < 4; i++) {
                    int e = i * 256 + tid;
                    int a = e >> 5, c = e & 31;
                    bval[i] = B[(size_t)(r1 + a) * CC + n0 + c];
                    aval[i] = mode ? A[(size_t)(m0 + a) * CC + r1 + c]
                                   : A[(size_t)(r1 + a) * CC + m0 + c];
                }
            }
            if (mode) {
                #pragma unroll
                for (int r = 0; r < 32; r++) {
                    float a0 = As[ty*2][r], a1 = As[ty*2+1][r];
                    float b0 = Bs[r][tx*2], b1 = Bs[r][tx*2+1];
                    acc[0][0] += a0*b0; acc[0][1] += a0*b1;
                    acc[1][0] += a1*b0; acc[1][1] += a1*b1;
                }
            } else {
                #pragma unroll
                for (int r = 0; r < 32; r++) {
                    float a0 = As[r][ty*2], a1 = As[r][ty*2+1];
                    float b0 = Bs[r][tx*2], b1 = Bs[r][tx*2+1];
                    acc[0][0] += a0*b0; acc[0][1] += a0*b1;
                    acc[1][0] += a1*b0; acc[1][1] += a1*b1;
                }
            }
            __syncthreads();
        }
        float* C = mode ? g_OV : g_P;
        #pragma unroll
        for (int i = 0; i < 2; i++)
            #pragma unroll
            for (int j = 0; j < 2; j++)
                C[(size_t)(m0 + ty*2 + i) * CC + n0 + tx*2 + j] = acc[i][j];
    } else if (blk < 1152) {
        int j = blk - 896;
        int o = tid;
        float su = qb[o] * kw[(size_t)o * CC + j];
        float sb = ow[(size_t)j * CC + o] * vb[o];
        #pragma unroll
        for (int d = 16; d; d >>= 1) {
            su += __shfl_xor_sync(0xffffffffu, su, d);
            sb += __shfl_xor_sync(0xffffffffu, sb, d);
        }
        if ((o & 31) == 0) {
            int w = o >> 5;
            red[0][w] = su; red[1][w] = sb;
        }
        __syncthreads();
        if (o == 0) {
            float a = 0.f, c = 0.f;
            #pragma unroll
            for (int i = 0; i < 8; i++) { a += red[0][i]; c += red[1][i]; }
            g_u[j] = a;
            g_bias2[j] = c + ob[j];
        }
    } else {
        int idx = (blk - 1152) * 256 + tid;
        if (idx < 256 * 40) {
            int f = idx / 40, k = idx % 40;
            g_basish[idx] = (k < 32) ? __float2half(basis[(size_t)k * 256 + f])
                                     : __float2half(0.f);
        }
    }
}

// ------- depthwise 3x3 causal conv + SiLU + fused qseed MMA ----------------------
#define TB 16
__global__ void __launch_bounds__(256)
dwconv_qseed(const __half* __restrict__ src,
             const float* __restrict__ dww, const float* __restrict__ dwb,
             float* __restrict__ emb, __half* __restrict__ embh,
             const __half* __restrict__ basish, float* __restrict__ Y)
{
    __shared__ float rows[TB + 2][FF + 2];
    __shared__ __half As[TB][264];
    __shared__ __half Bh[256 * 40];
    int nblk = TT / TB;
    long idx = blockIdx.x;
    int tb = (int)(idx % nblk);
    long bc = idx / nblk;
    int c = (int)(bc % CC);
    int t0 = tb * TB;
    int f = threadIdx.x;
    int lane = f & 31, warp = f >> 5;
    size_t chbase = (size_t)bc * TT * FF;

    {
        const uint4* bsrc = (const uint4*)basish;
        uint4* bdst = (uint4*)Bh;
        #pragma unroll
        for (int i = 0; i < 5; i++) {
            int e = i * 256 + f;
            if (e < 1280) bdst[e] = bsrc[e];
        }
    }
    #pragma unroll
    for (int r = 0; r < TB + 2; r++) {
        int tt = t0 - 2 + r;
        rows[r][f + 1] = (tt >= 0) ? __half2float(src[chbase + (size_t)tt * FF + f]) : 0.f;
        if (f == 0) { rows[r][0] = 0.f; rows[r][FF + 1] = 0.f; }
    }
    __syncthreads();
    float w[9];
    #pragma unroll
    for (int i = 0; i < 9; i++) w[i] = dww[c * 9 + i];
    float bv = dwb[c];
    #pragma unroll
    for (int r = 0; r < TB; r++) {
        float s = bv;
        #pragma unroll
        for (int dt = 0; dt < 3; dt++)
            #pragma unroll
            for (int df = 0; df < 3; df++)
                s += w[dt * 3 + df] * rows[r + dt][f + df];
        s = s / (1.f + __expf(-s));
        __half h = __float2half(s);
        emb [chbase + (size_t)(t0 + r) * FF + f] = s;
        embh[chbase + (size_t)(t0 + r) * FF + f] = h;
        As[r][f] = h;
    }
    __syncthreads();

    if (warp < 4) {
        float acc[4] = {0.f, 0.f, 0.f, 0.f};
        #pragma unroll
        for (int ks = 0; ks < 16; ks++) {
            unsigned a[4];
            ldmx4(a, sptr(&As[lane & 15][ks * 16 + (lane >> 4) * 8]));
            unsigned b0, b1;
            ldmx2t(b0, b1, sptr(&Bh[(ks * 16 + (lane & 15)) * 40 + warp * 8]));
            mma_h(acc, a, b0, b1);
        }
        int group = lane >> 2, tid4 = lane & 3;
        int col = warp * 8 + tid4 * 2;
        long rbase = bc * TT + t0;
        *(float2*)(Y + (rbase + group) * 32 + col)     = make_float2(acc[0], acc[1]);
        *(float2*)(Y + (rbase + group + 8) * 32 + col) = make_float2(acc[2], acc[3]);
    }
}

// ---------------- fused attention (512 threads): scores + softmax + pooled ------
#define ATTN_SMEM (256*264*2 + 34848 + 256*40*2)
__global__ void __launch_bounds__(512, 1)
attn_mma_kernel(const float* __restrict__ Q2, const __half* __restrict__ embh,
                const float* __restrict__ rb,
                const float* __restrict__ ssp, const float* __restrict__ psp,
                float* __restrict__ pooled)
{
    extern __shared__ __align__(16) char sm_[];
    __half* Eh = (__half*)sm_;
    char* regU = sm_ + 256 * 264 * 2;
    __half* q2T = (__half*)regU;
    float* scoresF = (float*)regU;
    float* poolSm = (float*)regU;
    __half* Wt = (__half*)(regU + 34848);

    int bt = blockIdx.x;
    int b = bt / TT, t = bt % TT;
    size_t qframe = ((size_t)b * CC * TT + t) * KK;
    size_t eframe = ((size_t)b * CC * TT + t) * FF;
    int tid = threadIdx.x;
    int lane = tid & 31, warp = tid >> 5;
    int group = lane >> 2, tid4 = lane & 3;

    #pragma unroll 8
    for (int i = 0; i < 16; i++) {
        int e = i * 512 + tid;
        int c = e >> 5, f8 = e & 31;
        *(uint4*)&Eh[c * 264 + f8 * 8] =
            *(const uint4*)(embh + eframe + (size_t)c * TT * FF + f8 * 8);
    }
    for (int e = tid; e < 16 * 264; e += 512)
        q2T[32 * 264 + e] = __float2half(0.f);
    if (tid < 256) q2T[32 * 264 + tid] = __float2half(g_u[tid]);
    #pragma unroll
    for (int i = 0; i < 4; i++) {
        int e = i * 512 + tid;
        int c = e >> 3, j = e & 7;
        float4 v = *(const float4*)(Q2 + qframe + (size_t)c * TT * KK + j * 4);
        q2T[(4*j + 0) * 264 + c] = __float2half(v.x);
        q2T[(4*j + 1) * 264 + c] = __float2half(v.y);
        q2T[(4*j + 2) * 264 + c] = __float2half(v.z);
        q2T[(4*j + 3) * 264 + c] = __float2half(v.w);
    }
    __syncthreads();

    float acc1[3][2][4];
    #pragma unroll
    for (int mt = 0; mt < 3; mt++)
        #pragma unroll
        for (int nt = 0; nt < 2; nt++)
            #pragma unroll
            for (int r = 0; r < 4; r++) acc1[mt][nt][r] = 0.f;

    #pragma unroll 1
    for (int ks = 0; ks < 256; ks += 16) {
        unsigned a[3][4];
        #pragma unroll
        for (int mt = 0; mt < 3; mt++)
            ldmx4(a[mt], sptr(&q2T[(mt * 16 + (lane & 15)) * 264 + ks + (lane >> 4) * 8]));
        #pragma unroll
        for (int nt = 0; nt < 2; nt++) {
            unsigned b0, b1;
            ldmx2t(b0, b1, sptr(&Eh[(ks + (lane & 15)) * 264 + warp * 16 + nt * 8]));
            mma_h(acc1[0][nt], a[0], b0, b1);
            mma_h(acc1[1][nt], a[1], b0, b1);
            mma_h(acc1[2][nt], a[2], b0, b1);
        }
    }
    __syncthreads();

    #pragma unroll
    for (int mt = 0; mt < 2; mt++)
        #pragma unroll
        for (int nt = 0; nt < 2; nt++) {
            int row = mt * 16 + group;
            int col = warp * 16 + nt * 8 + tid4 * 2;
            *(float2*)&scoresF[row * 264 + col]       = make_float2(acc1[mt][nt][0], acc1[mt][nt][1]);
            *(float2*)&scoresF[(row + 8) * 264 + col] = make_float2(acc1[mt][nt][2], acc1[mt][nt][3]);
        }
    if (group == 0) {
        #pragma unroll
        for (int nt = 0; nt < 2; nt++) {
            int col = warp * 16 + nt * 8 + tid4 * 2;
            *(float2*)&scoresF[32 * 264 + col] = make_float2(acc1[2][nt][0], acc1[2][nt][1]);
        }
    }
    __syncthreads();

    float ss = *ssp, ps = *psp;
    #pragma unroll
    for (int rr = 0; rr < 2; rr++) {
        int k = warp * 2 + rr;
        float v[8];
        float m = -1e30f;
        #pragma unroll
        for (int i = 0; i < 8; i++) {
            int f = lane + 32 * i;
            float raw = scoresF[k * 264 + f];
            float uu  = scoresF[32 * 264 + f];
            v[i] = ss * (raw + uu) + rb[k * FF + f] * ps;
            m = fmaxf(m, v[i]);
        }
        #pragma unroll
        for (int o = 16; o; o >>= 1) m = fmaxf(m, __shfl_xor_sync(0xffffffffu, m, o));
        float s = 0.f;
        #pragma unroll
        for (int i = 0; i < 8; i++) { v[i] = __expf(v[i] - m); s += v[i]; }
        #pragma unroll
        for (int o = 16; o; o >>= 1) s += __shfl_xor_sync(0xffffffffu, s, o);
        float inv = 1.f / s;
        #pragma unroll
        for (int i = 0; i < 8; i++) {
            int f = lane + 32 * i;
            Wt[f * 40 + k] = __float2half(v[i] * inv);
        }
    }
    __syncthreads();

    float acc2[4][4];
    #pragma unroll
    for (int nt = 0; nt < 4; nt++)
        #pragma unroll
        for (int r = 0; r < 4; r++) acc2[nt][r] = 0.f;

    #pragma unroll 1
    for (int fs = 0; fs < 256; fs += 16) {
        unsigned a[4];
        ldmx4(a, sptr(&Eh[(warp * 16 + (lane & 15)) * 264 + fs + (lane >> 4) * 8]));
        #pragma unroll
        for (int nt = 0; nt < 4; nt++) {
            unsigned b0, b1;
            ldmx2t(b0, b1, sptr(&Wt[(fs + (lane & 15)) * 40 + nt * 8]));
            mma_h(acc2[nt], a, b0, b1);
        }
    }
    __syncthreads();

    #pragma unroll
    for (int nt = 0; nt < 4; nt++) {
        int row = warp * 16 + group;
        int col = nt * 8 + tid4 * 2;
        *(float2*)&poolSm[row * 34 + col]       = make_float2(acc2[nt][0], acc2[nt][1]);
        *(float2*)&poolSm[(row + 8) * 34 + col] = make_float2(acc2[nt][2], acc2[nt][3]);
    }
    __syncthreads();
    #pragma unroll
    for (int i = 0; i < 16; i++) {
        int e = i * 512 + tid;
        int c = e >> 5, k = e & 31;
        pooled[qframe + (size_t)c * TT * KK + k] = poolSm[c * 34 + k];
    }
}

// ---------------- host launcher --------------------------------------------------
extern "C" void kernel_launch(void* const* d_in, const int* in_sizes, int n_in,
                              void* d_out, int out_size) {
    const float* x          = (const float*)d_in[0];
    const float* pre_norm_w = (const float*)d_in[1];
    const float* pre_pw_w   = (const float*)d_in[2];
    const float* pre_pw_b   = (const float*)d_in[3];
    const float* pre_dw_w   = (const float*)d_in[4];
    const float* pre_dw_b   = (const float*)d_in[5];
    const float* q_w        = (const float*)d_in[6];
    const float* q_b        = (const float*)d_in[7];
    const float* k_w        = (const float*)d_in[8];
    const float* k_b        = (const float*)d_in[9];
    const float* v_w        = (const float*)d_in[10];
    const float* v_b        = (const float*)d_in[11];
    const float* out_w      = (const float*)d_in[12];
    const float* out_b      = (const float*)d_in[13];
    const float* ffn_norm_w = (const float*)d_in[14];
    const float* ffn_in_w   = (const float*)d_in[15];
    const float* ffn_in_b   = (const float*)d_in[16];
    const float* ffn_out_w  = (const float*)d_in[17];
    const float* ffn_out_b  = (const float*)d_in[18];
    const float* score_scale= (const float*)d_in[19];
    const float* prior_scale= (const float*)d_in[20];
    const float* query_basis= (const float*)d_in[21];
    const float* routing_bias=(const float*)d_in[22];

    float* out        = (float*)d_out;
    float* out_hidden = out;
    float* out_emb    = out + (size_t)BB * CC * TT * KK;

    float *emb0, *qseed, *q2, *pooled, *hidden, *hffn;
    float *P, *OV, *Wp, *Wf, *bias2;
    __half *embh, *basish;
    cudaGetSymbolAddress((void**)&emb0,   g_emb0);
    cudaGetSymbolAddress((void**)&embh,   g_embh);
    cudaGetSymbolAddress((void**)&basish, g_basish);
    cudaGetSymbolAddress((void**)&qseed,  g_qseed);
    cudaGetSymbolAddress((void**)&q2,     g_q2);
    cudaGetSymbolAddress((void**)&pooled, g_pooled);
    cudaGetSymbolAddress((void**)&hidden, g_hidden);
    cudaGetSymbolAddress((void**)&hffn,   g_hffn);
    cudaGetSymbolAddress((void**)&P,      g_P);
    cudaGetSymbolAddress((void**)&OV,     g_OV);
    cudaGetSymbolAddress((void**)&Wp,     g_Wp);
    cudaGetSymbolAddress((void**)&Wf,     g_Wf);
    cudaGetSymbolAddress((void**)&bias2,  g_bias2);

    cudaFuncSetAttribute(attn_mma_kernel,
                         cudaFuncAttributeMaxDynamicSharedMemorySize, ATTN_SMEM);

    const int NBT = BB * TT;       // 800
    const int NF  = TT * FF;       // 102400
    const int NK  = TT * KK;       // 12800

    // 0. unified precompute
    prep_kernel<<<1192, 256>>>(pre_pw_w, pre_norm_w, ffn_in_w, ffn_norm_w,
                               k_w, q_w, out_w, v_w,
                               q_b, k_b, out_b, v_b, query_basis);

    // 1. pre pw with fused RMSNorm -> emb0 (fp16)  [BM=128, 2 CTAs/SM]
    gemm_h2<<<dim3(NF/128, 2, BB), 256>>>(Wp, pre_pw_b, x,
                                          nullptr, (__half*)emb0,
                                          1, CC, NF, (long)CC * NF);
    // 2. depthwise conv + SiLU -> emb (fp32), embh (fp16), qseed (fused MMA)
    dwconv_qseed<<<(long)BB*CC*(TT/TB), 256>>>((const __half*)emb0, pre_dw_w, pre_dw_b,
                                               out_emb, embh, basish, qseed);
    // 3. q2 = P @ qseed
    gemm_hs2<<<dim3(NK/128, 2, BB), 256>>>(P, nullptr, qseed, nullptr, q2, nullptr,
                                           0, CC, NK, (long)CC * NK);
    // 4. fused attention
    attn_mma_kernel<<<NBT, 512, ATTN_SMEM>>>(q2, embh, routing_bias,
                                             score_scale, prior_scale, pooled);
    // 5. hidden = OV @ pooled + bias2
    gemm_hs2<<<dim3(NK/128, 2, BB), 256>>>(OV, bias2, pooled, nullptr, hidden, nullptr,
                                           0, CC, NK, (long)CC * NK);
    // 6. ffn_in with fused RMSNorm
    gemm_hs2<<<dim3(NK/128, 4, BB), 256>>>(Wf, ffn_in_b, hidden, nullptr, hffn, nullptr,
                                           1, 2*CC, NK, (long)CC * NK);
    // 7. ffn_out with fused GLU load + residual -> d_out
    gemm_hs2<<<dim3(NK/128, 2, BB), 256>>>(ffn_out_w, ffn_out_b, hffn,
                                           hffn + (size_t)CC * NK,
                                           out_hidden, hidden,
                                           0, CC, NK, (long)2 * CC * NK);
}

// round 17
// speedup vs baseline: 1.2350x; 1.0357x over previous
#include <cuda_runtime.h>
#include <cuda_fp16.h>
#include <math.h>

#define BB 2
#define CC 256
#define TT 400
#define FF 256
#define KK 32
#define EPSV 1e-6f

typedef unsigned long long ull;

// ---------------- scratch ------------------------------------------------------
__device__ float  g_emb0   [(size_t)BB*CC*TT*FF];   // used as fp16
__device__ __half g_embh   [(size_t)BB*CC*TT*FF];
__device__ __half g_basish [256*40];
__device__ __half g_qseedh [(size_t)BB*CC*TT*KK];
__device__ __half g_q2h    [(size_t)BB*CC*TT*KK];
__device__ __half g_pooledh[(size_t)BB*CC*TT*KK];
__device__ float  g_hidden [(size_t)BB*CC*TT*KK];
__device__ __half g_hffnh  [(size_t)BB*2*CC*TT*KK];
__device__ float  g_P      [CC*CC];
__device__ float  g_OV     [CC*CC];
__device__ float  g_Wp     [CC*CC];
__device__ float  g_Wf     [2*CC*CC];
__device__ float  g_u      [CC];
__device__ float  g_bias2  [CC];

// ---------------- helpers ------------------------------------------------------
__device__ __forceinline__ unsigned sptr(const void* p) {
    return (unsigned)__cvta_generic_to_shared(p);
}
__device__ __forceinline__ void ldmx4(unsigned* a, unsigned addr) {
    asm volatile("ldmatrix.sync.aligned.m8n8.x4.shared.b16 {%0,%1,%2,%3}, [%4];"
        : "=r"(a[0]), "=r"(a[1]), "=r"(a[2]), "=r"(a[3]) : "r"(addr));
}
__device__ __forceinline__ void ldmx2t(unsigned& b0, unsigned& b1, unsigned addr) {
    asm volatile("ldmatrix.sync.aligned.m8n8.x2.trans.shared.b16 {%0,%1}, [%2];"
        : "=r"(b0), "=r"(b1) : "r"(addr));
}
__device__ __forceinline__ void mma_h(float* c, const unsigned* a, unsigned b0, unsigned b1) {
    asm volatile("mma.sync.aligned.m16n8k16.row.col.f32.f16.f16.f32 "
        "{%0,%1,%2,%3}, {%4,%5,%6,%7}, {%8,%9}, {%0,%1,%2,%3};"
        : "+f"(c[0]), "+f"(c[1]), "+f"(c[2]), "+f"(c[3])
        : "r"(a[0]), "r"(a[1]), "r"(a[2]), "r"(a[3]), "r"(b0), "r"(b1));
}
__device__ __forceinline__ void split2(float x, float y, __half2& hi, __half2& lo) {
    hi = __floats2half2_rn(x, y);
    float2 hf = __half22float2(hi);
    lo = __floats2half2_rn(x - hf.x, y - hf.y);
}

// ------- plain fp16 GEMM, BM=128, 256 threads, 2 CTAs/SM ------------------------
// X fp32 (with optional invMode RMSNorm) OR Xh_in fp16; out fp32 or fp16
__global__ void __launch_bounds__(256, 2)
gemm_h2(const float* __restrict__ W, const float* __restrict__ bias,
        const float* __restrict__ X, const __half* __restrict__ Xh_in,
        float* __restrict__ Y, __half* __restrict__ Yh,
        int invMode, int Cout, int Ntot, long xbstride)
{
    __shared__ __half Wh[2][128][24];
    __shared__ __half Xh[2][16][136];
    __shared__ float4 part[8][32];
    __shared__ float invs[128];

    int b  = blockIdx.z;
    int n0 = blockIdx.x * 128;
    int o0 = blockIdx.y * 128;
    const float*  Xb  = X     ? X     + (size_t)b * xbstride : nullptr;
    const __half* Xhb = Xh_in ? Xh_in + (size_t)b * xbstride : nullptr;
    float* Yb   = Y  ? Y  + (size_t)b * (size_t)Cout * Ntot : nullptr;
    __half* Yhb = Yh ? Yh + (size_t)b * (size_t)Cout * Ntot : nullptr;

    int tid = threadIdx.x;
    int lane = tid & 31, warp = tid >> 5;
    int wm = warp & 3, wn = warp >> 2;
    int group = lane >> 2, tid4 = lane & 3;

    float acc[2][8][4];
    #pragma unroll
    for (int mt = 0; mt < 2; mt++)
        #pragma unroll
        for (int nt = 0; nt < 8; nt++)
            #pragma unroll
            for (int r = 0; r < 4; r++) acc[mt][nt][r] = 0.f;

    float4 ssq = make_float4(0.f, 0.f, 0.f, 0.f);
    float4 wreg[2], xreg[2];
    uint2 xh_raw[2];

    #pragma unroll
    for (int i = 0; i < 2; i++) {
        int ws = i * 256 + tid;
        int wr = ws >> 2, wk = (ws & 3) * 4;
        wreg[i] = *(const float4*)(W + (size_t)(o0 + wr) * 256 + wk);
        int xs = i * 256 + tid;
        int xk = xs >> 5, xn = (xs & 31) * 4;
        if (Xhb) {
            xh_raw[i] = *(const uint2*)(Xhb + (size_t)xk * Ntot + n0 + xn);
        } else {
            float4 v = *(const float4*)(Xb + (size_t)xk * Ntot + n0 + xn);
            if (invMode) {
                ssq.x += v.x*v.x; ssq.y += v.y*v.y; ssq.z += v.z*v.z; ssq.w += v.w*v.w;
            }
            xreg[i] = v;
        }
    }

    #pragma unroll 1
    for (int kt = 0; kt < 16; kt++) {
        int buf = kt & 1;
        #pragma unroll
        for (int i = 0; i < 2; i++) {
            int ws = i * 256 + tid;
            int wr = ws >> 2, wk = (ws & 3) * 2;
            __half2* wh = (__half2*)&Wh[buf][wr][0];
            wh[wk]   = __floats2half2_rn(wreg[i].x, wreg[i].y);
            wh[wk+1] = __floats2half2_rn(wreg[i].z, wreg[i].w);
            int xs = i * 256 + tid;
            int xk = xs >> 5, xn = (xs & 31) * 4;
            if (Xhb) {
                *(uint2*)&Xh[buf][xk][xn] = xh_raw[i];
            } else {
                __half2* xr = (__half2*)&Xh[buf][xk][xn];
                xr[0] = __floats2half2_rn(xreg[i].x, xreg[i].y);
                xr[1] = __floats2half2_rn(xreg[i].z, xreg[i].w);
            }
        }
        __syncthreads();
        if (kt < 15) {
            int k0 = (kt + 1) * 16;
            #pragma unroll
            for (int i = 0; i < 2; i++) {
                int ws = i * 256 + tid;
                int wr = ws >> 2, wk = (ws & 3) * 4;
                wreg[i] = *(const float4*)(W + (size_t)(o0 + wr) * 256 + k0 + wk);
                int xs = i * 256 + tid;
                int xk = xs >> 5, xn = (xs & 31) * 4;
                if (Xhb) {
                    xh_raw[i] = *(const uint2*)(Xhb + (size_t)(k0 + xk) * Ntot + n0 + xn);
                } else {
                    float4 v = *(const float4*)(Xb + (size_t)(k0 + xk) * Ntot + n0 + xn);
                    if (invMode) {
                        ssq.x += v.x*v.x; ssq.y += v.y*v.y; ssq.z += v.z*v.z; ssq.w += v.w*v.w;
                    }
                    xreg[i] = v;
                }
            }
        }
        unsigned a[2][4];
        #pragma unroll
        for (int mt = 0; mt < 2; mt++) {
            int row = wm * 32 + mt * 16 + (lane & 15);
            ldmx4(a[mt], sptr(&Wh[buf][row][(lane >> 4) * 8]));
        }
        #pragma unroll
        for (int nt = 0; nt < 8; nt++) {
            unsigned b0, b1;
            ldmx2t(b0, b1, sptr(&Xh[buf][lane & 15][wn * 64 + nt * 8]));
            mma_h(acc[0][nt], a[0], b0, b1);
            mma_h(acc[1][nt], a[1], b0, b1);
        }
    }

    if (invMode) {
        part[warp][lane] = ssq;
        __syncthreads();
        if (tid < 32) {
            float4 s = part[0][tid];
            #pragma unroll
            for (int r = 1; r < 8; r++) {
                float4 p = part[r][tid];
                s.x += p.x; s.y += p.y; s.z += p.z; s.w += p.w;
            }
            invs[tid * 4 + 0] = rsqrtf(s.x * (1.f / CC) + EPSV);
            invs[tid * 4 + 1] = rsqrtf(s.y * (1.f / CC) + EPSV);
            invs[tid * 4 + 2] = rsqrtf(s.z * (1.f / CC) + EPSV);
            invs[tid * 4 + 3] = rsqrtf(s.w * (1.f / CC) + EPSV);
        }
        __syncthreads();
    }

    #pragma unroll
    for (int mt = 0; mt < 2; mt++) {
        int row = o0 + wm * 32 + mt * 16 + group;
        float bv0 = bias ? bias[row]     : 0.f;
        float bv8 = bias ? bias[row + 8] : 0.f;
        #pragma unroll
        for (int nt = 0; nt < 8; nt++) {
            int cl = wn * 64 + nt * 8 + tid4 * 2;
            int col = n0 + cl;
            size_t i0 = (size_t)row * Ntot + col;
            size_t i8 = (size_t)(row + 8) * Ntot + col;
            float a0 = acc[mt][nt][0], a1 = acc[mt][nt][1];
            float a2 = acc[mt][nt][2], a3 = acc[mt][nt][3];
            if (invMode) {
                float s0 = invs[cl], s1 = invs[cl + 1];
                a0 *= s0; a1 *= s1; a2 *= s0; a3 *= s1;
            }
            if (Yhb) {
                *(__half2*)(Yhb + i0) = __floats2half2_rn(a0 + bv0, a1 + bv0);
                *(__half2*)(Yhb + i8) = __floats2half2_rn(a2 + bv8, a3 + bv8);
            } else {
                *(float2*)(Yb + i0) = make_float2(a0 + bv0, a1 + bv0);
                *(float2*)(Yb + i8) = make_float2(a2 + bv8, a3 + bv8);
            }
        }
    }
}

// ------- 2-term split GEMM, BM=128, 2 CTAs/SM -----------------------------------
// X fp32 (invMode) OR Xh_in fp16 (optional Xgh_in fp16 GLU gate); out fp32/fp16
__global__ void __launch_bounds__(256, 2)
gemm_hs2(const float* __restrict__ W, const float* __restrict__ bias,
         const float* __restrict__ X,
         const __half* __restrict__ Xh_in, const __half* __restrict__ Xgh_in,
         float* __restrict__ Y, __half* __restrict__ Yh_out,
         const float* __restrict__ addsrc,
         int invMode, int Cout, int Ntot, long xbstride)
{
    __shared__ __half Whh[2][128][24];
    __shared__ __half Whl[2][128][24];
    __shared__ __half Xh[2][16][136];
    __shared__ float4 part[8][32];
    __shared__ float invs[128];

    int b  = blockIdx.z;
    int n0 = blockIdx.x * 128;
    int o0 = blockIdx.y * 128;
    const float*  Xb   = X      ? X      + (size_t)b * xbstride : nullptr;
    const __half* Xhb  = Xh_in  ? Xh_in  + (size_t)b * xbstride : nullptr;
    const __half* Xghb = Xgh_in ? Xgh_in + (size_t)b * xbstride : nullptr;
    float*  Yb  = Y      ? Y      + (size_t)b * (size_t)Cout * Ntot : nullptr;
    __half* Yhb = Yh_out ? Yh_out + (size_t)b * (size_t)Cout * Ntot : nullptr;
    const float* Ab = addsrc ? addsrc + (size_t)b * (size_t)Cout * Ntot : nullptr;

    int tid = threadIdx.x;
    int lane = tid & 31, warp = tid >> 5;
    int wm = warp & 3, wn = warp >> 2;
    int group = lane >> 2, tid4 = lane & 3;

    float acc[2][8][4];
    #pragma unroll
    for (int mt = 0; mt < 2; mt++)
        #pragma unroll
        for (int nt = 0; nt < 8; nt++)
            #pragma unroll
            for (int r = 0; r < 4; r++) acc[mt][nt][r] = 0.f;

    float4 ssq = make_float4(0.f, 0.f, 0.f, 0.f);
    float4 wreg[2], xreg[2];
    uint2 xh_raw[2], xgh_raw[2];

    #pragma unroll
    for (int i = 0; i < 2; i++) {
        int ws = i * 256 + tid;
        int wr = ws >> 2, wk = (ws & 3) * 4;
        wreg[i] = *(const float4*)(W + (size_t)(o0 + wr) * 256 + wk);
        int xs = i * 256 + tid;
        int xk = xs >> 5, xn = (xs & 31) * 4;
        if (Xhb) {
            xh_raw[i] = *(const uint2*)(Xhb + (size_t)xk * Ntot + n0 + xn);
            if (Xghb) xgh_raw[i] = *(const uint2*)(Xghb + (size_t)xk * Ntot + n0 + xn);
        } else {
            float4 v = *(const float4*)(Xb + (size_t)xk * Ntot + n0 + xn);
            if (invMode) {
                ssq.x += v.x*v.x; ssq.y += v.y*v.y; ssq.z += v.z*v.z; ssq.w += v.w*v.w;
            }
            xreg[i] = v;
        }
    }

    #pragma unroll 1
    for (int kt = 0; kt < 16; kt++) {
        int buf = kt & 1;
        #pragma unroll
        for (int i = 0; i < 2; i++) {
            int ws = i * 256 + tid;
            int wr = ws >> 2, wk = (ws & 3) * 2;
            __half2 hi, lo;
            __half2* wh = (__half2*)&Whh[buf][wr][0];
            __half2* wl = (__half2*)&Whl[buf][wr][0];
            split2(wreg[i].x, wreg[i].y, hi, lo); wh[wk]   = hi; wl[wk]   = lo;
            split2(wreg[i].z, wreg[i].w, hi, lo); wh[wk+1] = hi; wl[wk+1] = lo;
            int xs = i * 256 + tid;
            int xk = xs >> 5, xn = (xs & 31) * 4;
            if (Xhb) {
                if (Xghb) {
                    __half a4[4], g4[4];
                    *(uint2*)a4 = xh_raw[i];
                    *(uint2*)g4 = xgh_raw[i];
                    float v[4];
                    #pragma unroll
                    for (int j = 0; j < 4; j++) {
                        float av = __half2float(a4[j]);
                        float gv = __half2float(g4[j]);
                        v[j] = av * (gv / (1.f + __expf(-gv)));
                    }
                    __half2* xr = (__half2*)&Xh[buf][xk][xn];
                    xr[0] = __floats2half2_rn(v[0], v[1]);
                    xr[1] = __floats2half2_rn(v[2], v[3]);
                } else {
                    *(uint2*)&Xh[buf][xk][xn] = xh_raw[i];
                }
            } else {
                __half2* xr = (__half2*)&Xh[buf][xk][xn];
                xr[0] = __floats2half2_rn(xreg[i].x, xreg[i].y);
                xr[1] = __floats2half2_rn(xreg[i].z, xreg[i].w);
            }
        }
        __syncthreads();
        if (kt < 15) {
            int k0 = (kt + 1) * 16;
            #pragma unroll
            for (int i = 0; i < 2; i++) {
                int ws = i * 256 + tid;
                int wr = ws >> 2, wk = (ws & 3) * 4;
                wreg[i] = *(const float4*)(W + (size_t)(o0 + wr) * 256 + k0 + wk);
                int xs = i * 256 + tid;
                int xk = xs >> 5, xn = (xs & 31) * 4;
                if (Xhb) {
                    xh_raw[i] = *(const uint2*)(Xhb + (size_t)(k0 + xk) * Ntot + n0 + xn);
                    if (Xghb) xgh_raw[i] = *(const uint2*)(Xghb + (size_t)(k0 + xk) * Ntot + n0 + xn);
                } else {
                    float4 v = *(const float4*)(Xb + (size_t)(k0 + xk) * Ntot + n0 + xn);
                    if (invMode) {
                        ssq.x += v.x*v.x; ssq.y += v.y*v.y; ssq.z += v.z*v.z; ssq.w += v.w*v.w;
                    }
                    xreg[i] = v;
                }
            }
        }
        unsigned ah[2][4], al[2][4];
        #pragma unroll
        for (int mt = 0; mt < 2; mt++) {
            int row = wm * 32 + mt * 16 + (lane & 15);
            ldmx4(ah[mt], sptr(&Whh[buf][row][(lane >> 4) * 8]));
            ldmx4(al[mt], sptr(&Whl[buf][row][(lane >> 4) * 8]));
        }
        #pragma unroll
        for (int nt = 0; nt < 8; nt++) {
            unsigned b0, b1;
            ldmx2t(b0, b1, sptr(&Xh[buf][lane & 15][wn * 64 + nt * 8]));
            mma_h(acc[0][nt], ah[0], b0, b1);
            mma_h(acc[0][nt], al[0], b0, b1);
            mma_h(acc[1][nt], ah[1], b0, b1);
            mma_h(acc[1][nt], al[1], b0, b1);
        }
    }

    if (invMode) {
        part[warp][lane] = ssq;
        __syncthreads();
        if (tid < 32) {
            float4 s = part[0][tid];
            #pragma unroll
            for (int r = 1; r < 8; r++) {
                float4 p = part[r][tid];
                s.x += p.x; s.y += p.y; s.z += p.z; s.w += p.w;
            }
            invs[tid * 4 + 0] = rsqrtf(s.x * (1.f / CC) + EPSV);
            invs[tid * 4 + 1] = rsqrtf(s.y * (1.f / CC) + EPSV);
            invs[tid * 4 + 2] = rsqrtf(s.z * (1.f / CC) + EPSV);
            invs[tid * 4 + 3] = rsqrtf(s.w * (1.f / CC) + EPSV);
        }
        __syncthreads();
    }

    #pragma unroll
    for (int mt = 0; mt < 2; mt++) {
        int row = o0 + wm * 32 + mt * 16 + group;
        float bv0 = bias ? bias[row]     : 0.f;
        float bv8 = bias ? bias[row + 8] : 0.f;
        #pragma unroll
        for (int nt = 0; nt < 8; nt++) {
            int cl = wn * 64 + nt * 8 + tid4 * 2;
            int col = n0 + cl;
            size_t i0 = (size_t)row * Ntot + col;
            size_t i8 = (size_t)(row + 8) * Ntot + col;
            float a0 = acc[mt][nt][0], a1 = acc[mt][nt][1];
            float a2 = acc[mt][nt][2], a3 = acc[mt][nt][3];
            if (invMode) {
                float s0 = invs[cl], s1 = invs[cl + 1];
                a0 *= s0; a1 *= s1; a2 *= s0; a3 *= s1;
            }
            float2 v0 = make_float2(a0 + bv0, a1 + bv0);
            float2 v8 = make_float2(a2 + bv8, a3 + bv8);
            if (Ab) {
                float2 r0 = *(const float2*)(Ab + i0);
                float2 r8 = *(const float2*)(Ab + i8);
                v0.x += r0.x; v0.y += r0.y;
                v8.x += r8.x; v8.y += r8.y;
            }
            if (Yhb) {
                *(__half2*)(Yhb + i0) = __floats2half2_rn(v0.x, v0.y);
                *(__half2*)(Yhb + i8) = __floats2half2_rn(v8.x, v8.y);
            } else {
                *(float2*)(Yb + i0) = v0;
                *(float2*)(Yb + i8) = v8;
            }
        }
    }
}

// ---------------- unified precompute kernel -------------------------------------
__global__ void prep_kernel(const float* __restrict__ pw, const float* __restrict__ pnw,
                            const float* __restrict__ fw, const float* __restrict__ fnw,
                            const float* __restrict__ kw, const float* __restrict__ qw,
                            const float* __restrict__ ow, const float* __restrict__ vw,
                            const float* __restrict__ qb, const float* __restrict__ kb,
                            const float* __restrict__ ob, const float* __restrict__ vb,
                            const float* __restrict__ basis)
{
    __shared__ float As[32][33], Bs[32][33];
    __shared__ float red[2][8];
    int blk = blockIdx.x;
    int tid = threadIdx.x;

    if (blk < 256) {
        int i = blk * 256 + tid;
        g_Wp[i] = pw[i] * pnw[i & 255];
    } else if (blk < 768) {
        int i = (blk - 256) * 256 + tid;
        g_Wf[i] = fw[i] * fnw[i & 255];
    } else if (blk < 896) {
        int bid = blk - 768;
        int mode = bid >> 6;
        int rem = bid & 63;
        int m0 = (rem >> 3) * 32, n0 = (rem & 7) * 32;
        int tx = tid & 15, ty = tid >> 4;
        const float* A = mode ? ow : kw;
        const float* B = mode ? vw : qw;
        float acc[2][2] = {{0.f,0.f},{0.f,0.f}};
        float aval[4], bval[4];
        #pragma unroll
        for (int i = 0; i < 4; i++) {
            int e = i * 256 + tid;
            int a = e >> 5, c = e & 31;
            bval[i] = B[(size_t)a * CC + n0 + c];
            aval[i] = mode ? A[(size_t)(m0 + a) * CC + c]
                           : A[(size_t)a * CC + m0 + c];
        }
        #pragma unroll 1
        for (int r0 = 0; r0 < CC; r0 += 32) {
            #pragma unroll
            for (int i = 0; i < 4; i++) {
                int e = i * 256 + tid;
                int a = e >> 5, c = e & 31;
                As[a][c] = aval[i];
                Bs[a][c] = bval[i];
            }
            __syncthreads();
            if (r0 + 32 < CC) {
                int r1 = r0 + 32;
                #pragma unroll
                for (int i = 0; i < 4; i++) {
                    int e = i * 256 + tid;
                    int a = e >> 5, c = e & 31;
                    bval[i] = B[(size_t)(r1 + a) * CC + n0 + c];
                    aval[i] = mode ? A[(size_t)(m0 + a) * CC + r1 + c]
                                   : A[(size_t)(r1 + a) * CC + m0 + c];
                }
            }
            if (mode) {
                #pragma unroll
                for (int r = 0; r < 32; r++) {
                    float a0 = As[ty*2][r], a1 = As[ty*2+1][r];
                    float b0 = Bs[r][tx*2], b1 = Bs[r][tx*2+1];
                    acc[0][0] += a0*b0; acc[0][1] += a0*b1;
                    acc[1][0] += a1*b0; acc[1][1] += a1*b1;
                }
            } else {
                #pragma unroll
                for (int r = 0; r < 32; r++) {
                    float a0 = As[r][ty*2], a1 = As[r][ty*2+1];
                    float b0 = Bs[r][tx*2], b1 = Bs[r][tx*2+1];
                    acc[0][0] += a0*b0; acc[0][1] += a0*b1;
                    acc[1][0] += a1*b0; acc[1][1] += a1*b1;
                }
            }
            __syncthreads();
        }
        float* C = mode ? g_OV : g_P;
        #pragma unroll
        for (int i = 0; i < 2; i++)
            #pragma unroll
            for (int j = 0; j < 2; j++)
                C[(size_t)(m0 + ty*2 + i) * CC + n0 + tx*2 + j] = acc[i][j];
    } else if (blk < 1152) {
        int j = blk - 896;
        int o = tid;
        float su = qb[o] * kw[(size_t)o * CC + j];
        float sb = ow[(size_t)j * CC + o] * vb[o];
        #pragma unroll
        for (int d = 16; d; d >>= 1) {
            su += __shfl_xor_sync(0xffffffffu, su, d);
            sb += __shfl_xor_sync(0xffffffffu, sb, d);
        }
        if ((o & 31) == 0) {
            int w = o >> 5;
            red[0][w] = su; red[1][w] = sb;
        }
        __syncthreads();
        if (o == 0) {
            float a = 0.f, c = 0.f;
            #pragma unroll
            for (int i = 0; i < 8; i++) { a += red[0][i]; c += red[1][i]; }
            g_u[j] = a;
            g_bias2[j] = c + ob[j];
        }
    } else {
        int idx = (blk - 1152) * 256 + tid;
        if (idx < 256 * 40) {
            int f = idx / 40, k = idx % 40;
            g_basish[idx] = (k < 32) ? __float2half(basis[(size_t)k * 256 + f])
                                     : __float2half(0.f);
        }
    }
}

// ------- depthwise 3x3 causal conv + SiLU + fused qseed MMA (fp16 out) ----------
#define TB 16
__global__ void __launch_bounds__(256)
dwconv_qseed(const __half* __restrict__ src,
             const float* __restrict__ dww, const float* __restrict__ dwb,
             float* __restrict__ emb, __half* __restrict__ embh,
             const __half* __restrict__ basish, __half* __restrict__ Yh)
{
    __shared__ float rows[TB + 2][FF + 2];
    __shared__ __half As[TB][264];
    __shared__ __half Bh[256 * 40];
    int nblk = TT / TB;
    long idx = blockIdx.x;
    int tb = (int)(idx % nblk);
    long bc = idx / nblk;
    int c = (int)(bc % CC);
    int t0 = tb * TB;
    int f = threadIdx.x;
    int lane = f & 31, warp = f >> 5;
    size_t chbase = (size_t)bc * TT * FF;

    {
        const uint4* bsrc = (const uint4*)basish;
        uint4* bdst = (uint4*)Bh;
        #pragma unroll
        for (int i = 0; i < 5; i++) {
            int e = i * 256 + f;
            if (e < 1280) bdst[e] = bsrc[e];
        }
    }
    #pragma unroll
    for (int r = 0; r < TB + 2; r++) {
        int tt = t0 - 2 + r;
        rows[r][f + 1] = (tt >= 0) ? __half2float(src[chbase + (size_t)tt * FF + f]) : 0.f;
        if (f == 0) { rows[r][0] = 0.f; rows[r][FF + 1] = 0.f; }
    }
    __syncthreads();
    float w[9];
    #pragma unroll
    for (int i = 0; i < 9; i++) w[i] = dww[c * 9 + i];
    float bv = dwb[c];
    #pragma unroll
    for (int r = 0; r < TB; r++) {
        float s = bv;
        #pragma unroll
        for (int dt = 0; dt < 3; dt++)
            #pragma unroll
            for (int df = 0; df < 3; df++)
                s += w[dt * 3 + df] * rows[r + dt][f + df];
        s = s / (1.f + __expf(-s));
        __half h = __float2half(s);
        emb [chbase + (size_t)(t0 + r) * FF + f] = s;
        embh[chbase + (size_t)(t0 + r) * FF + f] = h;
        As[r][f] = h;
    }
    __syncthreads();

    if (warp < 4) {
        float acc[4] = {0.f, 0.f, 0.f, 0.f};
        #pragma unroll
        for (int ks = 0; ks < 16; ks++) {
            unsigned a[4];
            ldmx4(a, sptr(&As[lane & 15][ks * 16 + (lane >> 4) * 8]));
            unsigned b0, b1;
            ldmx2t(b0, b1, sptr(&Bh[(ks * 16 + (lane & 15)) * 40 + warp * 8]));
            mma_h(acc, a, b0, b1);
        }
        int group = lane >> 2, tid4 = lane & 3;
        int col = warp * 8 + tid4 * 2;
        long rbase = bc * TT + t0;
        *(__half2*)(Yh + (rbase + group) * 32 + col)     = __floats2half2_rn(acc[0], acc[1]);
        *(__half2*)(Yh + (rbase + group + 8) * 32 + col) = __floats2half2_rn(acc[2], acc[3]);
    }
}

// ---------------- fused attention (512 threads), fp16 q2 in / pooled out --------
#define ATTN_SMEM (256*264*2 + 34848 + 256*40*2)
__global__ void __launch_bounds__(512, 1)
attn_mma_kernel(const __half* __restrict__ Q2h, const __half* __restrict__ embh,
                const float* __restrict__ rb,
                const float* __restrict__ ssp, const float* __restrict__ psp,
                __half* __restrict__ pooledh)
{
    extern __shared__ __align__(16) char sm_[];
    __half* Eh = (__half*)sm_;
    char* regU = sm_ + 256 * 264 * 2;
    __half* q2T = (__half*)regU;
    float* scoresF = (float*)regU;
    float* poolSm = (float*)regU;
    __half* Wt = (__half*)(regU + 34848);

    int bt = blockIdx.x;
    int b = bt / TT, t = bt % TT;
    size_t qframe = ((size_t)b * CC * TT + t) * KK;
    size_t eframe = ((size_t)b * CC * TT + t) * FF;
    int tid = threadIdx.x;
    int lane = tid & 31, warp = tid >> 5;
    int group = lane >> 2, tid4 = lane & 3;

    #pragma unroll 8
    for (int i = 0; i < 16; i++) {
        int e = i * 512 + tid;
        int c = e >> 5, f8 = e & 31;
        *(uint4*)&Eh[c * 264 + f8 * 8] =
            *(const uint4*)(embh + eframe + (size_t)c * TT * FF + f8 * 8);
    }
    for (int e = tid; e < 16 * 264; e += 512)
        q2T[32 * 264 + e] = __float2half(0.f);
    if (tid < 256) q2T[32 * 264 + tid] = __float2half(g_u[tid]);
    #pragma unroll
    for (int i = 0; i < 4; i++) {
        int e = i * 512 + tid;
        int c = e >> 3, j = e & 7;
        __half a4[4];
        *(uint2*)a4 = *(const uint2*)(Q2h + qframe + (size_t)c * TT * KK + j * 4);
        q2T[(4*j + 0) * 264 + c] = a4[0];
        q2T[(4*j + 1) * 264 + c] = a4[1];
        q2T[(4*j + 2) * 264 + c] = a4[2];
        q2T[(4*j + 3) * 264 + c] = a4[3];
    }
    __syncthreads();

    float acc1[3][2][4];
    #pragma unroll
    for (int mt = 0; mt < 3; mt++)
        #pragma unroll
        for (int nt = 0; nt < 2; nt++)
            #pragma unroll
            for (int r = 0; r < 4; r++) acc1[mt][nt][r] = 0.f;

    #pragma unroll 1
    for (int ks = 0; ks < 256; ks += 16) {
        unsigned a[3][4];
        #pragma unroll
        for (int mt = 0; mt < 3; mt++)
            ldmx4(a[mt], sptr(&q2T[(mt * 16 + (lane & 15)) * 264 + ks + (lane >> 4) * 8]));
        #pragma unroll
        for (int nt = 0; nt < 2; nt++) {
            unsigned b0, b1;
            ldmx2t(b0, b1, sptr(&Eh[(ks + (lane & 15)) * 264 + warp * 16 + nt * 8]));
            mma_h(acc1[0][nt], a[0], b0, b1);
            mma_h(acc1[1][nt], a[1], b0, b1);
            mma_h(acc1[2][nt], a[2], b0, b1);
        }
    }
    __syncthreads();

    #pragma unroll
    for (int mt = 0; mt < 2; mt++)
        #pragma unroll
        for (int nt = 0; nt < 2; nt++) {
            int row = mt * 16 + group;
            int col = warp * 16 + nt * 8 + tid4 * 2;
            *(float2*)&scoresF[row * 264 + col]       = make_float2(acc1[mt][nt][0], acc1[mt][nt][1]);
            *(float2*)&scoresF[(row + 8) * 264 + col] = make_float2(acc1[mt][nt][2], acc1[mt][nt][3]);
        }
    if (group == 0) {
        #pragma unroll
        for (int nt = 0; nt < 2; nt++) {
            int col = warp * 16 + nt * 8 + tid4 * 2;
            *(float2*)&scoresF[32 * 264 + col] = make_float2(acc1[2][nt][0], acc1[2][nt][1]);
        }
    }
    __syncthreads();

    float ss = *ssp, ps = *psp;
    #pragma unroll
    for (int rr = 0; rr < 2; rr++) {
        int k = warp * 2 + rr;
        float v[8];
        float m = -1e30f;
        #pragma unroll
        for (int i = 0; i < 8; i++) {
            int f = lane + 32 * i;
            float raw = scoresF[k * 264 + f];
            float uu  = scoresF[32 * 264 + f];
            v[i] = ss * (raw + uu) + rb[k * FF + f] * ps;
            m = fmaxf(m, v[i]);
        }
        #pragma unroll
        for (int o = 16; o; o >>= 1) m = fmaxf(m, __shfl_xor_sync(0xffffffffu, m, o));
        float s = 0.f;
        #pragma unroll
        for (int i = 0; i < 8; i++) { v[i] = __expf(v[i] - m); s += v[i]; }
        #pragma unroll
        for (int o = 16; o; o >>= 1) s += __shfl_xor_sync(0xffffffffu, s, o);
        float inv = 1.f / s;
        #pragma unroll
        for (int i = 0; i < 8; i++) {
            int f = lane + 32 * i;
            Wt[f * 40 + k] = __float2half(v[i] * inv);
        }
    }
    __syncthreads();

    float acc2[4][4];
    #pragma unroll
    for (int nt = 0; nt < 4; nt++)
        #pragma unroll
        for (int r = 0; r < 4; r++) acc2[nt][r] = 0.f;

    #pragma unroll 1
    for (int fs = 0; fs < 256; fs += 16) {
        unsigned a[4];
        ldmx4(a, sptr(&Eh[(warp * 16 + (lane & 15)) * 264 + fs + (lane >> 4) * 8]));
        #pragma unroll
        for (int nt = 0; nt < 4; nt++) {
            unsigned b0, b1;
            ldmx2t(b0, b1, sptr(&Wt[(fs + (lane & 15)) * 40 + nt * 8]));
            mma_h(acc2[nt], a, b0, b1);
        }
    }
    __syncthreads();

    #pragma unroll
    for (int nt = 0; nt < 4; nt++) {
        int row = warp * 16 + group;
        int col = nt * 8 + tid4 * 2;
        *(float2*)&poolSm[row * 34 + col]       = make_float2(acc2[nt][0], acc2[nt][1]);
        *(float2*)&poolSm[(row + 8) * 34 + col] = make_float2(acc2[nt][2], acc2[nt][3]);
    }
    __syncthreads();
    #pragma unroll
    for (int i = 0; i < 16; i++) {
        int e = i * 512 + tid;
        int c = e >> 5, k = e & 31;
        pooledh[qframe + (size_t)c * TT * KK + k] = __float2half(poolSm[c * 34 + k]);
    }
}

// ---------------- host launcher --------------------------------------------------
extern "C" void kernel_launch(void* const* d_in, const int* in_sizes, int n_in,
                              void* d_out, int out_size) {
    const float* x          = (const float*)d_in[0];
    const float* pre_norm_w = (const float*)d_in[1];
    const float* pre_pw_w   = (const float*)d_in[2];
    const float* pre_pw_b   = (const float*)d_in[3];
    const float* pre_dw_w   = (const float*)d_in[4];
    const float* pre_dw_b   = (const float*)d_in[5];
    const float* q_w        = (const float*)d_in[6];
    const float* q_b        = (const float*)d_in[7];
    const float* k_w        = (const float*)d_in[8];
    const float* k_b        = (const float*)d_in[9];
    const float* v_w        = (const float*)d_in[10];
    const float* v_b        = (const float*)d_in[11];
    const float* out_w      = (const float*)d_in[12];
    const float* out_b      = (const float*)d_in[13];
    const float* ffn_norm_w = (const float*)d_in[14];
    const float* ffn_in_w   = (const float*)d_in[15];
    const float* ffn_in_b   = (const float*)d_in[16];
    const float* ffn_out_w  = (const float*)d_in[17];
    const float* ffn_out_b  = (const float*)d_in[18];
    const float* score_scale= (const float*)d_in[19];
    const float* prior_scale= (const float*)d_in[20];
    const float* query_basis= (const float*)d_in[21];
    const float* routing_bias=(const float*)d_in[22];

    float* out        = (float*)d_out;
    float* out_hidden = out;
    float* out_emb    = out + (size_t)BB * CC * TT * KK;

    float *emb0, *hidden;
    float *P, *OV, *Wp, *Wf, *bias2;
    __half *embh, *basish, *qseedh, *q2h, *pooledh, *hffnh;
    cudaGetSymbolAddress((void**)&emb0,    g_emb0);
    cudaGetSymbolAddress((void**)&embh,    g_embh);
    cudaGetSymbolAddress((void**)&basish,  g_basish);
    cudaGetSymbolAddress((void**)&qseedh,  g_qseedh);
    cudaGetSymbolAddress((void**)&q2h,     g_q2h);
    cudaGetSymbolAddress((void**)&pooledh, g_pooledh);
    cudaGetSymbolAddress((void**)&hidden,  g_hidden);
    cudaGetSymbolAddress((void**)&hffnh,   g_hffnh);
    cudaGetSymbolAddress((void**)&P,       g_P);
    cudaGetSymbolAddress((void**)&OV,      g_OV);
    cudaGetSymbolAddress((void**)&Wp,      g_Wp);
    cudaGetSymbolAddress((void**)&Wf,      g_Wf);
    cudaGetSymbolAddress((void**)&bias2,   g_bias2);

    cudaFuncSetAttribute(attn_mma_kernel,
                         cudaFuncAttributeMaxDynamicSharedMemorySize, ATTN_SMEM);

    const int NBT = BB * TT;       // 800
    const int NF  = TT * FF;       // 102400
    const int NK  = TT * KK;       // 12800

    // 0. unified precompute
    prep_kernel<<<1192, 256>>>(pre_pw_w, pre_norm_w, ffn_in_w, ffn_norm_w,
                               k_w, q_w, out_w, v_w,
                               q_b, k_b, out_b, v_b, query_basis);

    // 1. pre pw with fused RMSNorm -> emb0 (fp16)
    gemm_h2<<<dim3(NF/128, 2, BB), 256>>>(Wp, pre_pw_b, x, nullptr,
                                          nullptr, (__half*)emb0,
                                          1, CC, NF, (long)CC * NF);
    // 2. depthwise conv + SiLU -> emb (fp32), embh (fp16), qseed (fp16, fused MMA)
    dwconv_qseed<<<(long)BB*CC*(TT/TB), 256>>>((const __half*)emb0, pre_dw_w, pre_dw_b,
                                               out_emb, embh, basish, qseedh);
    // 3. q2 = P @ qseed   [plain, fp16 in/out]
    gemm_h2<<<dim3(NK/128, 2, BB), 256>>>(P, nullptr, nullptr, qseedh,
                                          nullptr, q2h,
                                          0, CC, NK, (long)CC * NK);
    // 4. fused attention -> pooled (fp16)
    attn_mma_kernel<<<NBT, 512, ATTN_SMEM>>>(q2h, embh, routing_bias,
                                             score_scale, prior_scale, pooledh);
    // 5. hidden = OV @ pooled + bias2   [split, fp16 X]
    gemm_hs2<<<dim3(NK/128, 2, BB), 256>>>(OV, bias2, nullptr, pooledh, nullptr,
                                           hidden, nullptr, nullptr,
                                           0, CC, NK, (long)CC * NK);
    // 6. ffn_in with fused RMSNorm -> hffn (fp16)  [split]
    gemm_hs2<<<dim3(NK/128, 4, BB), 256>>>(Wf, ffn_in_b, hidden, nullptr, nullptr,
                                           nullptr, hffnh, nullptr,
                                           1, 2*CC, NK, (long)CC * NK);
    // 7. ffn_out with fused GLU (fp16) + residual -> d_out  [split]
    gemm_hs2<<<dim3(NK/128, 2, BB), 256>>>(ffn_out_w, ffn_out_b, nullptr,
                                           hffnh, hffnh + (size_t)CC * NK,
                                           out_hidden, nullptr, hidden,
                                           0, CC, NK, (long)2 * CC * NK);
}